// round 2
// baseline (speedup 1.0000x reference)
#include <cuda_runtime.h>
#include <cuda_bf16.h>
#include <math.h>

// ---------------- problem constants ----------------
#define B_  2
#define L_  4096
#define D_  512
#define H_  8
#define DH_ 64
#define BL_ (B_ * L_)          // 8192
#define FF_ 2048               // 4*D

// ---------------- scratch (static device globals; no allocation) ----------------
__device__ float g_xn [BL_ * D_];
__device__ float g_q  [B_ * H_ * L_ * DH_];
__device__ float g_k  [B_ * H_ * L_ * DH_];
__device__ float g_v  [B_ * H_ * L_ * DH_];
__device__ float g_att[BL_ * D_];
__device__ float g_x1 [BL_ * D_];
__device__ float g_h  [BL_ * D_];
__device__ float g_ff [BL_ * FF_];

// ============================================================
// LayerNorm: one block per row of 512
// ============================================================
__global__ __launch_bounds__(256) void ln_kernel(const float* __restrict__ x,
                                                 const float* __restrict__ g,
                                                 const float* __restrict__ b,
                                                 float* __restrict__ y) {
    int row = blockIdx.x;
    const float* xr = x + (size_t)row * D_;
    float* yr = y + (size_t)row * D_;
    int tid = threadIdx.x;

    float v0 = xr[tid];
    float v1 = xr[tid + 256];
    float s  = v0 + v1;
    float ss = v0 * v0 + v1 * v1;

    #pragma unroll
    for (int o = 16; o > 0; o >>= 1) {
        s  += __shfl_xor_sync(0xffffffffu, s,  o);
        ss += __shfl_xor_sync(0xffffffffu, ss, o);
    }
    __shared__ float red[16];
    int w = tid >> 5, lane = tid & 31;
    if (lane == 0) { red[w] = s; red[w + 8] = ss; }
    __syncthreads();
    float S = 0.f, SS = 0.f;
    #pragma unroll
    for (int i = 0; i < 8; i++) { S += red[i]; SS += red[i + 8]; }
    float mu  = S * (1.0f / D_);
    float var = SS * (1.0f / D_) - mu * mu;
    float inv = rsqrtf(var + 1e-5f);

    yr[tid]       = (v0 - mu) * inv * g[tid]       + b[tid];
    yr[tid + 256] = (v1 - mu) * inv * g[tid + 256] + b[tid + 256];
}

// ============================================================
// GEMM: C[M,N] = A[M,K] @ B[N,K]^T, 128x128x16 tiles, 256 threads, 8x8 micro
// epilogue modes: 0 = qkv scatter, 1 = residual add, 2 = SiLU
// ============================================================
#define GEMM_MODE_QKV   0
#define GEMM_MODE_RESID 1
#define GEMM_MODE_SILU  2

__global__ __launch_bounds__(256) void gemm_kernel(
    const float* __restrict__ A, const float* __restrict__ B,
    int M, int N, int K, int mode,
    const float* __restrict__ resid, float* __restrict__ out,
    float* __restrict__ oq, float* __restrict__ ok, float* __restrict__ ov)
{
    __shared__ float As[16][132];
    __shared__ float Bs[16][132];

    int bm = blockIdx.y, bn = blockIdx.x;
    int tid = threadIdx.x;
    int tm = tid >> 4, tn = tid & 15;

    const float* Ab = A + (size_t)bm * 128 * K;
    const float* Bb = B + (size_t)bn * 128 * K;

    int lrow = tid >> 2;            // 0..63
    int lcol = (tid & 3) << 2;      // 0,4,8,12

    float acc[8][8];
    #pragma unroll
    for (int i = 0; i < 8; i++)
        #pragma unroll
        for (int j = 0; j < 8; j++) acc[i][j] = 0.f;

    for (int k0 = 0; k0 < K; k0 += 16) {
        #pragma unroll
        for (int p = 0; p < 2; p++) {
            int row = lrow + p * 64;
            float4 av = *(const float4*)&Ab[(size_t)row * K + k0 + lcol];
            As[lcol + 0][row] = av.x; As[lcol + 1][row] = av.y;
            As[lcol + 2][row] = av.z; As[lcol + 3][row] = av.w;
            float4 bv = *(const float4*)&Bb[(size_t)row * K + k0 + lcol];
            Bs[lcol + 0][row] = bv.x; Bs[lcol + 1][row] = bv.y;
            Bs[lcol + 2][row] = bv.z; Bs[lcol + 3][row] = bv.w;
        }
        __syncthreads();
        #pragma unroll
        for (int kk = 0; kk < 16; kk++) {
            float4 a0 = *(const float4*)&As[kk][tm * 8];
            float4 a1 = *(const float4*)&As[kk][tm * 8 + 4];
            float4 b0 = *(const float4*)&Bs[kk][tn * 8];
            float4 b1 = *(const float4*)&Bs[kk][tn * 8 + 4];
            float a[8] = {a0.x, a0.y, a0.z, a0.w, a1.x, a1.y, a1.z, a1.w};
            float bb[8] = {b0.x, b0.y, b0.z, b0.w, b1.x, b1.y, b1.z, b1.w};
            #pragma unroll
            for (int i = 0; i < 8; i++)
                #pragma unroll
                for (int j = 0; j < 8; j++)
                    acc[i][j] = fmaf(a[i], bb[j], acc[i][j]);
        }
        __syncthreads();
    }

    // epilogue
    #pragma unroll
    for (int i = 0; i < 8; i++) {
        int gm = bm * 128 + tm * 8 + i;
        #pragma unroll
        for (int j = 0; j < 8; j++) {
            int gn = bn * 128 + tn * 8 + j;
            float val = acc[i][j];
            if (mode == GEMM_MODE_QKV) {
                int which = gn >> 9;
                int h = (gn >> 6) & 7;
                int d = gn & 63;
                int bb_ = gm >> 12;      // gm / 4096
                int l  = gm & 4095;
                float* dst = (which == 0) ? oq : (which == 1) ? ok : ov;
                dst[(((size_t)bb_ * H_ + h) * L_ + l) * DH_ + d] = val;
            } else if (mode == GEMM_MODE_RESID) {
                size_t idx = (size_t)gm * N + gn;
                out[idx] = resid[idx] + val;
            } else { // SILU
                size_t idx = (size_t)gm * N + gn;
                out[idx] = val / (1.0f + __expf(-val));
            }
        }
    }
}

// ============================================================
// Flash attention (fp32), 64-query x 64-key tiles, online softmax,
// temporal decay bias + causal mask + key padding mask.
// grid: (L/64, B*H), 256 threads.
// ============================================================
#define PAD 68
__global__ __launch_bounds__(256) void attn_kernel(
    const float* __restrict__ q, const float* __restrict__ k,
    const float* __restrict__ v, const float* __restrict__ ts,
    const float* __restrict__ mask, const float* __restrict__ decay_rate,
    float* __restrict__ out)
{
    extern __shared__ float sm[];
    float* sQt = sm;                 // [64][PAD]  (d-major: sQt[d][r])
    float* sKt = sQt + 64 * PAD;     // [64][PAD]  (d-major: sKt[d][c])
    float* sV  = sKt + 64 * PAD;     // [64][PAD]  (sV[c][e])
    float* sSt = sV  + 64 * PAD;     // [64][PAD]  (sSt[c][r])
    float* tq   = sSt + 64 * PAD;    // [64]
    float* tk   = tq + 64;
    float* km   = tk + 64;
    float* mrow = km + 64;
    float* lrow = mrow + 64;
    float* frow = lrow + 64;

    int qt = blockIdx.x;
    int bh = blockIdx.y;
    int b  = bh >> 3, h = bh & 7;
    int tid = threadIdx.x;
    int tm = tid >> 4, tn = tid & 15;

    const float* qbase = q + ((size_t)bh * L_ + qt * 64) * DH_;

    // Q tile, transposed into smem
    for (int i = tid; i < 64 * 64; i += 256) {
        int r = i >> 6, d = i & 63;
        sQt[d * PAD + r] = qbase[i];
    }
    if (tid < 64) {
        int qi = qt * 64 + tid;
        tq[tid]   = ts[b * L_ + qi];
        mrow[tid] = -1e30f;
        lrow[tid] = 0.f;
    }
    float dcy = log1pf(__expf(decay_rate[h]));
    const float scale = 0.125f;       // 1/sqrt(64)
    float acc[4][4];
    #pragma unroll
    for (int i = 0; i < 4; i++)
        #pragma unroll
        for (int j = 0; j < 4; j++) acc[i][j] = 0.f;
    __syncthreads();

    for (int jt = 0; jt <= qt; jt++) {
        const float* kbase = k + ((size_t)bh * L_ + jt * 64) * DH_;
        const float* vbase = v + ((size_t)bh * L_ + jt * 64) * DH_;
        for (int i = tid; i < 64 * 64; i += 256) {
            int c = i >> 6, d = i & 63;
            sKt[d * PAD + c] = kbase[i];
            sV[c * PAD + d]  = vbase[i];
        }
        if (tid < 64) {
            int kj = jt * 64 + tid;
            tk[tid] = ts[b * L_ + kj];
            km[tid] = mask[b * L_ + kj];
        }
        __syncthreads();

        // ---- S = Q K^T (4x4 per thread) ----
        float s[4][4];
        #pragma unroll
        for (int i = 0; i < 4; i++)
            #pragma unroll
            for (int j = 0; j < 4; j++) s[i][j] = 0.f;
        #pragma unroll 4
        for (int d = 0; d < 64; d++) {
            float4 q4 = *(const float4*)(sQt + d * PAD + (tm << 2));
            float4 k4 = *(const float4*)(sKt + d * PAD + (tn << 2));
            float a[4] = {q4.x, q4.y, q4.z, q4.w};
            float bb[4] = {k4.x, k4.y, k4.z, k4.w};
            #pragma unroll
            for (int i = 0; i < 4; i++)
                #pragma unroll
                for (int j = 0; j < 4; j++)
                    s[i][j] = fmaf(a[i], bb[j], s[i][j]);
        }

        // bias + masks, store transposed (sSt[c][r])
        #pragma unroll
        for (int i = 0; i < 4; i++) {
            int r = tm * 4 + i;
            int qi = qt * 64 + r;
            #pragma unroll
            for (int j = 0; j < 4; j++) {
                int c = tn * 4 + j;
                int kj = jt * 64 + c;
                float val = s[i][j] * scale
                          - dcy * fabsf(tq[r] - tk[c]) * (1.0f / 24.0f);
                if (kj > qi || km[c] == 0.f) val = -1e30f;
                sSt[c * PAD + r] = val;
            }
        }
        __syncthreads();

        // ---- online softmax: thread t < 64 owns row t ----
        if (tid < 64) {
            int r = tid;
            float tmax = -1e30f;
            #pragma unroll 8
            for (int c = 0; c < 64; c++) tmax = fmaxf(tmax, sSt[c * PAD + r]);
            float mold = mrow[r];
            float mnew = fmaxf(mold, tmax);
            float fac  = __expf(mold - mnew);   // mold==mnew==-1e30 -> 1, acc is 0, safe
            float sum  = 0.f;
            #pragma unroll 8
            for (int c = 0; c < 64; c++) {
                float sv = sSt[c * PAD + r];
                float p = (sv <= -1e29f) ? 0.f : __expf(sv - mnew);
                sSt[c * PAD + r] = p;
                sum += p;
            }
            lrow[r] = lrow[r] * fac + sum;
            mrow[r] = mnew;
            frow[r] = fac;
        }
        __syncthreads();

        // ---- O = O*fac + P V ----
        #pragma unroll
        for (int i = 0; i < 4; i++) {
            float f = frow[tm * 4 + i];
            #pragma unroll
            for (int j = 0; j < 4; j++) acc[i][j] *= f;
        }
        #pragma unroll 4
        for (int c = 0; c < 64; c++) {
            float4 p4 = *(const float4*)(sSt + c * PAD + (tm << 2));
            float4 v4 = *(const float4*)(sV  + c * PAD + (tn << 2));
            float p[4] = {p4.x, p4.y, p4.z, p4.w};
            float vv[4] = {v4.x, v4.y, v4.z, v4.w};
            #pragma unroll
            for (int i = 0; i < 4; i++)
                #pragma unroll
                for (int j = 0; j < 4; j++)
                    acc[i][j] = fmaf(p[i], vv[j], acc[i][j]);
        }
        __syncthreads();   // protect smem before next tile's loads
    }

    // ---- write out: [B, L, H*dh] ----
    #pragma unroll
    for (int i = 0; i < 4; i++) {
        int r = tm * 4 + i;
        int qi = qt * 64 + r;
        float inv = 1.0f / lrow[r];
        float4 o;
        o.x = acc[i][0] * inv; o.y = acc[i][1] * inv;
        o.z = acc[i][2] * inv; o.w = acc[i][3] * inv;
        *(float4*)&out[((size_t)b * L_ + qi) * D_ + h * DH_ + tn * 4] = o;
    }
}

// ============================================================
// launch
// ============================================================
extern "C" void kernel_launch(void* const* d_in, const int* in_sizes, int n_in,
                              void* d_out, int out_size) {
    const float* x      = (const float*)d_in[0];
    const float* tsb    = (const float*)d_in[1];
    const float* mask   = (const float*)d_in[2];
    const float* ln1_g  = (const float*)d_in[3];
    const float* ln1_b  = (const float*)d_in[4];
    const float* w_qkv  = (const float*)d_in[5];
    const float* w_out  = (const float*)d_in[6];
    const float* decay  = (const float*)d_in[7];
    const float* ln2_g  = (const float*)d_in[8];
    const float* ln2_b  = (const float*)d_in[9];
    const float* w_ff1  = (const float*)d_in[10];
    const float* w_ff2  = (const float*)d_in[11];
    float* out = (float*)d_out;

    float *xn, *q, *k, *v, *att, *x1, *hh, *ff;
    cudaGetSymbolAddress((void**)&xn,  g_xn);
    cudaGetSymbolAddress((void**)&q,   g_q);
    cudaGetSymbolAddress((void**)&k,   g_k);
    cudaGetSymbolAddress((void**)&v,   g_v);
    cudaGetSymbolAddress((void**)&att, g_att);
    cudaGetSymbolAddress((void**)&x1,  g_x1);
    cudaGetSymbolAddress((void**)&hh,  g_h);
    cudaGetSymbolAddress((void**)&ff,  g_ff);

    int attn_smem = (4 * 64 * PAD + 6 * 64) * sizeof(float);   // ~71 KB
    cudaFuncSetAttribute(attn_kernel, cudaFuncAttributeMaxDynamicSharedMemorySize, attn_smem);

    // 1) LN1
    ln_kernel<<<BL_, 256>>>(x, ln1_g, ln1_b, xn);

    // 2) QKV GEMM: [8192,512] @ [1536,512]^T
    gemm_kernel<<<dim3(1536 / 128, BL_ / 128), 256>>>(
        xn, w_qkv, BL_, 1536, D_, GEMM_MODE_QKV, nullptr, nullptr, q, k, v);

    // 3) attention
    attn_kernel<<<dim3(L_ / 64, B_ * H_), 256, attn_smem>>>(
        q, k, v, tsb, mask, decay, att);

    // 4) out-proj + residual: x1 = x + att @ w_out^T
    gemm_kernel<<<dim3(D_ / 128, BL_ / 128), 256>>>(
        att, w_out, BL_, D_, D_, GEMM_MODE_RESID, x, x1, nullptr, nullptr, nullptr);

    // 5) LN2
    ln_kernel<<<BL_, 256>>>(x1, ln2_g, ln2_b, hh);

    // 6) FF1 + SiLU
    gemm_kernel<<<dim3(FF_ / 128, BL_ / 128), 256>>>(
        hh, w_ff1, BL_, FF_, D_, GEMM_MODE_SILU, nullptr, ff, nullptr, nullptr, nullptr);

    // 7) FF2 + residual -> d_out
    gemm_kernel<<<dim3(D_ / 128, BL_ / 128), 256>>>(
        ff, w_ff2, BL_, D_, FF_, GEMM_MODE_RESID, x1, out, nullptr, nullptr, nullptr);
}

// round 4
// speedup vs baseline: 3.2809x; 3.2809x over previous
#include <cuda_runtime.h>
#include <cuda_bf16.h>
#include <math.h>
#include <stdint.h>

#define B_  2
#define L_  4096
#define D_  512
#define H_  8
#define DH_ 64
#define BL_ 8192
#define FF_ 2048

// ---------------- scratch ----------------
__device__ float g_xn [BL_ * D_];
__device__ float g_q  [B_ * H_ * L_ * DH_];
__device__ float g_k  [B_ * H_ * L_ * DH_];
__device__ float g_v  [B_ * H_ * L_ * DH_];
__device__ float g_att[BL_ * D_];
__device__ float g_x1 [BL_ * D_];
__device__ float g_h  [BL_ * D_];
__device__ float g_ff [BL_ * FF_];
__device__ float g_w0 [3 * D_ * D_];
__device__ float g_w1 [D_ * D_];
__device__ float g_w2 [FF_ * D_];
__device__ float g_w3 [D_ * FF_];

__device__ __forceinline__ float rnd_tf32(float v) {
    uint32_t u;
    asm("cvt.rna.tf32.f32 %0, %1;" : "=r"(u) : "f"(v));
    return __uint_as_float(u);
}
__device__ __forceinline__ uint32_t f2u(float v) { return __float_as_uint(v); }

#define MMA_TF32(d, a, b)                                                    \
    asm volatile(                                                            \
        "mma.sync.aligned.m16n8k8.row.col.f32.tf32.tf32.f32 "                \
        "{%0,%1,%2,%3}, {%4,%5,%6,%7}, {%8,%9}, {%0,%1,%2,%3};"              \
        : "+f"(d[0]), "+f"(d[1]), "+f"(d[2]), "+f"(d[3])                     \
        : "r"(a[0]), "r"(a[1]), "r"(a[2]), "r"(a[3]), "r"(b[0]), "r"(b[1]))

// ============ weight rounding to tf32 grid ============
__global__ __launch_bounds__(256) void round_kernel(const float* __restrict__ in,
                                                    float* __restrict__ out, int n) {
    int i = (blockIdx.x * 256 + threadIdx.x) * 4;
    if (i < n) {
        float4 v = *(const float4*)(in + i);
        v.x = rnd_tf32(v.x); v.y = rnd_tf32(v.y);
        v.z = rnd_tf32(v.z); v.w = rnd_tf32(v.w);
        *(float4*)(out + i) = v;
    }
}

// ============ LayerNorm (tf32-rounded output) ============
__global__ __launch_bounds__(256) void ln_kernel(const float* __restrict__ x,
                                                 const float* __restrict__ g,
                                                 const float* __restrict__ b,
                                                 float* __restrict__ y) {
    int row = blockIdx.x;
    const float* xr = x + (size_t)row * D_;
    float* yr = y + (size_t)row * D_;
    int tid = threadIdx.x;
    float v0 = xr[tid], v1 = xr[tid + 256];
    float s = v0 + v1, ss = v0 * v0 + v1 * v1;
    #pragma unroll
    for (int o = 16; o > 0; o >>= 1) {
        s  += __shfl_xor_sync(0xffffffffu, s,  o);
        ss += __shfl_xor_sync(0xffffffffu, ss, o);
    }
    __shared__ float red[16];
    int w = tid >> 5, lane = tid & 31;
    if (lane == 0) { red[w] = s; red[w + 8] = ss; }
    __syncthreads();
    float S = 0.f, SS = 0.f;
    #pragma unroll
    for (int i = 0; i < 8; i++) { S += red[i]; SS += red[i + 8]; }
    float mu = S * (1.0f / D_);
    float inv = rsqrtf(SS * (1.0f / D_) - mu * mu + 1e-5f);
    yr[tid]       = rnd_tf32((v0 - mu) * inv * g[tid]       + b[tid]);
    yr[tid + 256] = rnd_tf32((v1 - mu) * inv * g[tid + 256] + b[tid + 256]);
}

// ============ mma.sync tf32 GEMM: C = A[M,K] @ W[N,K]^T ============
// 128x128 block, 256 thr, warp grid 2(M)x4(N), warp tile 64x32, K chunk 32, 4-stage cp.async
#define SROW 36
#define STAGE_F (128 * SROW * 2)
#define GEMM_SMEM_B (4 * STAGE_F * 4)
#define MODE_QKV   0
#define MODE_RESID 1
#define MODE_SILU  2

__global__ __launch_bounds__(256, 1) void mma_gemm(
    const float* __restrict__ A, const float* __restrict__ W,
    int K, int N, int mode, const float* __restrict__ resid,
    float* __restrict__ out, float* __restrict__ oq,
    float* __restrict__ okk, float* __restrict__ ov)
{
    extern __shared__ float sm[];
    uint32_t sbase = (uint32_t)__cvta_generic_to_shared(sm);
    int tid = threadIdx.x;
    int wid = tid >> 5, lane = tid & 31;
    int wm = wid & 1, wn = wid >> 1;
    int g = lane >> 2, qd = lane & 3;
    int bm = blockIdx.y, bn = blockIdx.x;
    const float* Ab = A + (size_t)bm * 128 * K;
    const float* Wb = W + (size_t)bn * 128 * K;
    const int NC = K >> 5;

    float acc[4][4][4];
    #pragma unroll
    for (int i = 0; i < 4; i++)
        #pragma unroll
        for (int j = 0; j < 4; j++)
            #pragma unroll
            for (int e = 0; e < 4; e++) acc[i][j][e] = 0.f;

    auto load_stage = [&](int c, int st) {
        int k0 = c << 5;
        #pragma unroll
        for (int i = 0; i < 4; i++) {
            int idx = tid + i * 256;
            int row = idx >> 3, c4 = (idx & 7) << 2;
            uint32_t da = sbase + (uint32_t)((st * STAGE_F + row * SROW + c4) << 2);
            asm volatile("cp.async.cg.shared.global [%0], [%1], 16;"
                         :: "r"(da), "l"(Ab + (size_t)row * K + k0 + c4) : "memory");
            asm volatile("cp.async.cg.shared.global [%0], [%1], 16;"
                         :: "r"(da + 128 * SROW * 4), "l"(Wb + (size_t)row * K + k0 + c4) : "memory");
        }
        asm volatile("cp.async.commit_group;" ::: "memory");
    };

    load_stage(0, 0); load_stage(1, 1); load_stage(2, 2);

    for (int c = 0; c < NC; c++) {
        asm volatile("cp.async.wait_group 2;" ::: "memory");
        __syncthreads();
        if (c + 3 < NC) load_stage(c + 3, (c + 3) & 3);

        const float* As = sm + (c & 3) * STAGE_F + (wm * 64) * SROW;
        const float* Bs = sm + (c & 3) * STAGE_F + 128 * SROW + (wn * 32) * SROW;
        #pragma unroll
        for (int ks = 0; ks < 4; ks++) {
            int k0 = ks * 8;
            uint32_t a[4][4], b[4][2];
            #pragma unroll
            for (int mt = 0; mt < 4; mt++) {
                const float* ap = As + mt * 16 * SROW;
                a[mt][0] = f2u(ap[(g    ) * SROW + k0 + qd    ]);
                a[mt][1] = f2u(ap[(g + 8) * SROW + k0 + qd    ]);
                a[mt][2] = f2u(ap[(g    ) * SROW + k0 + qd + 4]);
                a[mt][3] = f2u(ap[(g + 8) * SROW + k0 + qd + 4]);
            }
            #pragma unroll
            for (int nt = 0; nt < 4; nt++) {
                const float* bp = Bs + nt * 8 * SROW;
                b[nt][0] = f2u(bp[g * SROW + k0 + qd    ]);
                b[nt][1] = f2u(bp[g * SROW + k0 + qd + 4]);
            }
            #pragma unroll
            for (int mt = 0; mt < 4; mt++)
                #pragma unroll
                for (int nt = 0; nt < 4; nt++)
                    MMA_TF32(acc[mt][nt], a[mt], b[nt]);
        }
    }

    // epilogue
    #pragma unroll
    for (int mt = 0; mt < 4; mt++) {
        #pragma unroll
        for (int nt = 0; nt < 4; nt++) {
            int cb = bn * 128 + wn * 32 + nt * 8 + 2 * qd;
            #pragma unroll
            for (int hi = 0; hi < 2; hi++) {
                int r = bm * 128 + wm * 64 + mt * 16 + g + hi * 8;
                float v0 = acc[mt][nt][hi * 2], v1 = acc[mt][nt][hi * 2 + 1];
                if (mode == MODE_QKV) {
                    int which = cb >> 9, h = (cb >> 6) & 7, d0 = cb & 63;
                    int bb = r >> 12, l = r & 4095;
                    float* dst = (which == 0) ? oq : (which == 1) ? okk : ov;
                    float2 o2 = {rnd_tf32(v0), rnd_tf32(v1)};
                    *(float2*)(dst + (((size_t)bb * H_ + h) * L_ + l) * DH_ + d0) = o2;
                } else if (mode == MODE_RESID) {
                    size_t idx = (size_t)r * N + cb;
                    float2 rv = *(const float2*)(resid + idx);
                    float2 o2 = {rv.x + v0, rv.y + v1};
                    *(float2*)(out + idx) = o2;
                } else {
                    size_t idx = (size_t)r * N + cb;
                    float2 o2 = {rnd_tf32(v0 / (1.0f + __expf(-v0))),
                                 rnd_tf32(v1 / (1.0f + __expf(-v1)))};
                    *(float2*)(out + idx) = o2;
                }
            }
        }
    }
}

// ============ flash attention, mma.sync tf32 ============
// 128 thr (4 warps), q-tile 64, warp strip 16 rows; S and PV on tensor cores.
#define QS 68
#define VSS 72
#define ATTN_SMEM_B ((64 * QS * 3 + 64 * VSS + 192) * 4)

__global__ __launch_bounds__(128) void attn_kernel(
    const float* __restrict__ q, const float* __restrict__ k,
    const float* __restrict__ v, const float* __restrict__ ts,
    const float* __restrict__ mask, const float* __restrict__ decay_rate,
    float* __restrict__ out)
{
    extern __shared__ float sm[];
    float* Qs  = sm;
    float* Kc  = Qs + 64 * QS;
    float* Vsm = Kc + 64 * QS;
    float* Ps  = Vsm + 64 * VSS;
    float* tq  = Ps + 64 * QS;
    float* tk  = tq + 64;
    float* km  = tk + 64;

    int qt = gridDim.x - 1 - blockIdx.x;
    int bh = blockIdx.y, b = bh >> 3, h = bh & 7;
    int tid = threadIdx.x, wid = tid >> 5, lane = tid & 31;
    int g = lane >> 2, qd = lane & 3;
    int rbase = wid * 16;

    const float* qb = q + ((size_t)bh * L_ + qt * 64) * DH_;
    for (int i = tid; i < 1024; i += 128) {
        int r = i >> 4, c4 = (i & 15) << 2;
        *(float4*)(Qs + r * QS + c4) = *(const float4*)(qb + r * DH_ + c4);
    }
    if (tid < 64) tq[tid] = ts[b * L_ + qt * 64 + tid];

    float dcy = log1pf(__expf(decay_rate[h])) * (1.0f / 24.0f);
    float mprev[2] = {-1e30f, -1e30f};
    float lsum[2] = {0.f, 0.f};
    float o[8][4];
    #pragma unroll
    for (int i = 0; i < 8; i++)
        #pragma unroll
        for (int e = 0; e < 4; e++) o[i][e] = 0.f;
    __syncthreads();

    for (int jt = 0; jt <= qt; jt++) {
        __syncthreads();
        const float* kb = k + ((size_t)bh * L_ + jt * 64) * DH_;
        const float* vb = v + ((size_t)bh * L_ + jt * 64) * DH_;
        for (int i = tid; i < 1024; i += 128) {
            int r = i >> 4, c4 = (i & 15) << 2;
            *(float4*)(Kc  + r * QS  + c4) = *(const float4*)(kb + r * DH_ + c4);
            *(float4*)(Vsm + r * VSS + c4) = *(const float4*)(vb + r * DH_ + c4);
        }
        if (tid < 64) {
            tk[tid] = ts[b * L_ + jt * 64 + tid];
            km[tid] = mask[b * L_ + jt * 64 + tid];
        }
        __syncthreads();

        // ---- S = Q K^T ----
        float s[8][4];
        #pragma unroll
        for (int i = 0; i < 8; i++)
            #pragma unroll
            for (int e = 0; e < 4; e++) s[i][e] = 0.f;
        #pragma unroll
        for (int ks = 0; ks < 8; ks++) {
            int k0 = ks * 8;
            uint32_t a[4];
            a[0] = f2u(Qs[(rbase + g    ) * QS + k0 + qd    ]);
            a[1] = f2u(Qs[(rbase + 8 + g) * QS + k0 + qd    ]);
            a[2] = f2u(Qs[(rbase + g    ) * QS + k0 + qd + 4]);
            a[3] = f2u(Qs[(rbase + 8 + g) * QS + k0 + qd + 4]);
            #pragma unroll
            for (int nt = 0; nt < 8; nt++) {
                uint32_t bb[2];
                bb[0] = f2u(Kc[(nt * 8 + g) * QS + k0 + qd    ]);
                bb[1] = f2u(Kc[(nt * 8 + g) * QS + k0 + qd + 4]);
                MMA_TF32(s[nt], a, bb);
            }
        }

        // ---- bias + masks ----
        int qi0 = qt * 64 + rbase + g;
        float tq0 = tq[rbase + g], tq1 = tq[rbase + 8 + g];
        #pragma unroll
        for (int nt = 0; nt < 8; nt++) {
            #pragma unroll
            for (int ci = 0; ci < 4; ci++) {
                int col = nt * 8 + 2 * qd + (ci & 1);
                int kj = jt * 64 + col;
                int hi = ci >> 1;
                float val = s[nt][ci] * 0.125f
                          - dcy * fabsf((hi ? tq1 : tq0) - tk[col]);
                if (kj > qi0 + hi * 8 || km[col] == 0.f) val = -1e30f;
                s[nt][ci] = val;
            }
        }

        // ---- online softmax ----
        float rmax[2] = {-1e30f, -1e30f};
        #pragma unroll
        for (int nt = 0; nt < 8; nt++) {
            rmax[0] = fmaxf(rmax[0], fmaxf(s[nt][0], s[nt][1]));
            rmax[1] = fmaxf(rmax[1], fmaxf(s[nt][2], s[nt][3]));
        }
        #pragma unroll
        for (int off = 1; off < 4; off <<= 1) {
            rmax[0] = fmaxf(rmax[0], __shfl_xor_sync(0xffffffffu, rmax[0], off));
            rmax[1] = fmaxf(rmax[1], __shfl_xor_sync(0xffffffffu, rmax[1], off));
        }
        float mnew[2], fac[2], ps[2] = {0.f, 0.f};
        #pragma unroll
        for (int hi = 0; hi < 2; hi++) {
            mnew[hi] = fmaxf(mprev[hi], rmax[hi]);
            fac[hi]  = __expf(mprev[hi] - mnew[hi]);
        }
        #pragma unroll
        for (int nt = 0; nt < 8; nt++) {
            #pragma unroll
            for (int ci = 0; ci < 4; ci++) {
                float sv = s[nt][ci];
                float p = (sv <= -1e29f) ? 0.f : __expf(sv - mnew[ci >> 1]);
                s[nt][ci] = p;
                ps[ci >> 1] += p;
            }
        }
        #pragma unroll
        for (int off = 1; off < 4; off <<= 1) {
            ps[0] += __shfl_xor_sync(0xffffffffu, ps[0], off);
            ps[1] += __shfl_xor_sync(0xffffffffu, ps[1], off);
        }
        #pragma unroll
        for (int hi = 0; hi < 2; hi++) {
            lsum[hi] = lsum[hi] * fac[hi] + ps[hi];
            mprev[hi] = mnew[hi];
        }

        // ---- write P (tf32) + rescale O ----
        #pragma unroll
        for (int nt = 0; nt < 8; nt++) {
            float2 p0 = {rnd_tf32(s[nt][0]), rnd_tf32(s[nt][1])};
            float2 p1 = {rnd_tf32(s[nt][2]), rnd_tf32(s[nt][3])};
            *(float2*)(Ps + (rbase + g    ) * QS + nt * 8 + 2 * qd) = p0;
            *(float2*)(Ps + (rbase + 8 + g) * QS + nt * 8 + 2 * qd) = p1;
            o[nt][0] *= fac[0]; o[nt][1] *= fac[0];
            o[nt][2] *= fac[1]; o[nt][3] *= fac[1];
        }
        __syncwarp();

        // ---- O += P V ----
        #pragma unroll
        for (int ks = 0; ks < 8; ks++) {
            int k0 = ks * 8;
            uint32_t a[4];
            a[0] = f2u(Ps[(rbase + g    ) * QS + k0 + qd    ]);
            a[1] = f2u(Ps[(rbase + 8 + g) * QS + k0 + qd    ]);
            a[2] = f2u(Ps[(rbase + g    ) * QS + k0 + qd + 4]);
            a[3] = f2u(Ps[(rbase + 8 + g) * QS + k0 + qd + 4]);
            #pragma unroll
            for (int nt = 0; nt < 8; nt++) {
                uint32_t bb[2];
                bb[0] = f2u(Vsm[(k0 + qd    ) * VSS + nt * 8 + g]);
                bb[1] = f2u(Vsm[(k0 + qd + 4) * VSS + nt * 8 + g]);
                MMA_TF32(o[nt], a, bb);
            }
        }
    }

    // ---- output ----
    float inv0 = 1.0f / lsum[0], inv1 = 1.0f / lsum[1];
    int r0 = qt * 64 + rbase + g;
    #pragma unroll
    for (int nt = 0; nt < 8; nt++) {
        int col = h * 64 + nt * 8 + 2 * qd;
        float2 o0 = {rnd_tf32(o[nt][0] * inv0), rnd_tf32(o[nt][1] * inv0)};
        float2 o1 = {rnd_tf32(o[nt][2] * inv1), rnd_tf32(o[nt][3] * inv1)};
        *(float2*)(out + (size_t)(b * L_ + r0    ) * D_ + col) = o0;
        *(float2*)(out + (size_t)(b * L_ + r0 + 8) * D_ + col) = o1;
    }
}

// ============ launch ============
extern "C" void kernel_launch(void* const* d_in, const int* in_sizes, int n_in,
                              void* d_out, int out_size) {
    const float* x     = (const float*)d_in[0];
    const float* tsb   = (const float*)d_in[1];
    const float* mask  = (const float*)d_in[2];
    const float* ln1_g = (const float*)d_in[3];
    const float* ln1_b = (const float*)d_in[4];
    const float* w_qkv = (const float*)d_in[5];
    const float* w_out = (const float*)d_in[6];
    const float* decay = (const float*)d_in[7];
    const float* ln2_g = (const float*)d_in[8];
    const float* ln2_b = (const float*)d_in[9];
    const float* w_ff1 = (const float*)d_in[10];
    const float* w_ff2 = (const float*)d_in[11];
    float* out = (float*)d_out;

    float *xn, *q, *k, *v, *att, *x1, *hh, *ff, *w0, *w1, *w2, *w3;
    cudaGetSymbolAddress((void**)&xn, g_xn);
    cudaGetSymbolAddress((void**)&q, g_q);
    cudaGetSymbolAddress((void**)&k, g_k);
    cudaGetSymbolAddress((void**)&v, g_v);
    cudaGetSymbolAddress((void**)&att, g_att);
    cudaGetSymbolAddress((void**)&x1, g_x1);
    cudaGetSymbolAddress((void**)&hh, g_h);
    cudaGetSymbolAddress((void**)&ff, g_ff);
    cudaGetSymbolAddress((void**)&w0, g_w0);
    cudaGetSymbolAddress((void**)&w1, g_w1);
    cudaGetSymbolAddress((void**)&w2, g_w2);
    cudaGetSymbolAddress((void**)&w3, g_w3);

    cudaFuncSetAttribute(mma_gemm, cudaFuncAttributeMaxDynamicSharedMemorySize, GEMM_SMEM_B);
    cudaFuncSetAttribute(attn_kernel, cudaFuncAttributeMaxDynamicSharedMemorySize, ATTN_SMEM_B);

    round_kernel<<<3 * D_ * D_ / 1024, 256>>>(w_qkv, w0, 3 * D_ * D_);
    round_kernel<<<D_ * D_ / 1024, 256>>>(w_out, w1, D_ * D_);
    round_kernel<<<FF_ * D_ / 1024, 256>>>(w_ff1, w2, FF_ * D_);
    round_kernel<<<D_ * FF_ / 1024, 256>>>(w_ff2, w3, D_ * FF_);

    ln_kernel<<<BL_, 256>>>(x, ln1_g, ln1_b, xn);
    mma_gemm<<<dim3(1536 / 128, BL_ / 128), 256, GEMM_SMEM_B>>>(
        xn, w0, D_, 1536, MODE_QKV, nullptr, nullptr, q, k, v);
    attn_kernel<<<dim3(L_ / 64, B_ * H_), 128, ATTN_SMEM_B>>>(
        q, k, v, tsb, mask, decay, att);
    mma_gemm<<<dim3(D_ / 128, BL_ / 128), 256, GEMM_SMEM_B>>>(
        att, w1, D_, D_, MODE_RESID, x, x1, nullptr, nullptr, nullptr);
    ln_kernel<<<BL_, 256>>>(x1, ln2_g, ln2_b, hh);
    mma_gemm<<<dim3(FF_ / 128, BL_ / 128), 256, GEMM_SMEM_B>>>(
        hh, w2, D_, FF_, MODE_SILU, nullptr, ff, nullptr, nullptr, nullptr);
    mma_gemm<<<dim3(D_ / 128, BL_ / 128), 256, GEMM_SMEM_B>>>(
        ff, w3, FF_, D_, MODE_RESID, x1, out, nullptr, nullptr, nullptr);
}

// round 5
// speedup vs baseline: 3.3056x; 1.0075x over previous
#include <cuda_runtime.h>
#include <cuda_bf16.h>
#include <math.h>
#include <stdint.h>

#define B_  2
#define L_  4096
#define D_  512
#define H_  8
#define DH_ 64
#define BL_ 8192
#define FF_ 2048

// ---------------- scratch ----------------
__device__ float g_xn [BL_ * D_];
__device__ float g_q  [B_ * H_ * L_ * DH_];
__device__ float g_k  [B_ * H_ * L_ * DH_];
__device__ float g_v  [B_ * H_ * L_ * DH_];
__device__ float g_att[BL_ * D_];
__device__ float g_x1 [BL_ * D_];
__device__ float g_h  [BL_ * D_];
__device__ float g_ff [BL_ * FF_];
__device__ float g_w0 [3 * D_ * D_];
__device__ float g_w1 [D_ * D_];
__device__ float g_w2 [FF_ * D_];
__device__ float g_w3 [D_ * FF_];

__device__ __forceinline__ float rnd_tf32(float v) {
    uint32_t u;
    asm("cvt.rna.tf32.f32 %0, %1;" : "=r"(u) : "f"(v));
    return __uint_as_float(u);
}
__device__ __forceinline__ uint32_t f2u(float v) { return __float_as_uint(v); }

#define MMA_TF32(d, a, b)                                                    \
    asm volatile(                                                            \
        "mma.sync.aligned.m16n8k8.row.col.f32.tf32.tf32.f32 "                \
        "{%0,%1,%2,%3}, {%4,%5,%6,%7}, {%8,%9}, {%0,%1,%2,%3};"              \
        : "+f"(d[0]), "+f"(d[1]), "+f"(d[2]), "+f"(d[3])                     \
        : "r"(a[0]), "r"(a[1]), "r"(a[2]), "r"(a[3]), "r"(b[0]), "r"(b[1]))

// ============ fused weight rounding (all 4 weights, one launch) ============
__global__ __launch_bounds__(256) void round_all_kernel(
    const float* __restrict__ s0, float* __restrict__ d0,
    const float* __restrict__ s1, float* __restrict__ d1,
    const float* __restrict__ s2, float* __restrict__ d2,
    const float* __restrict__ s3, float* __restrict__ d3)
{
    const int n0 = 3 * D_ * D_, n1 = D_ * D_, n2 = FF_ * D_, n3 = D_ * FF_;
    int i = (blockIdx.x * 256 + threadIdx.x) * 4;
    const float* src; float* dst; int off;
    if (i < n0)                { src = s0; dst = d0; off = i; }
    else if (i < n0 + n1)      { src = s1; dst = d1; off = i - n0; }
    else if (i < n0 + n1 + n2) { src = s2; dst = d2; off = i - n0 - n1; }
    else                       { src = s3; dst = d3; off = i - n0 - n1 - n2; }
    float4 v = *(const float4*)(src + off);
    v.x = rnd_tf32(v.x); v.y = rnd_tf32(v.y);
    v.z = rnd_tf32(v.z); v.w = rnd_tf32(v.w);
    *(float4*)(dst + off) = v;
}

// ============ LayerNorm (tf32-rounded output) ============
__global__ __launch_bounds__(256) void ln_kernel(const float* __restrict__ x,
                                                 const float* __restrict__ g,
                                                 const float* __restrict__ b,
                                                 float* __restrict__ y) {
    int row = blockIdx.x;
    const float* xr = x + (size_t)row * D_;
    float* yr = y + (size_t)row * D_;
    int tid = threadIdx.x;
    float v0 = xr[tid], v1 = xr[tid + 256];
    float s = v0 + v1, ss = v0 * v0 + v1 * v1;
    #pragma unroll
    for (int o = 16; o > 0; o >>= 1) {
        s  += __shfl_xor_sync(0xffffffffu, s,  o);
        ss += __shfl_xor_sync(0xffffffffu, ss, o);
    }
    __shared__ float red[16];
    int w = tid >> 5, lane = tid & 31;
    if (lane == 0) { red[w] = s; red[w + 8] = ss; }
    __syncthreads();
    float S = 0.f, SS = 0.f;
    #pragma unroll
    for (int i = 0; i < 8; i++) { S += red[i]; SS += red[i + 8]; }
    float mu = S * (1.0f / D_);
    float inv = rsqrtf(SS * (1.0f / D_) - mu * mu + 1e-5f);
    yr[tid]       = rnd_tf32((v0 - mu) * inv * g[tid]       + b[tid]);
    yr[tid + 256] = rnd_tf32((v1 - mu) * inv * g[tid + 256] + b[tid + 256]);
}

// ============ mma.sync tf32 GEMM: C = A[M,K] @ W[N,K]^T ============
#define SROW 36
#define STAGE_F (128 * SROW * 2)
#define GEMM_SMEM_B (4 * STAGE_F * 4)
#define MODE_QKV   0
#define MODE_RESID 1
#define MODE_SILU  2

__global__ __launch_bounds__(256, 1) void mma_gemm(
    const float* __restrict__ A, const float* __restrict__ W,
    int K, int N, int mode, const float* __restrict__ resid,
    float* __restrict__ out, float* __restrict__ oq,
    float* __restrict__ okk, float* __restrict__ ov)
{
    extern __shared__ float sm[];
    uint32_t sbase = (uint32_t)__cvta_generic_to_shared(sm);
    int tid = threadIdx.x;
    int wid = tid >> 5, lane = tid & 31;
    int wm = wid & 1, wn = wid >> 1;
    int g = lane >> 2, qd = lane & 3;
    int bm = blockIdx.y, bn = blockIdx.x;
    const float* Ab = A + (size_t)bm * 128 * K;
    const float* Wb = W + (size_t)bn * 128 * K;
    const int NC = K >> 5;

    float acc[4][4][4];
    #pragma unroll
    for (int i = 0; i < 4; i++)
        #pragma unroll
        for (int j = 0; j < 4; j++)
            #pragma unroll
            for (int e = 0; e < 4; e++) acc[i][j][e] = 0.f;

    auto load_stage = [&](int c, int st) {
        int k0 = c << 5;
        #pragma unroll
        for (int i = 0; i < 4; i++) {
            int idx = tid + i * 256;
            int row = idx >> 3, c4 = (idx & 7) << 2;
            uint32_t da = sbase + (uint32_t)((st * STAGE_F + row * SROW + c4) << 2);
            asm volatile("cp.async.cg.shared.global [%0], [%1], 16;"
                         :: "r"(da), "l"(Ab + (size_t)row * K + k0 + c4) : "memory");
            asm volatile("cp.async.cg.shared.global [%0], [%1], 16;"
                         :: "r"(da + 128 * SROW * 4), "l"(Wb + (size_t)row * K + k0 + c4) : "memory");
        }
        asm volatile("cp.async.commit_group;" ::: "memory");
    };

    load_stage(0, 0); load_stage(1, 1); load_stage(2, 2);

    for (int c = 0; c < NC; c++) {
        asm volatile("cp.async.wait_group 2;" ::: "memory");
        __syncthreads();
        if (c + 3 < NC) load_stage(c + 3, (c + 3) & 3);

        const float* As = sm + (c & 3) * STAGE_F + (wm * 64) * SROW;
        const float* Bs = sm + (c & 3) * STAGE_F + 128 * SROW + (wn * 32) * SROW;
        #pragma unroll
        for (int ks = 0; ks < 4; ks++) {
            int k0 = ks * 8;
            uint32_t a[4][4], b[4][2];
            #pragma unroll
            for (int mt = 0; mt < 4; mt++) {
                const float* ap = As + mt * 16 * SROW;
                a[mt][0] = f2u(ap[(g    ) * SROW + k0 + qd    ]);
                a[mt][1] = f2u(ap[(g + 8) * SROW + k0 + qd    ]);
                a[mt][2] = f2u(ap[(g    ) * SROW + k0 + qd + 4]);
                a[mt][3] = f2u(ap[(g + 8) * SROW + k0 + qd + 4]);
            }
            #pragma unroll
            for (int nt = 0; nt < 4; nt++) {
                const float* bp = Bs + nt * 8 * SROW;
                b[nt][0] = f2u(bp[g * SROW + k0 + qd    ]);
                b[nt][1] = f2u(bp[g * SROW + k0 + qd + 4]);
            }
            #pragma unroll
            for (int mt = 0; mt < 4; mt++)
                #pragma unroll
                for (int nt = 0; nt < 4; nt++)
                    MMA_TF32(acc[mt][nt], a[mt], b[nt]);
        }
    }

    #pragma unroll
    for (int mt = 0; mt < 4; mt++) {
        #pragma unroll
        for (int nt = 0; nt < 4; nt++) {
            int cb = bn * 128 + wn * 32 + nt * 8 + 2 * qd;
            #pragma unroll
            for (int hi = 0; hi < 2; hi++) {
                int r = bm * 128 + wm * 64 + mt * 16 + g + hi * 8;
                float v0 = acc[mt][nt][hi * 2], v1 = acc[mt][nt][hi * 2 + 1];
                if (mode == MODE_QKV) {
                    int which = cb >> 9, h = (cb >> 6) & 7, d0 = cb & 63;
                    int bb = r >> 12, l = r & 4095;
                    float* dst = (which == 0) ? oq : (which == 1) ? okk : ov;
                    float2 o2 = {rnd_tf32(v0), rnd_tf32(v1)};
                    *(float2*)(dst + (((size_t)bb * H_ + h) * L_ + l) * DH_ + d0) = o2;
                } else if (mode == MODE_RESID) {
                    size_t idx = (size_t)r * N + cb;
                    float2 rv = *(const float2*)(resid + idx);
                    float2 o2 = {rv.x + v0, rv.y + v1};
                    *(float2*)(out + idx) = o2;
                } else {
                    size_t idx = (size_t)r * N + cb;
                    float2 o2 = {rnd_tf32(v0 / (1.0f + __expf(-v0))),
                                 rnd_tf32(v1 / (1.0f + __expf(-v1)))};
                    *(float2*)(out + idx) = o2;
                }
            }
        }
    }
}

// ============ flash attention, mma.sync tf32 ============
// Q tile 128 rows (8 warps x 16-row strips), K/V tile 64, double-buffered cp.async.
#define QS 68
#define VSS 72
#define AF_QS   (128 * QS)
#define AF_KC   (2 * 64 * QS)
#define AF_VD   (2 * 64 * VSS)
#define AF_PS   (128 * QS)
#define ATTN_F  (AF_QS + AF_KC + AF_VD + AF_PS + 128 + 128 + 128)
#define ATTN_SMEM_B (ATTN_F * 4)

__global__ __launch_bounds__(256) void attn_kernel(
    const float* __restrict__ q, const float* __restrict__ k,
    const float* __restrict__ v, const float* __restrict__ ts,
    const float* __restrict__ mask, const float* __restrict__ decay_rate,
    float* __restrict__ out)
{
    extern __shared__ float sm[];
    float* Qs  = sm;                    // [128][QS]
    float* Kc  = Qs + AF_QS;            // 2 x [64][QS]
    float* Vsm = Kc + AF_KC;            // 2 x [64][VSS]
    float* Ps  = Vsm + AF_VD;           // [128][QS]
    float* tq  = Ps + AF_PS;            // [128]
    float* tk  = tq + 128;              // 2 x [64]
    float* km  = tk + 128;              // 2 x [64]
    uint32_t smb = (uint32_t)__cvta_generic_to_shared(sm);

    int qt = gridDim.x - 1 - blockIdx.x;       // reversed for balance
    int bh = blockIdx.y, b = bh >> 3, h = bh & 7;
    int tid = threadIdx.x, wid = tid >> 5, lane = tid & 31;
    int g = lane >> 2, qd = lane & 3;
    int rbase = wid * 16;
    const int nkt = 2 * qt + 2;

    // Q tile (once)
    const float* qb = q + ((size_t)bh * L_ + qt * 128) * DH_;
    for (int i = tid; i < 2048; i += 256) {
        int r = i >> 4, c4 = (i & 15) << 2;
        *(float4*)(Qs + r * QS + c4) = *(const float4*)(qb + r * DH_ + c4);
    }
    if (tid < 128) tq[tid] = ts[b * L_ + qt * 128 + tid];

    float dcy = log1pf(__expf(decay_rate[h])) * (1.0f / 24.0f);
    float mprev[2] = {-1e30f, -1e30f};
    float lsum[2] = {0.f, 0.f};
    float o[8][4];
    #pragma unroll
    for (int i = 0; i < 8; i++)
        #pragma unroll
        for (int e = 0; e < 4; e++) o[i][e] = 0.f;

    auto load_kv = [&](int jt, int st) {
        const float* kb = k + ((size_t)bh * L_ + jt * 64) * DH_;
        const float* vb = v + ((size_t)bh * L_ + jt * 64) * DH_;
        uint32_t kdst = smb + (uint32_t)((AF_QS + st * 64 * QS) << 2);
        uint32_t vdst = smb + (uint32_t)((AF_QS + AF_KC + st * 64 * VSS) << 2);
        #pragma unroll
        for (int i = 0; i < 4; i++) {
            int idx = tid + i * 256;
            int r = idx >> 4, c4 = (idx & 15) << 2;
            asm volatile("cp.async.cg.shared.global [%0], [%1], 16;"
                         :: "r"(kdst + (uint32_t)((r * QS + c4) << 2)),
                            "l"(kb + (size_t)r * DH_ + c4) : "memory");
            asm volatile("cp.async.cg.shared.global [%0], [%1], 16;"
                         :: "r"(vdst + (uint32_t)((r * VSS + c4) << 2)),
                            "l"(vb + (size_t)r * DH_ + c4) : "memory");
        }
        if (tid < 64) {
            uint32_t tdst = smb + (uint32_t)((AF_QS + AF_KC + AF_VD + AF_PS + 128 + st * 64 + tid) << 2);
            asm volatile("cp.async.ca.shared.global [%0], [%1], 4;"
                         :: "r"(tdst), "l"(ts + b * L_ + jt * 64 + tid) : "memory");
            asm volatile("cp.async.ca.shared.global [%0], [%1], 4;"
                         :: "r"(tdst + 128 * 4), "l"(mask + b * L_ + jt * 64 + tid) : "memory");
        }
        asm volatile("cp.async.commit_group;" ::: "memory");
    };

    load_kv(0, 0);

    for (int jt = 0; jt < nkt; jt++) {
        int st = jt & 1;
        if (jt + 1 < nkt) {
            load_kv(jt + 1, (jt + 1) & 1);
            asm volatile("cp.async.wait_group 1;" ::: "memory");
        } else {
            asm volatile("cp.async.wait_group 0;" ::: "memory");
        }
        __syncthreads();

        const float* Kst = Kc + st * 64 * QS;
        const float* Vst = Vsm + st * 64 * VSS;
        const float* tks = tk + st * 64;
        const float* kms = km + st * 64;
        bool diag = (jt >= 2 * qt);

        // ---- S = Q K^T ----
        float s[8][4];
        #pragma unroll
        for (int i = 0; i < 8; i++)
            #pragma unroll
            for (int e = 0; e < 4; e++) s[i][e] = 0.f;
        #pragma unroll
        for (int ks = 0; ks < 8; ks++) {
            int k0 = ks * 8;
            uint32_t a[4];
            a[0] = f2u(Qs[(rbase + g    ) * QS + k0 + qd    ]);
            a[1] = f2u(Qs[(rbase + 8 + g) * QS + k0 + qd    ]);
            a[2] = f2u(Qs[(rbase + g    ) * QS + k0 + qd + 4]);
            a[3] = f2u(Qs[(rbase + 8 + g) * QS + k0 + qd + 4]);
            #pragma unroll
            for (int nt = 0; nt < 8; nt++) {
                uint32_t bb[2];
                bb[0] = f2u(Kst[(nt * 8 + g) * QS + k0 + qd    ]);
                bb[1] = f2u(Kst[(nt * 8 + g) * QS + k0 + qd + 4]);
                MMA_TF32(s[nt], a, bb);
            }
        }

        // ---- bias + masks ----
        int qi0 = qt * 128 + rbase + g;
        float tq0 = tq[rbase + g], tq1 = tq[rbase + 8 + g];
        #pragma unroll
        for (int nt = 0; nt < 8; nt++) {
            #pragma unroll
            for (int ci = 0; ci < 4; ci++) {
                int col = nt * 8 + 2 * qd + (ci & 1);
                int hi = ci >> 1;
                float val = s[nt][ci] * 0.125f
                          - dcy * fabsf((hi ? tq1 : tq0) - tks[col]);
                bool dead = (kms[col] == 0.f);
                if (diag) dead |= (jt * 64 + col > qi0 + hi * 8);
                if (dead) val = -1e30f;
                s[nt][ci] = val;
            }
        }

        // ---- online softmax ----
        float rmax[2] = {-1e30f, -1e30f};
        #pragma unroll
        for (int nt = 0; nt < 8; nt++) {
            rmax[0] = fmaxf(rmax[0], fmaxf(s[nt][0], s[nt][1]));
            rmax[1] = fmaxf(rmax[1], fmaxf(s[nt][2], s[nt][3]));
        }
        #pragma unroll
        for (int off = 1; off < 4; off <<= 1) {
            rmax[0] = fmaxf(rmax[0], __shfl_xor_sync(0xffffffffu, rmax[0], off));
            rmax[1] = fmaxf(rmax[1], __shfl_xor_sync(0xffffffffu, rmax[1], off));
        }
        float mnew[2], fac[2], ps[2] = {0.f, 0.f};
        #pragma unroll
        for (int hi = 0; hi < 2; hi++) {
            mnew[hi] = fmaxf(mprev[hi], rmax[hi]);
            fac[hi]  = __expf(mprev[hi] - mnew[hi]);
        }
        #pragma unroll
        for (int nt = 0; nt < 8; nt++) {
            #pragma unroll
            for (int ci = 0; ci < 4; ci++) {
                float sv = s[nt][ci];
                float p = (sv <= -1e29f) ? 0.f : __expf(sv - mnew[ci >> 1]);
                s[nt][ci] = p;
                ps[ci >> 1] += p;
            }
        }
        #pragma unroll
        for (int off = 1; off < 4; off <<= 1) {
            ps[0] += __shfl_xor_sync(0xffffffffu, ps[0], off);
            ps[1] += __shfl_xor_sync(0xffffffffu, ps[1], off);
        }
        #pragma unroll
        for (int hi = 0; hi < 2; hi++) {
            lsum[hi] = lsum[hi] * fac[hi] + ps[hi];
            mprev[hi] = mnew[hi];
        }

        // ---- write P (tf32) + rescale O ----
        #pragma unroll
        for (int nt = 0; nt < 8; nt++) {
            float2 p0 = {rnd_tf32(s[nt][0]), rnd_tf32(s[nt][1])};
            float2 p1 = {rnd_tf32(s[nt][2]), rnd_tf32(s[nt][3])};
            *(float2*)(Ps + (rbase + g    ) * QS + nt * 8 + 2 * qd) = p0;
            *(float2*)(Ps + (rbase + 8 + g) * QS + nt * 8 + 2 * qd) = p1;
            o[nt][0] *= fac[0]; o[nt][1] *= fac[0];
            o[nt][2] *= fac[1]; o[nt][3] *= fac[1];
        }
        __syncwarp();

        // ---- O += P V ----
        #pragma unroll
        for (int ks = 0; ks < 8; ks++) {
            int k0 = ks * 8;
            uint32_t a[4];
            a[0] = f2u(Ps[(rbase + g    ) * QS + k0 + qd    ]);
            a[1] = f2u(Ps[(rbase + 8 + g) * QS + k0 + qd    ]);
            a[2] = f2u(Ps[(rbase + g    ) * QS + k0 + qd + 4]);
            a[3] = f2u(Ps[(rbase + 8 + g) * QS + k0 + qd + 4]);
            #pragma unroll
            for (int nt = 0; nt < 8; nt++) {
                uint32_t bb[2];
                bb[0] = f2u(Vst[(k0 + qd    ) * VSS + nt * 8 + g]);
                bb[1] = f2u(Vst[(k0 + qd + 4) * VSS + nt * 8 + g]);
                MMA_TF32(o[nt], a, bb);
            }
        }
        __syncthreads();
    }

    // ---- output ----
    float inv0 = 1.0f / lsum[0], inv1 = 1.0f / lsum[1];
    int r0 = qt * 128 + rbase + g;
    #pragma unroll
    for (int nt = 0; nt < 8; nt++) {
        int col = h * 64 + nt * 8 + 2 * qd;
        float2 o0 = {rnd_tf32(o[nt][0] * inv0), rnd_tf32(o[nt][1] * inv0)};
        float2 o1 = {rnd_tf32(o[nt][2] * inv1), rnd_tf32(o[nt][3] * inv1)};
        *(float2*)(out + (size_t)(b * L_ + r0    ) * D_ + col) = o0;
        *(float2*)(out + (size_t)(b * L_ + r0 + 8) * D_ + col) = o1;
    }
}

// ============ launch ============
extern "C" void kernel_launch(void* const* d_in, const int* in_sizes, int n_in,
                              void* d_out, int out_size) {
    const float* x     = (const float*)d_in[0];
    const float* tsb   = (const float*)d_in[1];
    const float* mask  = (const float*)d_in[2];
    const float* ln1_g = (const float*)d_in[3];
    const float* ln1_b = (const float*)d_in[4];
    const float* w_qkv = (const float*)d_in[5];
    const float* w_out = (const float*)d_in[6];
    const float* decay = (const float*)d_in[7];
    const float* ln2_g = (const float*)d_in[8];
    const float* ln2_b = (const float*)d_in[9];
    const float* w_ff1 = (const float*)d_in[10];
    const float* w_ff2 = (const float*)d_in[11];
    float* out = (float*)d_out;

    float *xn, *q, *k, *v, *att, *x1, *hh, *ff, *w0, *w1, *w2, *w3;
    cudaGetSymbolAddress((void**)&xn, g_xn);
    cudaGetSymbolAddress((void**)&q, g_q);
    cudaGetSymbolAddress((void**)&k, g_k);
    cudaGetSymbolAddress((void**)&v, g_v);
    cudaGetSymbolAddress((void**)&att, g_att);
    cudaGetSymbolAddress((void**)&x1, g_x1);
    cudaGetSymbolAddress((void**)&hh, g_h);
    cudaGetSymbolAddress((void**)&ff, g_ff);
    cudaGetSymbolAddress((void**)&w0, g_w0);
    cudaGetSymbolAddress((void**)&w1, g_w1);
    cudaGetSymbolAddress((void**)&w2, g_w2);
    cudaGetSymbolAddress((void**)&w3, g_w3);

    cudaFuncSetAttribute(mma_gemm, cudaFuncAttributeMaxDynamicSharedMemorySize, GEMM_SMEM_B);
    cudaFuncSetAttribute(attn_kernel, cudaFuncAttributeMaxDynamicSharedMemorySize, ATTN_SMEM_B);

    const int n_total = 3 * D_ * D_ + D_ * D_ + FF_ * D_ + D_ * FF_;
    round_all_kernel<<<n_total / 1024, 256>>>(w_qkv, w0, w_out, w1, w_ff1, w2, w_ff2, w3);

    ln_kernel<<<BL_, 256>>>(x, ln1_g, ln1_b, xn);
    mma_gemm<<<dim3(1536 / 128, BL_ / 128), 256, GEMM_SMEM_B>>>(
        xn, w0, D_, 1536, MODE_QKV, nullptr, nullptr, q, k, v);
    attn_kernel<<<dim3(L_ / 128, B_ * H_), 256, ATTN_SMEM_B>>>(
        q, k, v, tsb, mask, decay, att);
    mma_gemm<<<dim3(D_ / 128, BL_ / 128), 256, GEMM_SMEM_B>>>(
        att, w1, D_, D_, MODE_RESID, x, x1, nullptr, nullptr, nullptr);
    ln_kernel<<<BL_, 256>>>(x1, ln2_g, ln2_b, hh);
    mma_gemm<<<dim3(FF_ / 128, BL_ / 128), 256, GEMM_SMEM_B>>>(
        hh, w2, D_, FF_, MODE_SILU, nullptr, ff, nullptr, nullptr, nullptr);
    mma_gemm<<<dim3(D_ / 128, BL_ / 128), 256, GEMM_SMEM_B>>>(
        ff, w3, FF_, D_, MODE_RESID, x1, out, nullptr, nullptr, nullptr);
}

// round 6
// speedup vs baseline: 3.5988x; 1.0887x over previous
#include <cuda_runtime.h>
#include <cuda_bf16.h>
#include <math.h>
#include <stdint.h>

#define B_  2
#define L_  4096
#define D_  512
#define H_  8
#define DH_ 64
#define BL_ 8192
#define FF_ 2048

// ---------------- scratch ----------------
__device__ float g_xn [BL_ * D_];
__device__ float g_q  [B_ * H_ * L_ * DH_];
__device__ float g_k  [B_ * H_ * L_ * DH_];
__device__ float g_v  [B_ * H_ * L_ * DH_];
__device__ float g_att[BL_ * D_];
__device__ float g_x1 [BL_ * D_];
__device__ float g_h  [BL_ * D_];
__device__ float g_ff [BL_ * FF_];
__device__ float g_w0 [3 * D_ * D_];
__device__ float g_w1 [D_ * D_];
__device__ float g_w2 [FF_ * D_];
__device__ float g_w3 [D_ * FF_];

__device__ __forceinline__ float rnd_tf32(float v) {
    uint32_t u;
    asm("cvt.rna.tf32.f32 %0, %1;" : "=r"(u) : "f"(v));
    return __uint_as_float(u);
}
__device__ __forceinline__ uint32_t f2u(float v) { return __float_as_uint(v); }

#define MMA_TF32(d, a, b)                                                    \
    asm volatile(                                                            \
        "mma.sync.aligned.m16n8k8.row.col.f32.tf32.tf32.f32 "                \
        "{%0,%1,%2,%3}, {%4,%5,%6,%7}, {%8,%9}, {%0,%1,%2,%3};"              \
        : "+f"(d[0]), "+f"(d[1]), "+f"(d[2]), "+f"(d[3])                     \
        : "r"(a[0]), "r"(a[1]), "r"(a[2]), "r"(a[3]), "r"(b[0]), "r"(b[1]))

// ============ fused weight rounding ============
__global__ __launch_bounds__(256) void round_all_kernel(
    const float* __restrict__ s0, float* __restrict__ d0,
    const float* __restrict__ s1, float* __restrict__ d1,
    const float* __restrict__ s2, float* __restrict__ d2,
    const float* __restrict__ s3, float* __restrict__ d3)
{
    const int n0 = 3 * D_ * D_, n1 = D_ * D_, n2 = FF_ * D_;
    int i = (blockIdx.x * 256 + threadIdx.x) * 4;
    const float* src; float* dst; int off;
    if (i < n0)                { src = s0; dst = d0; off = i; }
    else if (i < n0 + n1)      { src = s1; dst = d1; off = i - n0; }
    else if (i < n0 + n1 + n2) { src = s2; dst = d2; off = i - n0 - n1; }
    else                       { src = s3; dst = d3; off = i - n0 - n1 - n2; }
    float4 v = *(const float4*)(src + off);
    v.x = rnd_tf32(v.x); v.y = rnd_tf32(v.y);
    v.z = rnd_tf32(v.z); v.w = rnd_tf32(v.w);
    *(float4*)(dst + off) = v;
}

// ============ LayerNorm ============
__global__ __launch_bounds__(256) void ln_kernel(const float* __restrict__ x,
                                                 const float* __restrict__ g,
                                                 const float* __restrict__ b,
                                                 float* __restrict__ y) {
    int row = blockIdx.x;
    const float* xr = x + (size_t)row * D_;
    float* yr = y + (size_t)row * D_;
    int tid = threadIdx.x;
    float v0 = xr[tid], v1 = xr[tid + 256];
    float s = v0 + v1, ss = v0 * v0 + v1 * v1;
    #pragma unroll
    for (int o = 16; o > 0; o >>= 1) {
        s  += __shfl_xor_sync(0xffffffffu, s,  o);
        ss += __shfl_xor_sync(0xffffffffu, ss, o);
    }
    __shared__ float red[16];
    int w = tid >> 5, lane = tid & 31;
    if (lane == 0) { red[w] = s; red[w + 8] = ss; }
    __syncthreads();
    float S = 0.f, SS = 0.f;
    #pragma unroll
    for (int i = 0; i < 8; i++) { S += red[i]; SS += red[i + 8]; }
    float mu = S * (1.0f / D_);
    float inv = rsqrtf(SS * (1.0f / D_) - mu * mu + 1e-5f);
    yr[tid]       = rnd_tf32((v0 - mu) * inv * g[tid]       + b[tid]);
    yr[tid + 256] = rnd_tf32((v1 - mu) * inv * g[tid + 256] + b[tid + 256]);
}

// ============ mma.sync tf32 GEMM, 3-stage, 2 CTA/SM ============
#define SROW 36
#define STAGE_F (128 * SROW * 2)
#define GEMM_SMEM_B (3 * STAGE_F * 4)
#define MODE_QKV   0
#define MODE_RESID 1
#define MODE_SILU  2

__global__ __launch_bounds__(256, 2) void mma_gemm(
    const float* __restrict__ A, const float* __restrict__ W,
    int K, int N, int mode, const float* __restrict__ resid,
    float* __restrict__ out, float* __restrict__ oq,
    float* __restrict__ okk, float* __restrict__ ov)
{
    extern __shared__ float sm[];
    uint32_t sbase = (uint32_t)__cvta_generic_to_shared(sm);
    int tid = threadIdx.x;
    int wid = tid >> 5, lane = tid & 31;
    int wm = wid & 1, wn = wid >> 1;
    int g = lane >> 2, qd = lane & 3;
    int bm = blockIdx.y, bn = blockIdx.x;
    const float* Ab = A + (size_t)bm * 128 * K;
    const float* Wb = W + (size_t)bn * 128 * K;
    const int NC = K >> 5;

    float acc[4][4][4];
    #pragma unroll
    for (int i = 0; i < 4; i++)
        #pragma unroll
        for (int j = 0; j < 4; j++)
            #pragma unroll
            for (int e = 0; e < 4; e++) acc[i][j][e] = 0.f;

    auto load_stage = [&](int c, int st) {
        int k0 = c << 5;
        #pragma unroll
        for (int i = 0; i < 4; i++) {
            int idx = tid + i * 256;
            int row = idx >> 3, c4 = (idx & 7) << 2;
            uint32_t da = sbase + (uint32_t)((st * STAGE_F + row * SROW + c4) << 2);
            asm volatile("cp.async.cg.shared.global [%0], [%1], 16;"
                         :: "r"(da), "l"(Ab + (size_t)row * K + k0 + c4) : "memory");
            asm volatile("cp.async.cg.shared.global [%0], [%1], 16;"
                         :: "r"(da + 128 * SROW * 4), "l"(Wb + (size_t)row * K + k0 + c4) : "memory");
        }
        asm volatile("cp.async.commit_group;" ::: "memory");
    };

    load_stage(0, 0); load_stage(1, 1); load_stage(2, 2);
    int st = 0;

    for (int c = 0; c < NC; c++) {
        asm volatile("cp.async.wait_group 2;" ::: "memory");
        __syncthreads();

        const float* As = sm + st * STAGE_F + (wm * 64) * SROW;
        const float* Bs = sm + st * STAGE_F + 128 * SROW + (wn * 32) * SROW;
        #pragma unroll
        for (int ks = 0; ks < 4; ks++) {
            int k0 = ks * 8;
            uint32_t a[4][4], b[4][2];
            #pragma unroll
            for (int mt = 0; mt < 4; mt++) {
                const float* ap = As + mt * 16 * SROW;
                a[mt][0] = f2u(ap[(g    ) * SROW + k0 + qd    ]);
                a[mt][1] = f2u(ap[(g + 8) * SROW + k0 + qd    ]);
                a[mt][2] = f2u(ap[(g    ) * SROW + k0 + qd + 4]);
                a[mt][3] = f2u(ap[(g + 8) * SROW + k0 + qd + 4]);
            }
            #pragma unroll
            for (int nt = 0; nt < 4; nt++) {
                const float* bp = Bs + nt * 8 * SROW;
                b[nt][0] = f2u(bp[g * SROW + k0 + qd    ]);
                b[nt][1] = f2u(bp[g * SROW + k0 + qd + 4]);
            }
            #pragma unroll
            for (int mt = 0; mt < 4; mt++)
                #pragma unroll
                for (int nt = 0; nt < 4; nt++)
                    MMA_TF32(acc[mt][nt], a[mt], b[nt]);
        }
        __syncthreads();
        if (c + 3 < NC) load_stage(c + 3, st);
        st = (st == 2) ? 0 : st + 1;
    }

    #pragma unroll
    for (int mt = 0; mt < 4; mt++) {
        #pragma unroll
        for (int nt = 0; nt < 4; nt++) {
            int cb = bn * 128 + wn * 32 + nt * 8 + 2 * qd;
            #pragma unroll
            for (int hi = 0; hi < 2; hi++) {
                int r = bm * 128 + wm * 64 + mt * 16 + g + hi * 8;
                float v0 = acc[mt][nt][hi * 2], v1 = acc[mt][nt][hi * 2 + 1];
                if (mode == MODE_QKV) {
                    int which = cb >> 9, h = (cb >> 6) & 7, d0 = cb & 63;
                    int bb = r >> 12, l = r & 4095;
                    float* dst = (which == 0) ? oq : (which == 1) ? okk : ov;
                    float2 o2 = {rnd_tf32(v0), rnd_tf32(v1)};
                    *(float2*)(dst + (((size_t)bb * H_ + h) * L_ + l) * DH_ + d0) = o2;
                } else if (mode == MODE_RESID) {
                    size_t idx = (size_t)r * N + cb;
                    float2 rv = *(const float2*)(resid + idx);
                    float2 o2 = {rv.x + v0, rv.y + v1};
                    *(float2*)(out + idx) = o2;
                } else {
                    size_t idx = (size_t)r * N + cb;
                    float2 o2 = {rnd_tf32(v0 / (1.0f + __expf(-v0))),
                                 rnd_tf32(v1 / (1.0f + __expf(-v1)))};
                    *(float2*)(out + idx) = o2;
                }
            }
        }
    }
}

// ============ flash attention, mma.sync tf32, no P smem (shfl transform) ============
#define QS 68
#define VSS 72
#define AF_QS   (128 * QS)
#define AF_KC   (2 * 64 * QS)
#define AF_VD   (2 * 64 * VSS)
#define ATTN_F  (AF_QS + AF_KC + AF_VD + 128 + 128 + 128)
#define ATTN_SMEM_B (ATTN_F * 4)

__global__ __launch_bounds__(256, 2) void attn_kernel(
    const float* __restrict__ q, const float* __restrict__ k,
    const float* __restrict__ v, const float* __restrict__ ts,
    const float* __restrict__ mask, const float* __restrict__ decay_rate,
    float* __restrict__ out)
{
    extern __shared__ float sm[];
    float* Qs  = sm;                    // [128][QS]
    float* Kc  = Qs + AF_QS;            // 2 x [64][QS]
    float* Vsm = Kc + AF_KC;            // 2 x [64][VSS]
    float* tq  = Vsm + AF_VD;           // [128]
    float* tk  = tq + 128;              // 2 x [64]
    float* km  = tk + 128;              // 2 x [64]
    uint32_t smb = (uint32_t)__cvta_generic_to_shared(sm);

    int qt = gridDim.x - 1 - blockIdx.x;
    int bh = blockIdx.y, b = bh >> 3, h = bh & 7;
    int tid = threadIdx.x, wid = tid >> 5, lane = tid & 31;
    int g = lane >> 2, qd = lane & 3;
    int rbase = wid * 16;
    const int nkt = 2 * qt + 2;

    const float* qb = q + ((size_t)bh * L_ + qt * 128) * DH_;
    for (int i = tid; i < 2048; i += 256) {
        int r = i >> 4, c4 = (i & 15) << 2;
        *(float4*)(Qs + r * QS + c4) = *(const float4*)(qb + r * DH_ + c4);
    }
    if (tid < 128) tq[tid] = ts[b * L_ + qt * 128 + tid];

    float dcy = log1pf(__expf(decay_rate[h])) * (1.0f / 24.0f);
    float mprev[2] = {-1e30f, -1e30f};
    float lsum[2] = {0.f, 0.f};
    float o[8][4];
    #pragma unroll
    for (int i = 0; i < 8; i++)
        #pragma unroll
        for (int e = 0; e < 4; e++) o[i][e] = 0.f;

    auto load_kv = [&](int jt, int st) {
        const float* kb = k + ((size_t)bh * L_ + jt * 64) * DH_;
        const float* vb = v + ((size_t)bh * L_ + jt * 64) * DH_;
        uint32_t kdst = smb + (uint32_t)((AF_QS + st * 64 * QS) << 2);
        uint32_t vdst = smb + (uint32_t)((AF_QS + AF_KC + st * 64 * VSS) << 2);
        #pragma unroll
        for (int i = 0; i < 4; i++) {
            int idx = tid + i * 256;
            int r = idx >> 4, c4 = (idx & 15) << 2;
            asm volatile("cp.async.cg.shared.global [%0], [%1], 16;"
                         :: "r"(kdst + (uint32_t)((r * QS + c4) << 2)),
                            "l"(kb + (size_t)r * DH_ + c4) : "memory");
            asm volatile("cp.async.cg.shared.global [%0], [%1], 16;"
                         :: "r"(vdst + (uint32_t)((r * VSS + c4) << 2)),
                            "l"(vb + (size_t)r * DH_ + c4) : "memory");
        }
        if (tid < 64) {
            uint32_t tdst = smb + (uint32_t)((AF_QS + AF_KC + AF_VD + 128 + st * 64 + tid) << 2);
            asm volatile("cp.async.ca.shared.global [%0], [%1], 4;"
                         :: "r"(tdst), "l"(ts + b * L_ + jt * 64 + tid) : "memory");
            asm volatile("cp.async.ca.shared.global [%0], [%1], 4;"
                         :: "r"(tdst + 128 * 4), "l"(mask + b * L_ + jt * 64 + tid) : "memory");
        }
        asm volatile("cp.async.commit_group;" ::: "memory");
    };

    load_kv(0, 0);

    for (int jt = 0; jt < nkt; jt++) {
        int st = jt & 1;
        if (jt + 1 < nkt) {
            load_kv(jt + 1, (jt + 1) & 1);
            asm volatile("cp.async.wait_group 1;" ::: "memory");
        } else {
            asm volatile("cp.async.wait_group 0;" ::: "memory");
        }
        __syncthreads();

        const float* Kst = Kc + st * 64 * QS;
        const float* Vst = Vsm + st * 64 * VSS;
        const float* tks = tk + st * 64;
        const float* kms = km + st * 64;
        bool diag = (jt >= 2 * qt);

        // ---- S = Q K^T ----
        float s[8][4];
        #pragma unroll
        for (int i = 0; i < 8; i++)
            #pragma unroll
            for (int e = 0; e < 4; e++) s[i][e] = 0.f;
        #pragma unroll
        for (int ks = 0; ks < 8; ks++) {
            int k0 = ks * 8;
            uint32_t a[4];
            a[0] = f2u(Qs[(rbase + g    ) * QS + k0 + qd    ]);
            a[1] = f2u(Qs[(rbase + 8 + g) * QS + k0 + qd    ]);
            a[2] = f2u(Qs[(rbase + g    ) * QS + k0 + qd + 4]);
            a[3] = f2u(Qs[(rbase + 8 + g) * QS + k0 + qd + 4]);
            #pragma unroll
            for (int nt = 0; nt < 8; nt++) {
                uint32_t bb[2];
                bb[0] = f2u(Kst[(nt * 8 + g) * QS + k0 + qd    ]);
                bb[1] = f2u(Kst[(nt * 8 + g) * QS + k0 + qd + 4]);
                MMA_TF32(s[nt], a, bb);
            }
        }

        // ---- bias + masks ----
        int qi0 = qt * 128 + rbase + g;
        float tq0 = tq[rbase + g], tq1 = tq[rbase + 8 + g];
        #pragma unroll
        for (int nt = 0; nt < 8; nt++) {
            #pragma unroll
            for (int ci = 0; ci < 4; ci++) {
                int col = nt * 8 + 2 * qd + (ci & 1);
                int hi = ci >> 1;
                float val = s[nt][ci] * 0.125f
                          - dcy * fabsf((hi ? tq1 : tq0) - tks[col]);
                bool dead = (kms[col] == 0.f);
                if (diag) dead |= (jt * 64 + col > qi0 + hi * 8);
                if (dead) val = -1e30f;
                s[nt][ci] = val;
            }
        }

        // ---- online softmax ----
        float rmax[2] = {-1e30f, -1e30f};
        #pragma unroll
        for (int nt = 0; nt < 8; nt++) {
            rmax[0] = fmaxf(rmax[0], fmaxf(s[nt][0], s[nt][1]));
            rmax[1] = fmaxf(rmax[1], fmaxf(s[nt][2], s[nt][3]));
        }
        #pragma unroll
        for (int off = 1; off < 4; off <<= 1) {
            rmax[0] = fmaxf(rmax[0], __shfl_xor_sync(0xffffffffu, rmax[0], off));
            rmax[1] = fmaxf(rmax[1], __shfl_xor_sync(0xffffffffu, rmax[1], off));
        }
        float mnew[2], fac[2], ps[2] = {0.f, 0.f};
        #pragma unroll
        for (int hi = 0; hi < 2; hi++) {
            mnew[hi] = fmaxf(mprev[hi], rmax[hi]);
            fac[hi]  = __expf(mprev[hi] - mnew[hi]);
        }
        #pragma unroll
        for (int nt = 0; nt < 8; nt++) {
            #pragma unroll
            for (int ci = 0; ci < 4; ci++) {
                float sv = s[nt][ci];
                float p = (sv <= -1e29f) ? 0.f : __expf(sv - mnew[ci >> 1]);
                ps[ci >> 1] += p;
                s[nt][ci] = rnd_tf32(p);
            }
        }
        #pragma unroll
        for (int off = 1; off < 4; off <<= 1) {
            ps[0] += __shfl_xor_sync(0xffffffffu, ps[0], off);
            ps[1] += __shfl_xor_sync(0xffffffffu, ps[1], off);
        }
        #pragma unroll
        for (int hi = 0; hi < 2; hi++) {
            lsum[hi] = lsum[hi] * fac[hi] + ps[hi];
            mprev[hi] = mnew[hi];
        }
        #pragma unroll
        for (int nt = 0; nt < 8; nt++) {
            o[nt][0] *= fac[0]; o[nt][1] *= fac[0];
            o[nt][2] *= fac[1]; o[nt][3] *= fac[1];
        }

        // ---- O += P V  (P fragments via in-warp shuffle transform) ----
        int srcA = (g << 2) + (qd >> 1);
        bool odd = qd & 1;
        #pragma unroll
        for (int ks = 0; ks < 8; ks++) {
            int k0 = ks * 8;
            float v0 = __shfl_sync(0xffffffffu, s[ks][0], srcA);
            float v1 = __shfl_sync(0xffffffffu, s[ks][1], srcA);
            float v2 = __shfl_sync(0xffffffffu, s[ks][2], srcA);
            float v3 = __shfl_sync(0xffffffffu, s[ks][3], srcA);
            float w0 = __shfl_sync(0xffffffffu, s[ks][0], srcA + 2);
            float w1 = __shfl_sync(0xffffffffu, s[ks][1], srcA + 2);
            float w2 = __shfl_sync(0xffffffffu, s[ks][2], srcA + 2);
            float w3 = __shfl_sync(0xffffffffu, s[ks][3], srcA + 2);
            uint32_t a[4];
            a[0] = f2u(odd ? v1 : v0);
            a[1] = f2u(odd ? v3 : v2);
            a[2] = f2u(odd ? w1 : w0);
            a[3] = f2u(odd ? w3 : w2);
            #pragma unroll
            for (int nt = 0; nt < 8; nt++) {
                uint32_t bb[2];
                bb[0] = f2u(Vst[(k0 + qd    ) * VSS + nt * 8 + g]);
                bb[1] = f2u(Vst[(k0 + qd + 4) * VSS + nt * 8 + g]);
                MMA_TF32(o[nt], a, bb);
            }
        }
        __syncthreads();
    }

    // ---- output ----
    float inv0 = 1.0f / lsum[0], inv1 = 1.0f / lsum[1];
    int r0 = qt * 128 + rbase + g;
    #pragma unroll
    for (int nt = 0; nt < 8; nt++) {
        int col = h * 64 + nt * 8 + 2 * qd;
        float2 o0 = {rnd_tf32(o[nt][0] * inv0), rnd_tf32(o[nt][1] * inv0)};
        float2 o1 = {rnd_tf32(o[nt][2] * inv1), rnd_tf32(o[nt][3] * inv1)};
        *(float2*)(out + (size_t)(b * L_ + r0    ) * D_ + col) = o0;
        *(float2*)(out + (size_t)(b * L_ + r0 + 8) * D_ + col) = o1;
    }
}

// ============ launch ============
extern "C" void kernel_launch(void* const* d_in, const int* in_sizes, int n_in,
                              void* d_out, int out_size) {
    const float* x     = (const float*)d_in[0];
    const float* tsb   = (const float*)d_in[1];
    const float* mask  = (const float*)d_in[2];
    const float* ln1_g = (const float*)d_in[3];
    const float* ln1_b = (const float*)d_in[4];
    const float* w_qkv = (const float*)d_in[5];
    const float* w_out = (const float*)d_in[6];
    const float* decay = (const float*)d_in[7];
    const float* ln2_g = (const float*)d_in[8];
    const float* ln2_b = (const float*)d_in[9];
    const float* w_ff1 = (const float*)d_in[10];
    const float* w_ff2 = (const float*)d_in[11];
    float* out = (float*)d_out;

    float *xn, *q, *k, *v, *att, *x1, *hh, *ff, *w0, *w1, *w2, *w3;
    cudaGetSymbolAddress((void**)&xn, g_xn);
    cudaGetSymbolAddress((void**)&q, g_q);
    cudaGetSymbolAddress((void**)&k, g_k);
    cudaGetSymbolAddress((void**)&v, g_v);
    cudaGetSymbolAddress((void**)&att, g_att);
    cudaGetSymbolAddress((void**)&x1, g_x1);
    cudaGetSymbolAddress((void**)&hh, g_h);
    cudaGetSymbolAddress((void**)&ff, g_ff);
    cudaGetSymbolAddress((void**)&w0, g_w0);
    cudaGetSymbolAddress((void**)&w1, g_w1);
    cudaGetSymbolAddress((void**)&w2, g_w2);
    cudaGetSymbolAddress((void**)&w3, g_w3);

    cudaFuncSetAttribute(mma_gemm, cudaFuncAttributeMaxDynamicSharedMemorySize, GEMM_SMEM_B);
    cudaFuncSetAttribute(attn_kernel, cudaFuncAttributeMaxDynamicSharedMemorySize, ATTN_SMEM_B);

    const int n_total = 3 * D_ * D_ + D_ * D_ + FF_ * D_ + D_ * FF_;
    round_all_kernel<<<n_total / 1024, 256>>>(w_qkv, w0, w_out, w1, w_ff1, w2, w_ff2, w3);

    ln_kernel<<<BL_, 256>>>(x, ln1_g, ln1_b, xn);
    mma_gemm<<<dim3(1536 / 128, BL_ / 128), 256, GEMM_SMEM_B>>>(
        xn, w0, D_, 1536, MODE_QKV, nullptr, nullptr, q, k, v);
    attn_kernel<<<dim3(L_ / 128, B_ * H_), 256, ATTN_SMEM_B>>>(
        q, k, v, tsb, mask, decay, att);
    mma_gemm<<<dim3(D_ / 128, BL_ / 128), 256, GEMM_SMEM_B>>>(
        att, w1, D_, D_, MODE_RESID, x, x1, nullptr, nullptr, nullptr);
    ln_kernel<<<BL_, 256>>>(x1, ln2_g, ln2_b, hh);
    mma_gemm<<<dim3(FF_ / 128, BL_ / 128), 256, GEMM_SMEM_B>>>(
        hh, w2, D_, FF_, MODE_SILU, nullptr, ff, nullptr, nullptr, nullptr);
    mma_gemm<<<dim3(D_ / 128, BL_ / 128), 256, GEMM_SMEM_B>>>(
        ff, w3, FF_, D_, MODE_RESID, x1, out, nullptr, nullptr, nullptr);
}

// round 7
// speedup vs baseline: 4.8947x; 1.3601x over previous
#include <cuda_runtime.h>
#include <cuda_bf16.h>
#include <math.h>
#include <stdint.h>

#define B_  2
#define L_  4096
#define D_  512
#define H_  8
#define DH_ 64
#define BL_ 8192
#define FF_ 2048

// ---------------- scratch ----------------
__device__ float g_xn [BL_ * D_];
__device__ __nv_bfloat16 g_q [B_ * H_ * L_ * DH_];
__device__ __nv_bfloat16 g_k [B_ * H_ * L_ * DH_];
__device__ __nv_bfloat16 g_v [B_ * H_ * L_ * DH_];
__device__ float g_att[BL_ * D_];
__device__ float g_x1 [BL_ * D_];
__device__ float g_h  [BL_ * D_];
__device__ float g_ff [BL_ * FF_];
__device__ float g_w0 [3 * D_ * D_];
__device__ float g_w1 [D_ * D_];
__device__ float g_w2 [FF_ * D_];
__device__ float g_w3 [D_ * FF_];

__device__ __forceinline__ float rnd_tf32(float v) {
    uint32_t u;
    asm("cvt.rna.tf32.f32 %0, %1;" : "=r"(u) : "f"(v));
    return __uint_as_float(u);
}
__device__ __forceinline__ uint32_t f2u(float v) { return __float_as_uint(v); }
__device__ __forceinline__ float exp2fast(float x) {
    float r;
    asm("ex2.approx.f32 %0, %1;" : "=f"(r) : "f"(x));
    return r;
}
__device__ __forceinline__ uint32_t packbf(float lo, float hi) {
    uint32_t r;
    asm("cvt.rn.bf16x2.f32 %0, %1, %2;" : "=r"(r) : "f"(hi), "f"(lo));
    return r;
}

#define MMA_TF32(d, a, b)                                                    \
    asm volatile(                                                            \
        "mma.sync.aligned.m16n8k8.row.col.f32.tf32.tf32.f32 "                \
        "{%0,%1,%2,%3}, {%4,%5,%6,%7}, {%8,%9}, {%0,%1,%2,%3};"              \
        : "+f"(d[0]), "+f"(d[1]), "+f"(d[2]), "+f"(d[3])                     \
        : "r"(a[0]), "r"(a[1]), "r"(a[2]), "r"(a[3]), "r"(b[0]), "r"(b[1]))

#define MMA_BF16(d, a, b0, b1)                                               \
    asm volatile(                                                            \
        "mma.sync.aligned.m16n8k16.row.col.f32.bf16.bf16.f32 "               \
        "{%0,%1,%2,%3}, {%4,%5,%6,%7}, {%8,%9}, {%0,%1,%2,%3};"              \
        : "+f"(d[0]), "+f"(d[1]), "+f"(d[2]), "+f"(d[3])                     \
        : "r"(a[0]), "r"(a[1]), "r"(a[2]), "r"(a[3]), "r"(b0), "r"(b1))

#define LDSM_X4(r0, r1, r2, r3, addr)                                        \
    asm volatile("ldmatrix.sync.aligned.m8n8.x4.shared.b16 {%0,%1,%2,%3}, [%4];" \
        : "=r"(r0), "=r"(r1), "=r"(r2), "=r"(r3) : "r"(addr))

#define LDSM_X4T(r0, r1, r2, r3, addr)                                       \
    asm volatile("ldmatrix.sync.aligned.m8n8.x4.trans.shared.b16 {%0,%1,%2,%3}, [%4];" \
        : "=r"(r0), "=r"(r1), "=r"(r2), "=r"(r3) : "r"(addr))

// ============ fused weight rounding ============
__global__ __launch_bounds__(256) void round_all_kernel(
    const float* __restrict__ s0, float* __restrict__ d0,
    const float* __restrict__ s1, float* __restrict__ d1,
    const float* __restrict__ s2, float* __restrict__ d2,
    const float* __restrict__ s3, float* __restrict__ d3)
{
    const int n0 = 3 * D_ * D_, n1 = D_ * D_, n2 = FF_ * D_;
    int i = (blockIdx.x * 256 + threadIdx.x) * 4;
    const float* src; float* dst; int off;
    if (i < n0)                { src = s0; dst = d0; off = i; }
    else if (i < n0 + n1)      { src = s1; dst = d1; off = i - n0; }
    else if (i < n0 + n1 + n2) { src = s2; dst = d2; off = i - n0 - n1; }
    else                       { src = s3; dst = d3; off = i - n0 - n1 - n2; }
    float4 v = *(const float4*)(src + off);
    v.x = rnd_tf32(v.x); v.y = rnd_tf32(v.y);
    v.z = rnd_tf32(v.z); v.w = rnd_tf32(v.w);
    *(float4*)(dst + off) = v;
}

// ============ LayerNorm ============
__global__ __launch_bounds__(256) void ln_kernel(const float* __restrict__ x,
                                                 const float* __restrict__ g,
                                                 const float* __restrict__ b,
                                                 float* __restrict__ y) {
    int row = blockIdx.x;
    const float* xr = x + (size_t)row * D_;
    float* yr = y + (size_t)row * D_;
    int tid = threadIdx.x;
    float v0 = xr[tid], v1 = xr[tid + 256];
    float s = v0 + v1, ss = v0 * v0 + v1 * v1;
    #pragma unroll
    for (int o = 16; o > 0; o >>= 1) {
        s  += __shfl_xor_sync(0xffffffffu, s,  o);
        ss += __shfl_xor_sync(0xffffffffu, ss, o);
    }
    __shared__ float red[16];
    int w = tid >> 5, lane = tid & 31;
    if (lane == 0) { red[w] = s; red[w + 8] = ss; }
    __syncthreads();
    float S = 0.f, SS = 0.f;
    #pragma unroll
    for (int i = 0; i < 8; i++) { S += red[i]; SS += red[i + 8]; }
    float mu = S * (1.0f / D_);
    float inv = rsqrtf(SS * (1.0f / D_) - mu * mu + 1e-5f);
    yr[tid]       = rnd_tf32((v0 - mu) * inv * g[tid]       + b[tid]);
    yr[tid + 256] = rnd_tf32((v1 - mu) * inv * g[tid + 256] + b[tid + 256]);
}

// ============ mma.sync tf32 GEMM, 3-stage, 2 CTA/SM ============
#define SROW 36
#define STAGE_F (128 * SROW * 2)
#define GEMM_SMEM_B (3 * STAGE_F * 4)
#define MODE_QKV   0
#define MODE_RESID 1
#define MODE_SILU  2

__global__ __launch_bounds__(256, 2) void mma_gemm(
    const float* __restrict__ A, const float* __restrict__ W,
    int K, int N, int mode, const float* __restrict__ resid,
    float* __restrict__ out, __nv_bfloat16* __restrict__ oq,
    __nv_bfloat16* __restrict__ okk, __nv_bfloat16* __restrict__ ov)
{
    extern __shared__ float sm[];
    uint32_t sbase = (uint32_t)__cvta_generic_to_shared(sm);
    int tid = threadIdx.x;
    int wid = tid >> 5, lane = tid & 31;
    int wm = wid & 1, wn = wid >> 1;
    int g = lane >> 2, qd = lane & 3;
    int bm = blockIdx.y, bn = blockIdx.x;
    const float* Ab = A + (size_t)bm * 128 * K;
    const float* Wb = W + (size_t)bn * 128 * K;
    const int NC = K >> 5;

    float acc[4][4][4];
    #pragma unroll
    for (int i = 0; i < 4; i++)
        #pragma unroll
        for (int j = 0; j < 4; j++)
            #pragma unroll
            for (int e = 0; e < 4; e++) acc[i][j][e] = 0.f;

    auto load_stage = [&](int c, int st) {
        int k0 = c << 5;
        #pragma unroll
        for (int i = 0; i < 4; i++) {
            int idx = tid + i * 256;
            int row = idx >> 3, c4 = (idx & 7) << 2;
            uint32_t da = sbase + (uint32_t)((st * STAGE_F + row * SROW + c4) << 2);
            asm volatile("cp.async.cg.shared.global [%0], [%1], 16;"
                         :: "r"(da), "l"(Ab + (size_t)row * K + k0 + c4) : "memory");
            asm volatile("cp.async.cg.shared.global [%0], [%1], 16;"
                         :: "r"(da + 128 * SROW * 4), "l"(Wb + (size_t)row * K + k0 + c4) : "memory");
        }
        asm volatile("cp.async.commit_group;" ::: "memory");
    };

    load_stage(0, 0); load_stage(1, 1); load_stage(2, 2);
    int st = 0;

    for (int c = 0; c < NC; c++) {
        asm volatile("cp.async.wait_group 2;" ::: "memory");
        __syncthreads();

        const float* As = sm + st * STAGE_F + (wm * 64) * SROW;
        const float* Bs = sm + st * STAGE_F + 128 * SROW + (wn * 32) * SROW;
        #pragma unroll
        for (int ks = 0; ks < 4; ks++) {
            int k0 = ks * 8;
            uint32_t a[4][4], b[4][2];
            #pragma unroll
            for (int mt = 0; mt < 4; mt++) {
                const float* ap = As + mt * 16 * SROW;
                a[mt][0] = f2u(ap[(g    ) * SROW + k0 + qd    ]);
                a[mt][1] = f2u(ap[(g + 8) * SROW + k0 + qd    ]);
                a[mt][2] = f2u(ap[(g    ) * SROW + k0 + qd + 4]);
                a[mt][3] = f2u(ap[(g + 8) * SROW + k0 + qd + 4]);
            }
            #pragma unroll
            for (int nt = 0; nt < 4; nt++) {
                const float* bp = Bs + nt * 8 * SROW;
                b[nt][0] = f2u(bp[g * SROW + k0 + qd    ]);
                b[nt][1] = f2u(bp[g * SROW + k0 + qd + 4]);
            }
            #pragma unroll
            for (int mt = 0; mt < 4; mt++)
                #pragma unroll
                for (int nt = 0; nt < 4; nt++)
                    MMA_TF32(acc[mt][nt], a[mt], b[nt]);
        }
        __syncthreads();
        if (c + 3 < NC) load_stage(c + 3, st);
        st = (st == 2) ? 0 : st + 1;
    }

    #pragma unroll
    for (int mt = 0; mt < 4; mt++) {
        #pragma unroll
        for (int nt = 0; nt < 4; nt++) {
            int cb = bn * 128 + wn * 32 + nt * 8 + 2 * qd;
            #pragma unroll
            for (int hi = 0; hi < 2; hi++) {
                int r = bm * 128 + wm * 64 + mt * 16 + g + hi * 8;
                float v0 = acc[mt][nt][hi * 2], v1 = acc[mt][nt][hi * 2 + 1];
                if (mode == MODE_QKV) {
                    int which = cb >> 9, h = (cb >> 6) & 7, d0 = cb & 63;
                    int bb = r >> 12, l = r & 4095;
                    __nv_bfloat16* dst = (which == 0) ? oq : (which == 1) ? okk : ov;
                    __nv_bfloat162 o2 = __floats2bfloat162_rn(v0, v1);
                    *(__nv_bfloat162*)(dst + (((size_t)bb * H_ + h) * L_ + l) * DH_ + d0) = o2;
                } else if (mode == MODE_RESID) {
                    size_t idx = (size_t)r * N + cb;
                    float2 rv = *(const float2*)(resid + idx);
                    float2 o2 = {rv.x + v0, rv.y + v1};
                    *(float2*)(out + idx) = o2;
                } else {
                    size_t idx = (size_t)r * N + cb;
                    float2 o2 = {rnd_tf32(v0 / (1.0f + __expf(-v0))),
                                 rnd_tf32(v1 / (1.0f + __expf(-v1)))};
                    *(float2*)(out + idx) = o2;
                }
            }
        }
    }
}

// ============ flash attention, bf16 mma m16n8k16 + ldmatrix ============
#define KSB 72                       // bf16 elements per smem row (144B, 16B-aligned, conflict-free)
#define ROWB (KSB * 2)               // 144 bytes
#define OQ_B   0
#define OK_B   (128 * ROWB)                   // 18432
#define OV_B   (OK_B + 2 * 64 * ROWB)         // +18432
#define OTQ_B  (OV_B + 2 * 64 * ROWB)         // +18432
#define OTK_B  (OTQ_B + 128 * 4)
#define OKM_B  (OTK_B + 2 * 64 * 4)
#define ATTN_SMEM_B (OKM_B + 2 * 64 * 4)      // 56832

__global__ __launch_bounds__(256, 2) void attn_kernel(
    const __nv_bfloat16* __restrict__ q, const __nv_bfloat16* __restrict__ k,
    const __nv_bfloat16* __restrict__ v, const float* __restrict__ ts,
    const float* __restrict__ mask, const float* __restrict__ decay_rate,
    float* __restrict__ out)
{
    extern __shared__ char smc[];
    uint32_t smb = (uint32_t)__cvta_generic_to_shared(smc);
    float* tq = (float*)(smc + OTQ_B);
    float* tk = (float*)(smc + OTK_B);
    float* km = (float*)(smc + OKM_B);

    int qt = gridDim.x - 1 - blockIdx.x;
    int bh = blockIdx.y, b = bh >> 3, h = bh & 7;
    int tid = threadIdx.x, wid = tid >> 5, lane = tid & 31;
    int g = lane >> 2, qd = lane & 3;
    int rbase = wid * 16;
    const int nkt = 2 * qt + 2;

    // ---- ldmatrix per-lane addresses ----
    uint32_t qaddr = smb + OQ_B + (uint32_t)(rbase + (lane & 7) + ((lane >> 3) & 1) * 8) * ROWB
                   + (uint32_t)(lane >> 4) * 16;
    uint32_t kaddr = smb + OK_B + (uint32_t)((lane & 7) + ((lane >> 4) & 1) * 8) * ROWB
                   + (uint32_t)((lane >> 3) & 1) * 16;
    uint32_t vaddr = smb + OV_B + (uint32_t)((lane & 7) + ((lane >> 3) & 1) * 8) * ROWB
                   + (uint32_t)(lane >> 4) * 16;

    // ---- Q tile (once): 128 rows x 64 bf16 ----
    const __nv_bfloat16* qb = q + ((size_t)bh * L_ + qt * 128) * DH_;
    for (int i = tid; i < 1024; i += 256) {
        int r = i >> 3, c8 = (i & 7) << 3;
        *(uint4*)(smc + OQ_B + r * ROWB + c8 * 2) = *(const uint4*)(qb + (size_t)r * DH_ + c8);
    }
    if (tid < 128) tq[tid] = ts[b * L_ + qt * 128 + tid];

    const float LOG2E = 1.44269504f;
    float scale2 = 0.125f * LOG2E;
    float dcy2 = log1pf(__expf(decay_rate[h])) * (LOG2E / 24.0f);
    float mprev[2] = {-1e30f, -1e30f};
    float lsum[2] = {0.f, 0.f};
    float o[8][4];
    #pragma unroll
    for (int i = 0; i < 8; i++)
        #pragma unroll
        for (int e = 0; e < 4; e++) o[i][e] = 0.f;

    auto load_kv = [&](int jt, int st) {
        const __nv_bfloat16* kb = k + ((size_t)bh * L_ + jt * 64) * DH_;
        const __nv_bfloat16* vb = v + ((size_t)bh * L_ + jt * 64) * DH_;
        uint32_t kdst = smb + OK_B + (uint32_t)st * 64 * ROWB;
        uint32_t vdst = smb + OV_B + (uint32_t)st * 64 * ROWB;
        #pragma unroll
        for (int i = 0; i < 2; i++) {
            int idx = tid + i * 256;
            int r = idx >> 3, c8 = (idx & 7) << 3;
            asm volatile("cp.async.cg.shared.global [%0], [%1], 16;"
                         :: "r"(kdst + (uint32_t)(r * ROWB + c8 * 2)),
                            "l"(kb + (size_t)r * DH_ + c8) : "memory");
            asm volatile("cp.async.cg.shared.global [%0], [%1], 16;"
                         :: "r"(vdst + (uint32_t)(r * ROWB + c8 * 2)),
                            "l"(vb + (size_t)r * DH_ + c8) : "memory");
        }
        if (tid < 64) {
            uint32_t tdst = smb + OTK_B + (uint32_t)((st * 64 + tid) * 4);
            asm volatile("cp.async.ca.shared.global [%0], [%1], 4;"
                         :: "r"(tdst), "l"(ts + b * L_ + jt * 64 + tid) : "memory");
            asm volatile("cp.async.ca.shared.global [%0], [%1], 4;"
                         :: "r"(tdst + (OKM_B - OTK_B)), "l"(mask + b * L_ + jt * 64 + tid) : "memory");
        }
        asm volatile("cp.async.commit_group;" ::: "memory");
    };

    load_kv(0, 0);

    for (int jt = 0; jt < nkt; jt++) {
        int st = jt & 1;
        if (jt + 1 < nkt) {
            load_kv(jt + 1, (jt + 1) & 1);
            asm volatile("cp.async.wait_group 1;" ::: "memory");
        } else {
            asm volatile("cp.async.wait_group 0;" ::: "memory");
        }
        __syncthreads();

        uint32_t kst = kaddr + (uint32_t)st * 64 * ROWB;
        uint32_t vst = vaddr + (uint32_t)st * 64 * ROWB;
        const float* tks = tk + st * 64;
        const float* kms = km + st * 64;
        bool diag = (jt >= 2 * qt);

        // ---- S = Q K^T  (m16n8k16, ldmatrix) ----
        float s[8][4];
        #pragma unroll
        for (int i = 0; i < 8; i++)
            #pragma unroll
            for (int e = 0; e < 4; e++) s[i][e] = 0.f;
        #pragma unroll
        for (int ks = 0; ks < 4; ks++) {           // d-chunks of 16
            uint32_t qa0, qa1, qa2, qa3;
            LDSM_X4(qa0, qa1, qa2, qa3, qaddr + ks * 32);
            uint32_t a[4] = {qa0, qa1, qa2, qa3};
            #pragma unroll
            for (int p = 0; p < 4; p++) {          // kcol blocks of 16
                uint32_t b0, b1, b2, b3;
                LDSM_X4(b0, b1, b2, b3, kst + (uint32_t)(p * 16 * ROWB) + ks * 32);
                MMA_BF16(s[2 * p],     a, b0, b1);
                MMA_BF16(s[2 * p + 1], a, b2, b3);
            }
        }

        // ---- bias + masks (log2 domain) ----
        int qi0 = qt * 128 + rbase + g;
        float tq0 = tq[rbase + g], tq1 = tq[rbase + 8 + g];
        #pragma unroll
        for (int nt = 0; nt < 8; nt++) {
            #pragma unroll
            for (int ci = 0; ci < 4; ci++) {
                int col = nt * 8 + 2 * qd + (ci & 1);
                int hi = ci >> 1;
                float val = s[nt][ci] * scale2
                          - dcy2 * fabsf((hi ? tq1 : tq0) - tks[col]);
                bool dead = (kms[col] == 0.f);
                if (diag) dead |= (jt * 64 + col > qi0 + hi * 8);
                if (dead) val = -1e30f;
                s[nt][ci] = val;
            }
        }

        // ---- online softmax (exp2) ----
        float rmax[2] = {-1e30f, -1e30f};
        #pragma unroll
        for (int nt = 0; nt < 8; nt++) {
            rmax[0] = fmaxf(rmax[0], fmaxf(s[nt][0], s[nt][1]));
            rmax[1] = fmaxf(rmax[1], fmaxf(s[nt][2], s[nt][3]));
        }
        #pragma unroll
        for (int off = 1; off < 4; off <<= 1) {
            rmax[0] = fmaxf(rmax[0], __shfl_xor_sync(0xffffffffu, rmax[0], off));
            rmax[1] = fmaxf(rmax[1], __shfl_xor_sync(0xffffffffu, rmax[1], off));
        }
        float mnew[2], fac[2], ps[2] = {0.f, 0.f};
        #pragma unroll
        for (int hi = 0; hi < 2; hi++) {
            mnew[hi] = fmaxf(mprev[hi], rmax[hi]);
            fac[hi]  = exp2fast(mprev[hi] - mnew[hi]);
        }
        #pragma unroll
        for (int nt = 0; nt < 8; nt++) {
            #pragma unroll
            for (int ci = 0; ci < 4; ci++) {
                float p = exp2fast(s[nt][ci] - mnew[ci >> 1]);
                ps[ci >> 1] += p;
                s[nt][ci] = p;
            }
        }
        #pragma unroll
        for (int off = 1; off < 4; off <<= 1) {
            ps[0] += __shfl_xor_sync(0xffffffffu, ps[0], off);
            ps[1] += __shfl_xor_sync(0xffffffffu, ps[1], off);
        }
        #pragma unroll
        for (int hi = 0; hi < 2; hi++) {
            lsum[hi] = lsum[hi] * fac[hi] + ps[hi];
            mprev[hi] = mnew[hi];
        }
        #pragma unroll
        for (int nt = 0; nt < 8; nt++) {
            o[nt][0] *= fac[0]; o[nt][1] *= fac[0];
            o[nt][2] *= fac[1]; o[nt][3] *= fac[1];
        }

        // ---- O += P V  (P packed from accumulators; V via ldmatrix.trans) ----
        #pragma unroll
        for (int kc = 0; kc < 4; kc++) {            // kpos chunks of 16
            uint32_t a[4];
            a[0] = packbf(s[2 * kc][0],     s[2 * kc][1]);
            a[1] = packbf(s[2 * kc][2],     s[2 * kc][3]);
            a[2] = packbf(s[2 * kc + 1][0], s[2 * kc + 1][1]);
            a[3] = packbf(s[2 * kc + 1][2], s[2 * kc + 1][3]);
            #pragma unroll
            for (int p = 0; p < 4; p++) {           // d blocks of 16
                uint32_t b0, b1, b2, b3;
                LDSM_X4T(b0, b1, b2, b3, vst + (uint32_t)(kc * 16 * ROWB) + p * 32);
                MMA_BF16(o[2 * p],     a, b0, b1);
                MMA_BF16(o[2 * p + 1], a, b2, b3);
            }
        }
        __syncthreads();
    }

    // ---- output ----
    float inv0 = 1.0f / lsum[0], inv1 = 1.0f / lsum[1];
    int r0 = qt * 128 + rbase + g;
    #pragma unroll
    for (int nt = 0; nt < 8; nt++) {
        int col = h * 64 + nt * 8 + 2 * qd;
        float2 o0 = {rnd_tf32(o[nt][0] * inv0), rnd_tf32(o[nt][1] * inv0)};
        float2 o1 = {rnd_tf32(o[nt][2] * inv1), rnd_tf32(o[nt][3] * inv1)};
        *(float2*)(out + (size_t)(b * L_ + r0    ) * D_ + col) = o0;
        *(float2*)(out + (size_t)(b * L_ + r0 + 8) * D_ + col) = o1;
    }
}

// ============ launch ============
extern "C" void kernel_launch(void* const* d_in, const int* in_sizes, int n_in,
                              void* d_out, int out_size) {
    const float* x     = (const float*)d_in[0];
    const float* tsb   = (const float*)d_in[1];
    const float* mask  = (const float*)d_in[2];
    const float* ln1_g = (const float*)d_in[3];
    const float* ln1_b = (const float*)d_in[4];
    const float* w_qkv = (const float*)d_in[5];
    const float* w_out = (const float*)d_in[6];
    const float* decay = (const float*)d_in[7];
    const float* ln2_g = (const float*)d_in[8];
    const float* ln2_b = (const float*)d_in[9];
    const float* w_ff1 = (const float*)d_in[10];
    const float* w_ff2 = (const float*)d_in[11];
    float* out = (float*)d_out;

    float *xn, *att, *x1, *hh, *ff, *w0, *w1, *w2, *w3;
    __nv_bfloat16 *q, *k, *v;
    cudaGetSymbolAddress((void**)&xn, g_xn);
    cudaGetSymbolAddress((void**)&q, g_q);
    cudaGetSymbolAddress((void**)&k, g_k);
    cudaGetSymbolAddress((void**)&v, g_v);
    cudaGetSymbolAddress((void**)&att, g_att);
    cudaGetSymbolAddress((void**)&x1, g_x1);
    cudaGetSymbolAddress((void**)&hh, g_h);
    cudaGetSymbolAddress((void**)&ff, g_ff);
    cudaGetSymbolAddress((void**)&w0, g_w0);
    cudaGetSymbolAddress((void**)&w1, g_w1);
    cudaGetSymbolAddress((void**)&w2, g_w2);
    cudaGetSymbolAddress((void**)&w3, g_w3);

    cudaFuncSetAttribute(mma_gemm, cudaFuncAttributeMaxDynamicSharedMemorySize, GEMM_SMEM_B);
    cudaFuncSetAttribute(attn_kernel, cudaFuncAttributeMaxDynamicSharedMemorySize, ATTN_SMEM_B);

    const int n_total = 3 * D_ * D_ + D_ * D_ + FF_ * D_ + D_ * FF_;
    round_all_kernel<<<n_total / 1024, 256>>>(w_qkv, w0, w_out, w1, w_ff1, w2, w_ff2, w3);

    ln_kernel<<<BL_, 256>>>(x, ln1_g, ln1_b, xn);
    mma_gemm<<<dim3(1536 / 128, BL_ / 128), 256, GEMM_SMEM_B>>>(
        xn, w0, D_, 1536, MODE_QKV, nullptr, nullptr, q, k, v);
    attn_kernel<<<dim3(L_ / 128, B_ * H_), 256, ATTN_SMEM_B>>>(
        q, k, v, tsb, mask, decay, att);
    mma_gemm<<<dim3(D_ / 128, BL_ / 128), 256, GEMM_SMEM_B>>>(
        att, w1, D_, D_, MODE_RESID, x, x1, nullptr, nullptr, nullptr);
    ln_kernel<<<BL_, 256>>>(x1, ln2_g, ln2_b, hh);
    mma_gemm<<<dim3(FF_ / 128, BL_ / 128), 256, GEMM_SMEM_B>>>(
        hh, w2, D_, FF_, MODE_SILU, nullptr, ff, nullptr, nullptr, nullptr);
    mma_gemm<<<dim3(D_ / 128, BL_ / 128), 256, GEMM_SMEM_B>>>(
        ff, w3, FF_, D_, MODE_RESID, x1, out, nullptr, nullptr, nullptr);
}

// round 8
// speedup vs baseline: 6.5517x; 1.3385x over previous
#include <cuda_runtime.h>
#include <cuda_bf16.h>
#include <math.h>
#include <stdint.h>

#define B_  2
#define L_  4096
#define D_  512
#define H_  8
#define DH_ 64
#define BL_ 8192
#define FF_ 2048

// ---------------- scratch ----------------
__device__ __nv_bfloat16 g_xn [BL_ * D_];
__device__ __nv_bfloat16 g_q [B_ * H_ * L_ * DH_];
__device__ __nv_bfloat16 g_k [B_ * H_ * L_ * DH_];
__device__ __nv_bfloat16 g_v [B_ * H_ * L_ * DH_];
__device__ __nv_bfloat16 g_att[BL_ * D_];
__device__ float g_x1 [BL_ * D_];
__device__ __nv_bfloat16 g_h  [BL_ * D_];
__device__ __nv_bfloat16 g_ff [BL_ * FF_];
__device__ __nv_bfloat16 g_w0 [3 * D_ * D_];
__device__ __nv_bfloat16 g_w1 [D_ * D_];
__device__ __nv_bfloat16 g_w2 [FF_ * D_];
__device__ __nv_bfloat16 g_w3 [D_ * FF_];

__device__ __forceinline__ uint32_t f2u(float v) { return __float_as_uint(v); }
__device__ __forceinline__ float exp2fast(float x) {
    float r;
    asm("ex2.approx.f32 %0, %1;" : "=f"(r) : "f"(x));
    return r;
}
__device__ __forceinline__ uint32_t packbf(float lo, float hi) {
    uint32_t r;
    asm("cvt.rn.bf16x2.f32 %0, %1, %2;" : "=r"(r) : "f"(hi), "f"(lo));
    return r;
}

#define MMA_BF16(d, a, b0, b1)                                               \
    asm volatile(                                                            \
        "mma.sync.aligned.m16n8k16.row.col.f32.bf16.bf16.f32 "               \
        "{%0,%1,%2,%3}, {%4,%5,%6,%7}, {%8,%9}, {%0,%1,%2,%3};"              \
        : "+f"(d[0]), "+f"(d[1]), "+f"(d[2]), "+f"(d[3])                     \
        : "r"(a[0]), "r"(a[1]), "r"(a[2]), "r"(a[3]), "r"(b0), "r"(b1))

#define LDSM_X4(r0, r1, r2, r3, addr)                                        \
    asm volatile("ldmatrix.sync.aligned.m8n8.x4.shared.b16 {%0,%1,%2,%3}, [%4];" \
        : "=r"(r0), "=r"(r1), "=r"(r2), "=r"(r3) : "r"(addr))

#define LDSM_X4T(r0, r1, r2, r3, addr)                                       \
    asm volatile("ldmatrix.sync.aligned.m8n8.x4.trans.shared.b16 {%0,%1,%2,%3}, [%4];" \
        : "=r"(r0), "=r"(r1), "=r"(r2), "=r"(r3) : "r"(addr))

// ============ weight conversion fp32 -> bf16 ============
__global__ __launch_bounds__(256) void round_all_kernel(
    const float* __restrict__ s0, __nv_bfloat16* __restrict__ d0,
    const float* __restrict__ s1, __nv_bfloat16* __restrict__ d1,
    const float* __restrict__ s2, __nv_bfloat16* __restrict__ d2,
    const float* __restrict__ s3, __nv_bfloat16* __restrict__ d3)
{
    const int n0 = 3 * D_ * D_, n1 = D_ * D_, n2 = FF_ * D_;
    int i = (blockIdx.x * 256 + threadIdx.x) * 4;
    const float* src; __nv_bfloat16* dst; int off;
    if (i < n0)                { src = s0; dst = d0; off = i; }
    else if (i < n0 + n1)      { src = s1; dst = d1; off = i - n0; }
    else if (i < n0 + n1 + n2) { src = s2; dst = d2; off = i - n0 - n1; }
    else                       { src = s3; dst = d3; off = i - n0 - n1 - n2; }
    float4 v = *(const float4*)(src + off);
    uint2 o;
    o.x = packbf(v.x, v.y);
    o.y = packbf(v.z, v.w);
    *(uint2*)(dst + off) = o;
}

// ============ LayerNorm (bf16 output) ============
__global__ __launch_bounds__(256) void ln_kernel(const float* __restrict__ x,
                                                 const float* __restrict__ g,
                                                 const float* __restrict__ b,
                                                 __nv_bfloat16* __restrict__ y) {
    int row = blockIdx.x;
    const float* xr = x + (size_t)row * D_;
    __nv_bfloat16* yr = y + (size_t)row * D_;
    int tid = threadIdx.x;
    float v0 = xr[tid], v1 = xr[tid + 256];
    float s = v0 + v1, ss = v0 * v0 + v1 * v1;
    #pragma unroll
    for (int o = 16; o > 0; o >>= 1) {
        s  += __shfl_xor_sync(0xffffffffu, s,  o);
        ss += __shfl_xor_sync(0xffffffffu, ss, o);
    }
    __shared__ float red[16];
    int w = tid >> 5, lane = tid & 31;
    if (lane == 0) { red[w] = s; red[w + 8] = ss; }
    __syncthreads();
    float S = 0.f, SS = 0.f;
    #pragma unroll
    for (int i = 0; i < 8; i++) { S += red[i]; SS += red[i + 8]; }
    float mu = S * (1.0f / D_);
    float inv = rsqrtf(SS * (1.0f / D_) - mu * mu + 1e-5f);
    yr[tid]       = __float2bfloat16((v0 - mu) * inv * g[tid]       + b[tid]);
    yr[tid + 256] = __float2bfloat16((v1 - mu) * inv * g[tid + 256] + b[tid + 256]);
}

// ============ bf16 mma GEMM: C = A[M,K] @ W[N,K]^T ============
// 128x128 block, 256 thr, warp grid 2(M)x4(N), warp tile 64x32, K-chunk 32,
// 3-stage cp.async, ldmatrix fragments, 2 CTA/SM.
#define ROWG 80                       // bytes per smem row (40 bf16)
#define STG_B (128 * ROWG)            // 10240 per matrix
#define STAGE_B (2 * STG_B)           // 20480
#define GEMM_SMEM_B (3 * STAGE_B)     // 61440
#define MODE_QKV   0
#define MODE_RESID 1
#define MODE_SILU  2

__global__ __launch_bounds__(256, 2) void mma_gemm(
    const __nv_bfloat16* __restrict__ A, const __nv_bfloat16* __restrict__ W,
    int K, int N, int mode, const float* __restrict__ resid,
    float* __restrict__ out, __nv_bfloat16* __restrict__ outb,
    __nv_bfloat16* __restrict__ oq, __nv_bfloat16* __restrict__ okk,
    __nv_bfloat16* __restrict__ ov)
{
    extern __shared__ char smg[];
    uint32_t sbase = (uint32_t)__cvta_generic_to_shared(smg);
    int tid = threadIdx.x;
    int wid = tid >> 5, lane = tid & 31;
    int wm = wid & 1, wn = wid >> 1;
    int g = lane >> 2, qd = lane & 3;
    int bm = blockIdx.y, bn = blockIdx.x;
    const __nv_bfloat16* Ab = A + (size_t)bm * 128 * K;
    const __nv_bfloat16* Wb = W + (size_t)bn * 128 * K;
    const int NC = K >> 5;

    // ldmatrix lane address components
    int arow = wm * 64 + (lane & 7) + ((lane >> 3) & 1) * 8;
    int acol = (lane >> 4) * 16;
    int wrow = wn * 32 + (lane & 7) + ((lane >> 4) & 1) * 8;
    int wcol = ((lane >> 3) & 1) * 16;

    float acc[4][4][4];
    #pragma unroll
    for (int i = 0; i < 4; i++)
        #pragma unroll
        for (int j = 0; j < 4; j++)
            #pragma unroll
            for (int e = 0; e < 4; e++) acc[i][j][e] = 0.f;

    auto load_stage = [&](int c, int st) {
        int k0 = c << 5;
        #pragma unroll
        for (int i = 0; i < 2; i++) {
            int idx = tid + i * 256;
            int r = idx >> 2, cb = idx & 3;
            uint32_t da = sbase + (uint32_t)(st * STAGE_B + r * ROWG + cb * 16);
            asm volatile("cp.async.cg.shared.global [%0], [%1], 16;"
                         :: "r"(da), "l"(Ab + (size_t)r * K + k0 + cb * 8) : "memory");
            asm volatile("cp.async.cg.shared.global [%0], [%1], 16;"
                         :: "r"(da + STG_B), "l"(Wb + (size_t)r * K + k0 + cb * 8) : "memory");
        }
        asm volatile("cp.async.commit_group;" ::: "memory");
    };

    load_stage(0, 0); load_stage(1, 1); load_stage(2, 2);
    int st = 0;

    for (int c = 0; c < NC; c++) {
        asm volatile("cp.async.wait_group 2;" ::: "memory");
        __syncthreads();

        uint32_t abase = sbase + (uint32_t)(st * STAGE_B);
        uint32_t wbase = abase + STG_B;
        #pragma unroll
        for (int kc = 0; kc < 2; kc++) {
            uint32_t a[4][4], bfr[2][4];
            #pragma unroll
            for (int mt = 0; mt < 4; mt++)
                LDSM_X4(a[mt][0], a[mt][1], a[mt][2], a[mt][3],
                        abase + (uint32_t)((arow + mt * 16) * ROWG + acol + kc * 32));
            #pragma unroll
            for (int t = 0; t < 2; t++)
                LDSM_X4(bfr[t][0], bfr[t][1], bfr[t][2], bfr[t][3],
                        wbase + (uint32_t)((wrow + t * 16) * ROWG + wcol + kc * 32));
            #pragma unroll
            for (int mt = 0; mt < 4; mt++)
                #pragma unroll
                for (int t = 0; t < 2; t++) {
                    MMA_BF16(acc[mt][2 * t],     a[mt], bfr[t][0], bfr[t][1]);
                    MMA_BF16(acc[mt][2 * t + 1], a[mt], bfr[t][2], bfr[t][3]);
                }
        }
        __syncthreads();
        if (c + 3 < NC) load_stage(c + 3, st);
        st = (st == 2) ? 0 : st + 1;
    }

    #pragma unroll
    for (int mt = 0; mt < 4; mt++) {
        #pragma unroll
        for (int nt = 0; nt < 4; nt++) {
            int cb = bn * 128 + wn * 32 + nt * 8 + 2 * qd;
            #pragma unroll
            for (int hi = 0; hi < 2; hi++) {
                int r = bm * 128 + wm * 64 + mt * 16 + g + hi * 8;
                float v0 = acc[mt][nt][hi * 2], v1 = acc[mt][nt][hi * 2 + 1];
                if (mode == MODE_QKV) {
                    int which = cb >> 9, h = (cb >> 6) & 7, d0 = cb & 63;
                    int bb = r >> 12, l = r & 4095;
                    __nv_bfloat16* dst = (which == 0) ? oq : (which == 1) ? okk : ov;
                    *(uint32_t*)(dst + (((size_t)bb * H_ + h) * L_ + l) * DH_ + d0) = packbf(v0, v1);
                } else if (mode == MODE_RESID) {
                    size_t idx = (size_t)r * N + cb;
                    float2 rv = *(const float2*)(resid + idx);
                    float2 o2 = {rv.x + v0, rv.y + v1};
                    *(float2*)(out + idx) = o2;
                } else {
                    size_t idx = (size_t)r * N + cb;
                    float a0 = v0 / (1.0f + __expf(-v0));
                    float a1 = v1 / (1.0f + __expf(-v1));
                    *(uint32_t*)(outb + idx) = packbf(a0, a1);
                }
            }
        }
    }
}

// ============ flash attention, bf16 mma m16n8k16 + ldmatrix ============
#define KSB 72
#define ROWB (KSB * 2)
#define OQ_B   0
#define OK_B   (128 * ROWB)
#define OV_B   (OK_B + 2 * 64 * ROWB)
#define OTQ_B  (OV_B + 2 * 64 * ROWB)
#define OTK_B  (OTQ_B + 128 * 4)
#define OKM_B  (OTK_B + 2 * 64 * 4)
#define ATTN_SMEM_B (OKM_B + 2 * 64 * 4)

__global__ __launch_bounds__(256, 2) void attn_kernel(
    const __nv_bfloat16* __restrict__ q, const __nv_bfloat16* __restrict__ k,
    const __nv_bfloat16* __restrict__ v, const float* __restrict__ ts,
    const float* __restrict__ mask, const float* __restrict__ decay_rate,
    __nv_bfloat16* __restrict__ out)
{
    extern __shared__ char smc[];
    uint32_t smb = (uint32_t)__cvta_generic_to_shared(smc);
    float* tq = (float*)(smc + OTQ_B);
    float* tk = (float*)(smc + OTK_B);
    float* km = (float*)(smc + OKM_B);

    int qt = gridDim.x - 1 - blockIdx.x;
    int bh = blockIdx.y, b = bh >> 3, h = bh & 7;
    int tid = threadIdx.x, wid = tid >> 5, lane = tid & 31;
    int g = lane >> 2, qd = lane & 3;
    int rbase = wid * 16;
    const int nkt = 2 * qt + 2;

    uint32_t qaddr = smb + OQ_B + (uint32_t)(rbase + (lane & 7) + ((lane >> 3) & 1) * 8) * ROWB
                   + (uint32_t)(lane >> 4) * 16;
    uint32_t kaddr = smb + OK_B + (uint32_t)((lane & 7) + ((lane >> 4) & 1) * 8) * ROWB
                   + (uint32_t)((lane >> 3) & 1) * 16;
    uint32_t vaddr = smb + OV_B + (uint32_t)((lane & 7) + ((lane >> 3) & 1) * 8) * ROWB
                   + (uint32_t)(lane >> 4) * 16;

    const __nv_bfloat16* qb = q + ((size_t)bh * L_ + qt * 128) * DH_;
    for (int i = tid; i < 1024; i += 256) {
        int r = i >> 3, c8 = (i & 7) << 3;
        *(uint4*)(smc + OQ_B + r * ROWB + c8 * 2) = *(const uint4*)(qb + (size_t)r * DH_ + c8);
    }
    if (tid < 128) tq[tid] = ts[b * L_ + qt * 128 + tid];

    const float LOG2E = 1.44269504f;
    float scale2 = 0.125f * LOG2E;
    float dcy2 = log1pf(__expf(decay_rate[h])) * (LOG2E / 24.0f);
    float mprev[2] = {-1e30f, -1e30f};
    float lsum[2] = {0.f, 0.f};
    float o[8][4];
    #pragma unroll
    for (int i = 0; i < 8; i++)
        #pragma unroll
        for (int e = 0; e < 4; e++) o[i][e] = 0.f;

    auto load_kv = [&](int jt, int st) {
        const __nv_bfloat16* kb = k + ((size_t)bh * L_ + jt * 64) * DH_;
        const __nv_bfloat16* vb = v + ((size_t)bh * L_ + jt * 64) * DH_;
        uint32_t kdst = smb + OK_B + (uint32_t)st * 64 * ROWB;
        uint32_t vdst = smb + OV_B + (uint32_t)st * 64 * ROWB;
        #pragma unroll
        for (int i = 0; i < 2; i++) {
            int idx = tid + i * 256;
            int r = idx >> 3, c8 = (idx & 7) << 3;
            asm volatile("cp.async.cg.shared.global [%0], [%1], 16;"
                         :: "r"(kdst + (uint32_t)(r * ROWB + c8 * 2)),
                            "l"(kb + (size_t)r * DH_ + c8) : "memory");
            asm volatile("cp.async.cg.shared.global [%0], [%1], 16;"
                         :: "r"(vdst + (uint32_t)(r * ROWB + c8 * 2)),
                            "l"(vb + (size_t)r * DH_ + c8) : "memory");
        }
        if (tid < 64) {
            uint32_t tdst = smb + OTK_B + (uint32_t)((st * 64 + tid) * 4);
            asm volatile("cp.async.ca.shared.global [%0], [%1], 4;"
                         :: "r"(tdst), "l"(ts + b * L_ + jt * 64 + tid) : "memory");
            asm volatile("cp.async.ca.shared.global [%0], [%1], 4;"
                         :: "r"(tdst + (OKM_B - OTK_B)), "l"(mask + b * L_ + jt * 64 + tid) : "memory");
        }
        asm volatile("cp.async.commit_group;" ::: "memory");
    };

    load_kv(0, 0);

    for (int jt = 0; jt < nkt; jt++) {
        int st = jt & 1;
        if (jt + 1 < nkt) {
            load_kv(jt + 1, (jt + 1) & 1);
            asm volatile("cp.async.wait_group 1;" ::: "memory");
        } else {
            asm volatile("cp.async.wait_group 0;" ::: "memory");
        }
        __syncthreads();

        uint32_t kst = kaddr + (uint32_t)st * 64 * ROWB;
        uint32_t vst = vaddr + (uint32_t)st * 64 * ROWB;
        const float* tks = tk + st * 64;
        const float* kms = km + st * 64;
        bool diag = (jt >= 2 * qt);

        float s[8][4];
        #pragma unroll
        for (int i = 0; i < 8; i++)
            #pragma unroll
            for (int e = 0; e < 4; e++) s[i][e] = 0.f;
        #pragma unroll
        for (int ks = 0; ks < 4; ks++) {
            uint32_t qa0, qa1, qa2, qa3;
            LDSM_X4(qa0, qa1, qa2, qa3, qaddr + ks * 32);
            uint32_t a[4] = {qa0, qa1, qa2, qa3};
            #pragma unroll
            for (int p = 0; p < 4; p++) {
                uint32_t b0, b1, b2, b3;
                LDSM_X4(b0, b1, b2, b3, kst + (uint32_t)(p * 16 * ROWB) + ks * 32);
                MMA_BF16(s[2 * p],     a, b0, b1);
                MMA_BF16(s[2 * p + 1], a, b2, b3);
            }
        }

        int qi0 = qt * 128 + rbase + g;
        float tq0 = tq[rbase + g], tq1 = tq[rbase + 8 + g];
        #pragma unroll
        for (int nt = 0; nt < 8; nt++) {
            #pragma unroll
            for (int ci = 0; ci < 4; ci++) {
                int col = nt * 8 + 2 * qd + (ci & 1);
                int hi = ci >> 1;
                float val = s[nt][ci] * scale2
                          - dcy2 * fabsf((hi ? tq1 : tq0) - tks[col]);
                bool dead = (kms[col] == 0.f);
                if (diag) dead |= (jt * 64 + col > qi0 + hi * 8);
                if (dead) val = -1e30f;
                s[nt][ci] = val;
            }
        }

        float rmax[2] = {-1e30f, -1e30f};
        #pragma unroll
        for (int nt = 0; nt < 8; nt++) {
            rmax[0] = fmaxf(rmax[0], fmaxf(s[nt][0], s[nt][1]));
            rmax[1] = fmaxf(rmax[1], fmaxf(s[nt][2], s[nt][3]));
        }
        #pragma unroll
        for (int off = 1; off < 4; off <<= 1) {
            rmax[0] = fmaxf(rmax[0], __shfl_xor_sync(0xffffffffu, rmax[0], off));
            rmax[1] = fmaxf(rmax[1], __shfl_xor_sync(0xffffffffu, rmax[1], off));
        }
        float mnew[2], fac[2], ps[2] = {0.f, 0.f};
        #pragma unroll
        for (int hi = 0; hi < 2; hi++) {
            mnew[hi] = fmaxf(mprev[hi], rmax[hi]);
            fac[hi]  = exp2fast(mprev[hi] - mnew[hi]);
        }
        #pragma unroll
        for (int nt = 0; nt < 8; nt++) {
            #pragma unroll
            for (int ci = 0; ci < 4; ci++) {
                float p = exp2fast(s[nt][ci] - mnew[ci >> 1]);
                ps[ci >> 1] += p;
                s[nt][ci] = p;
            }
        }
        #pragma unroll
        for (int off = 1; off < 4; off <<= 1) {
            ps[0] += __shfl_xor_sync(0xffffffffu, ps[0], off);
            ps[1] += __shfl_xor_sync(0xffffffffu, ps[1], off);
        }
        #pragma unroll
        for (int hi = 0; hi < 2; hi++) {
            lsum[hi] = lsum[hi] * fac[hi] + ps[hi];
            mprev[hi] = mnew[hi];
        }
        #pragma unroll
        for (int nt = 0; nt < 8; nt++) {
            o[nt][0] *= fac[0]; o[nt][1] *= fac[0];
            o[nt][2] *= fac[1]; o[nt][3] *= fac[1];
        }

        #pragma unroll
        for (int kc = 0; kc < 4; kc++) {
            uint32_t a[4];
            a[0] = packbf(s[2 * kc][0],     s[2 * kc][1]);
            a[1] = packbf(s[2 * kc][2],     s[2 * kc][3]);
            a[2] = packbf(s[2 * kc + 1][0], s[2 * kc + 1][1]);
            a[3] = packbf(s[2 * kc + 1][2], s[2 * kc + 1][3]);
            #pragma unroll
            for (int p = 0; p < 4; p++) {
                uint32_t b0, b1, b2, b3;
                LDSM_X4T(b0, b1, b2, b3, vst + (uint32_t)(kc * 16 * ROWB) + p * 32);
                MMA_BF16(o[2 * p],     a, b0, b1);
                MMA_BF16(o[2 * p + 1], a, b2, b3);
            }
        }
        __syncthreads();
    }

    float inv0 = 1.0f / lsum[0], inv1 = 1.0f / lsum[1];
    int r0 = qt * 128 + rbase + g;
    #pragma unroll
    for (int nt = 0; nt < 8; nt++) {
        int col = h * 64 + nt * 8 + 2 * qd;
        *(uint32_t*)(out + (size_t)(b * L_ + r0    ) * D_ + col) = packbf(o[nt][0] * inv0, o[nt][1] * inv0);
        *(uint32_t*)(out + (size_t)(b * L_ + r0 + 8) * D_ + col) = packbf(o[nt][2] * inv1, o[nt][3] * inv1);
    }
}

// ============ launch ============
extern "C" void kernel_launch(void* const* d_in, const int* in_sizes, int n_in,
                              void* d_out, int out_size) {
    const float* x     = (const float*)d_in[0];
    const float* tsb   = (const float*)d_in[1];
    const float* mask  = (const float*)d_in[2];
    const float* ln1_g = (const float*)d_in[3];
    const float* ln1_b = (const float*)d_in[4];
    const float* w_qkv = (const float*)d_in[5];
    const float* w_out = (const float*)d_in[6];
    const float* decay = (const float*)d_in[7];
    const float* ln2_g = (const float*)d_in[8];
    const float* ln2_b = (const float*)d_in[9];
    const float* w_ff1 = (const float*)d_in[10];
    const float* w_ff2 = (const float*)d_in[11];
    float* out = (float*)d_out;

    __nv_bfloat16 *xn, *q, *k, *v, *att, *hh, *ff, *w0, *w1, *w2, *w3;
    float *x1;
    cudaGetSymbolAddress((void**)&xn, g_xn);
    cudaGetSymbolAddress((void**)&q, g_q);
    cudaGetSymbolAddress((void**)&k, g_k);
    cudaGetSymbolAddress((void**)&v, g_v);
    cudaGetSymbolAddress((void**)&att, g_att);
    cudaGetSymbolAddress((void**)&x1, g_x1);
    cudaGetSymbolAddress((void**)&hh, g_h);
    cudaGetSymbolAddress((void**)&ff, g_ff);
    cudaGetSymbolAddress((void**)&w0, g_w0);
    cudaGetSymbolAddress((void**)&w1, g_w1);
    cudaGetSymbolAddress((void**)&w2, g_w2);
    cudaGetSymbolAddress((void**)&w3, g_w3);

    cudaFuncSetAttribute(mma_gemm, cudaFuncAttributeMaxDynamicSharedMemorySize, GEMM_SMEM_B);
    cudaFuncSetAttribute(attn_kernel, cudaFuncAttributeMaxDynamicSharedMemorySize, ATTN_SMEM_B);

    const int n_total = 3 * D_ * D_ + D_ * D_ + FF_ * D_ + D_ * FF_;
    round_all_kernel<<<n_total / 1024, 256>>>(w_qkv, w0, w_out, w1, w_ff1, w2, w_ff2, w3);

    ln_kernel<<<BL_, 256>>>(x, ln1_g, ln1_b, xn);
    mma_gemm<<<dim3(1536 / 128, BL_ / 128), 256, GEMM_SMEM_B>>>(
        xn, w0, D_, 1536, MODE_QKV, nullptr, nullptr, nullptr, q, k, v);
    attn_kernel<<<dim3(L_ / 128, B_ * H_), 256, ATTN_SMEM_B>>>(
        q, k, v, tsb, mask, decay, att);
    mma_gemm<<<dim3(D_ / 128, BL_ / 128), 256, GEMM_SMEM_B>>>(
        att, w1, D_, D_, MODE_RESID, x, x1, nullptr, nullptr, nullptr, nullptr);
    ln_kernel<<<BL_, 256>>>(x1, ln2_g, ln2_b, hh);
    mma_gemm<<<dim3(FF_ / 128, BL_ / 128), 256, GEMM_SMEM_B>>>(
        hh, w2, D_, FF_, MODE_SILU, nullptr, nullptr, ff, nullptr, nullptr, nullptr);
    mma_gemm<<<dim3(D_ / 128, BL_ / 128), 256, GEMM_SMEM_B>>>(
        ff, w3, FF_, D_, MODE_RESID, x1, out, nullptr, nullptr, nullptr, nullptr);
}

// round 9
// speedup vs baseline: 6.6129x; 1.0093x over previous
#include <cuda_runtime.h>
#include <cuda_bf16.h>
#include <math.h>
#include <stdint.h>

#define B_  2
#define L_  4096
#define D_  512
#define H_  8
#define DH_ 64
#define BL_ 8192
#define FF_ 2048

// ---------------- scratch ----------------
__device__ __nv_bfloat16 g_xn [BL_ * D_];
__device__ __nv_bfloat16 g_q [B_ * H_ * L_ * DH_];
__device__ __nv_bfloat16 g_k [B_ * H_ * L_ * DH_];
__device__ __nv_bfloat16 g_v [B_ * H_ * L_ * DH_];
__device__ __nv_bfloat16 g_att[BL_ * D_];
__device__ float g_x1 [BL_ * D_];
__device__ __nv_bfloat16 g_h  [BL_ * D_];
__device__ __nv_bfloat16 g_ff [BL_ * FF_];
__device__ __nv_bfloat16 g_w0 [3 * D_ * D_];
__device__ __nv_bfloat16 g_w1 [D_ * D_];
__device__ __nv_bfloat16 g_w2 [FF_ * D_];
__device__ __nv_bfloat16 g_w3 [D_ * FF_];

__device__ __forceinline__ float exp2fast(float x) {
    float r;
    asm("ex2.approx.f32 %0, %1;" : "=f"(r) : "f"(x));
    return r;
}
__device__ __forceinline__ uint32_t packbf(float lo, float hi) {
    uint32_t r;
    asm("cvt.rn.bf16x2.f32 %0, %1, %2;" : "=r"(r) : "f"(hi), "f"(lo));
    return r;
}

#define MMA_BF16(d, a, b0, b1)                                               \
    asm volatile(                                                            \
        "mma.sync.aligned.m16n8k16.row.col.f32.bf16.bf16.f32 "               \
        "{%0,%1,%2,%3}, {%4,%5,%6,%7}, {%8,%9}, {%0,%1,%2,%3};"              \
        : "+f"(d[0]), "+f"(d[1]), "+f"(d[2]), "+f"(d[3])                     \
        : "r"(a[0]), "r"(a[1]), "r"(a[2]), "r"(a[3]), "r"(b0), "r"(b1))

#define LDSM_X4(r0, r1, r2, r3, addr)                                        \
    asm volatile("ldmatrix.sync.aligned.m8n8.x4.shared.b16 {%0,%1,%2,%3}, [%4];" \
        : "=r"(r0), "=r"(r1), "=r"(r2), "=r"(r3) : "r"(addr))

#define LDSM_X4T(r0, r1, r2, r3, addr)                                       \
    asm volatile("ldmatrix.sync.aligned.m8n8.x4.trans.shared.b16 {%0,%1,%2,%3}, [%4];" \
        : "=r"(r0), "=r"(r1), "=r"(r2), "=r"(r3) : "r"(addr))

// ============ weight conversion fp32 -> bf16 ============
__global__ __launch_bounds__(256) void round_all_kernel(
    const float* __restrict__ s0, __nv_bfloat16* __restrict__ d0,
    const float* __restrict__ s1, __nv_bfloat16* __restrict__ d1,
    const float* __restrict__ s2, __nv_bfloat16* __restrict__ d2,
    const float* __restrict__ s3, __nv_bfloat16* __restrict__ d3)
{
    const int n0 = 3 * D_ * D_, n1 = D_ * D_, n2 = FF_ * D_;
    int i = (blockIdx.x * 256 + threadIdx.x) * 4;
    const float* src; __nv_bfloat16* dst; int off;
    if (i < n0)                { src = s0; dst = d0; off = i; }
    else if (i < n0 + n1)      { src = s1; dst = d1; off = i - n0; }
    else if (i < n0 + n1 + n2) { src = s2; dst = d2; off = i - n0 - n1; }
    else                       { src = s3; dst = d3; off = i - n0 - n1 - n2; }
    float4 v = *(const float4*)(src + off);
    uint2 o;
    o.x = packbf(v.x, v.y);
    o.y = packbf(v.z, v.w);
    *(uint2*)(dst + off) = o;
}

// ============ LayerNorm (bf16 output) ============
__global__ __launch_bounds__(256) void ln_kernel(const float* __restrict__ x,
                                                 const float* __restrict__ g,
                                                 const float* __restrict__ b,
                                                 __nv_bfloat16* __restrict__ y) {
    int row = blockIdx.x;
    const float* xr = x + (size_t)row * D_;
    __nv_bfloat16* yr = y + (size_t)row * D_;
    int tid = threadIdx.x;
    float v0 = xr[tid], v1 = xr[tid + 256];
    float s = v0 + v1, ss = v0 * v0 + v1 * v1;
    #pragma unroll
    for (int o = 16; o > 0; o >>= 1) {
        s  += __shfl_xor_sync(0xffffffffu, s,  o);
        ss += __shfl_xor_sync(0xffffffffu, ss, o);
    }
    __shared__ float red[16];
    int w = tid >> 5, lane = tid & 31;
    if (lane == 0) { red[w] = s; red[w + 8] = ss; }
    __syncthreads();
    float S = 0.f, SS = 0.f;
    #pragma unroll
    for (int i = 0; i < 8; i++) { S += red[i]; SS += red[i + 8]; }
    float mu = S * (1.0f / D_);
    float inv = rsqrtf(SS * (1.0f / D_) - mu * mu + 1e-5f);
    yr[tid]       = __float2bfloat16((v0 - mu) * inv * g[tid]       + b[tid]);
    yr[tid + 256] = __float2bfloat16((v1 - mu) * inv * g[tid + 256] + b[tid + 256]);
}

// ============ bf16 mma GEMM: C = A[M,K] @ W[N,K]^T ============
#define ROWG 80
#define STG_B (128 * ROWG)
#define STAGE_B (2 * STG_B)
#define GEMM_SMEM_B (3 * STAGE_B)
#define MODE_QKV   0
#define MODE_RESID 1
#define MODE_SILU  2

__global__ __launch_bounds__(256, 2) void mma_gemm(
    const __nv_bfloat16* __restrict__ A, const __nv_bfloat16* __restrict__ W,
    int K, int N, int mode, const float* __restrict__ resid,
    float* __restrict__ out, __nv_bfloat16* __restrict__ outb,
    __nv_bfloat16* __restrict__ oq, __nv_bfloat16* __restrict__ okk,
    __nv_bfloat16* __restrict__ ov)
{
    extern __shared__ char smg[];
    uint32_t sbase = (uint32_t)__cvta_generic_to_shared(smg);
    int tid = threadIdx.x;
    int wid = tid >> 5, lane = tid & 31;
    int wm = wid & 1, wn = wid >> 1;
    int g = lane >> 2, qd = lane & 3;
    int bm = blockIdx.y, bn = blockIdx.x;
    const __nv_bfloat16* Ab = A + (size_t)bm * 128 * K;
    const __nv_bfloat16* Wb = W + (size_t)bn * 128 * K;
    const int NC = K >> 5;

    int arow = wm * 64 + (lane & 7) + ((lane >> 3) & 1) * 8;
    int acol = (lane >> 4) * 16;
    int wrow = wn * 32 + (lane & 7) + ((lane >> 4) & 1) * 8;
    int wcol = ((lane >> 3) & 1) * 16;

    float acc[4][4][4];
    #pragma unroll
    for (int i = 0; i < 4; i++)
        #pragma unroll
        for (int j = 0; j < 4; j++)
            #pragma unroll
            for (int e = 0; e < 4; e++) acc[i][j][e] = 0.f;

    auto load_stage = [&](int c, int st) {
        int k0 = c << 5;
        #pragma unroll
        for (int i = 0; i < 2; i++) {
            int idx = tid + i * 256;
            int r = idx >> 2, cb = idx & 3;
            uint32_t da = sbase + (uint32_t)(st * STAGE_B + r * ROWG + cb * 16);
            asm volatile("cp.async.cg.shared.global [%0], [%1], 16;"
                         :: "r"(da), "l"(Ab + (size_t)r * K + k0 + cb * 8) : "memory");
            asm volatile("cp.async.cg.shared.global [%0], [%1], 16;"
                         :: "r"(da + STG_B), "l"(Wb + (size_t)r * K + k0 + cb * 8) : "memory");
        }
        asm volatile("cp.async.commit_group;" ::: "memory");
    };

    load_stage(0, 0); load_stage(1, 1); load_stage(2, 2);
    int st = 0;

    for (int c = 0; c < NC; c++) {
        asm volatile("cp.async.wait_group 2;" ::: "memory");
        __syncthreads();

        uint32_t abase = sbase + (uint32_t)(st * STAGE_B);
        uint32_t wbase = abase + STG_B;
        #pragma unroll
        for (int kc = 0; kc < 2; kc++) {
            uint32_t a[4][4], bfr[2][4];
            #pragma unroll
            for (int mt = 0; mt < 4; mt++)
                LDSM_X4(a[mt][0], a[mt][1], a[mt][2], a[mt][3],
                        abase + (uint32_t)((arow + mt * 16) * ROWG + acol + kc * 32));
            #pragma unroll
            for (int t = 0; t < 2; t++)
                LDSM_X4(bfr[t][0], bfr[t][1], bfr[t][2], bfr[t][3],
                        wbase + (uint32_t)((wrow + t * 16) * ROWG + wcol + kc * 32));
            #pragma unroll
            for (int mt = 0; mt < 4; mt++)
                #pragma unroll
                for (int t = 0; t < 2; t++) {
                    MMA_BF16(acc[mt][2 * t],     a[mt], bfr[t][0], bfr[t][1]);
                    MMA_BF16(acc[mt][2 * t + 1], a[mt], bfr[t][2], bfr[t][3]);
                }
        }
        __syncthreads();
        if (c + 3 < NC) load_stage(c + 3, st);
        st = (st == 2) ? 0 : st + 1;
    }

    #pragma unroll
    for (int mt = 0; mt < 4; mt++) {
        #pragma unroll
        for (int nt = 0; nt < 4; nt++) {
            int cb = bn * 128 + wn * 32 + nt * 8 + 2 * qd;
            #pragma unroll
            for (int hi = 0; hi < 2; hi++) {
                int r = bm * 128 + wm * 64 + mt * 16 + g + hi * 8;
                float v0 = acc[mt][nt][hi * 2], v1 = acc[mt][nt][hi * 2 + 1];
                if (mode == MODE_QKV) {
                    int which = cb >> 9, h = (cb >> 6) & 7, d0 = cb & 63;
                    int bb = r >> 12, l = r & 4095;
                    __nv_bfloat16* dst = (which == 0) ? oq : (which == 1) ? okk : ov;
                    *(uint32_t*)(dst + (((size_t)bb * H_ + h) * L_ + l) * DH_ + d0) = packbf(v0, v1);
                } else if (mode == MODE_RESID) {
                    size_t idx = (size_t)r * N + cb;
                    float2 rv = *(const float2*)(resid + idx);
                    float2 o2 = {rv.x + v0, rv.y + v1};
                    *(float2*)(out + idx) = o2;
                } else {
                    size_t idx = (size_t)r * N + cb;
                    float a0 = v0 / (1.0f + __expf(-v0));
                    float a1 = v1 / (1.0f + __expf(-v1));
                    *(uint32_t*)(outb + idx) = packbf(a0, a1);
                }
            }
        }
    }
}

// ============ flash attention, bf16 mma + ldmatrix + separable bias ============
// bias: -dcy*|tq_r - tk_c| = -dcy*tq_r + dcy*tk_c on surviving (causal) entries;
// the per-row term cancels in softmax, leaving only a per-column constant
// colb[c] = mask ? dcy2*tk_c : -3e38 precomputed at tile load.
#define KSB 72
#define ROWB (KSB * 2)
#define OQ_B   0
#define OK_B   (128 * ROWB)
#define OV_B   (OK_B + 2 * 64 * ROWB)
#define OCB_B  (OV_B + 2 * 64 * ROWB)
#define ATTN_SMEM_B (OCB_B + 2 * 64 * 4)

__global__ __launch_bounds__(256, 2) void attn_kernel(
    const __nv_bfloat16* __restrict__ q, const __nv_bfloat16* __restrict__ k,
    const __nv_bfloat16* __restrict__ v, const float* __restrict__ ts,
    const float* __restrict__ mask, const float* __restrict__ decay_rate,
    __nv_bfloat16* __restrict__ out)
{
    extern __shared__ char smc[];
    uint32_t smb = (uint32_t)__cvta_generic_to_shared(smc);
    float* colb = (float*)(smc + OCB_B);

    int qt = gridDim.x - 1 - blockIdx.x;
    int bh = blockIdx.y, b = bh >> 3, h = bh & 7;
    int tid = threadIdx.x, wid = tid >> 5, lane = tid & 31;
    int g = lane >> 2, qd = lane & 3;
    int rbase = wid * 16;
    const int nkt = 2 * qt + 2;

    uint32_t qaddr = smb + OQ_B + (uint32_t)(rbase + (lane & 7) + ((lane >> 3) & 1) * 8) * ROWB
                   + (uint32_t)(lane >> 4) * 16;
    uint32_t kaddr = smb + OK_B + (uint32_t)((lane & 7) + ((lane >> 4) & 1) * 8) * ROWB
                   + (uint32_t)((lane >> 3) & 1) * 16;
    uint32_t vaddr = smb + OV_B + (uint32_t)((lane & 7) + ((lane >> 3) & 1) * 8) * ROWB
                   + (uint32_t)(lane >> 4) * 16;

    const __nv_bfloat16* qb = q + ((size_t)bh * L_ + qt * 128) * DH_;
    for (int i = tid; i < 1024; i += 256) {
        int r = i >> 3, c8 = (i & 7) << 3;
        *(uint4*)(smc + OQ_B + r * ROWB + c8 * 2) = *(const uint4*)(qb + (size_t)r * DH_ + c8);
    }

    const float LOG2E = 1.44269504f;
    float scale2 = 0.125f * LOG2E;
    float dcy2 = log1pf(__expf(decay_rate[h])) * (LOG2E / 24.0f);
    float mprev[2] = {-1e30f, -1e30f};
    float lsum[2] = {0.f, 0.f};
    float o[8][4];
    #pragma unroll
    for (int i = 0; i < 8; i++)
        #pragma unroll
        for (int e = 0; e < 4; e++) o[i][e] = 0.f;

    auto load_kv = [&](int jt, int st) {
        const __nv_bfloat16* kb = k + ((size_t)bh * L_ + jt * 64) * DH_;
        const __nv_bfloat16* vb = v + ((size_t)bh * L_ + jt * 64) * DH_;
        uint32_t kdst = smb + OK_B + (uint32_t)st * 64 * ROWB;
        uint32_t vdst = smb + OV_B + (uint32_t)st * 64 * ROWB;
        #pragma unroll
        for (int i = 0; i < 2; i++) {
            int idx = tid + i * 256;
            int r = idx >> 3, c8 = (idx & 7) << 3;
            asm volatile("cp.async.cg.shared.global [%0], [%1], 16;"
                         :: "r"(kdst + (uint32_t)(r * ROWB + c8 * 2)),
                            "l"(kb + (size_t)r * DH_ + c8) : "memory");
            asm volatile("cp.async.cg.shared.global [%0], [%1], 16;"
                         :: "r"(vdst + (uint32_t)(r * ROWB + c8 * 2)),
                            "l"(vb + (size_t)r * DH_ + c8) : "memory");
        }
        asm volatile("cp.async.commit_group;" ::: "memory");
        if (tid < 64) {
            // transformed column bias (plain LDG -> STS; ordered by the tile barrier)
            float t = ts[b * L_ + jt * 64 + tid];
            float m = mask[b * L_ + jt * 64 + tid];
            colb[st * 64 + tid] = (m != 0.f) ? dcy2 * t : -3e38f;
        }
    };

    load_kv(0, 0);

    for (int jt = 0; jt < nkt; jt++) {
        int st = jt & 1;
        if (jt + 1 < nkt) {
            load_kv(jt + 1, (jt + 1) & 1);
            asm volatile("cp.async.wait_group 1;" ::: "memory");
        } else {
            asm volatile("cp.async.wait_group 0;" ::: "memory");
        }
        __syncthreads();

        uint32_t kst = kaddr + (uint32_t)st * 64 * ROWB;
        uint32_t vst = vaddr + (uint32_t)st * 64 * ROWB;
        const float* cbs = colb + st * 64;
        bool diag = (jt >= 2 * qt);

        // ---- S = Q K^T ----
        float s[8][4];
        #pragma unroll
        for (int i = 0; i < 8; i++)
            #pragma unroll
            for (int e = 0; e < 4; e++) s[i][e] = 0.f;
        #pragma unroll
        for (int ks = 0; ks < 4; ks++) {
            uint32_t qa0, qa1, qa2, qa3;
            LDSM_X4(qa0, qa1, qa2, qa3, qaddr + ks * 32);
            uint32_t a[4] = {qa0, qa1, qa2, qa3};
            #pragma unroll
            for (int p = 0; p < 4; p++) {
                uint32_t b0, b1, b2, b3;
                LDSM_X4(b0, b1, b2, b3, kst + (uint32_t)(p * 16 * ROWB) + ks * 32);
                MMA_BF16(s[2 * p],     a, b0, b1);
                MMA_BF16(s[2 * p + 1], a, b2, b3);
            }
        }

        // ---- bias (separable, per-column only) + causal on diagonal tiles ----
        int qi0 = qt * 128 + rbase + g;
        #pragma unroll
        for (int nt = 0; nt < 8; nt++) {
            float2 cb2 = *(const float2*)(cbs + nt * 8 + 2 * qd);
            s[nt][0] = fmaf(s[nt][0], scale2, cb2.x);
            s[nt][1] = fmaf(s[nt][1], scale2, cb2.y);
            s[nt][2] = fmaf(s[nt][2], scale2, cb2.x);
            s[nt][3] = fmaf(s[nt][3], scale2, cb2.y);
            if (diag) {
                int colbase = jt * 64 + nt * 8 + 2 * qd;
                if (colbase     > qi0)     s[nt][0] = -3e38f;
                if (colbase + 1 > qi0)     s[nt][1] = -3e38f;
                if (colbase     > qi0 + 8) s[nt][2] = -3e38f;
                if (colbase + 1 > qi0 + 8) s[nt][3] = -3e38f;
            }
        }

        // ---- online softmax (exp2) ----
        float rmax[2] = {-1e30f, -1e30f};
        #pragma unroll
        for (int nt = 0; nt < 8; nt++) {
            rmax[0] = fmaxf(rmax[0], fmaxf(s[nt][0], s[nt][1]));
            rmax[1] = fmaxf(rmax[1], fmaxf(s[nt][2], s[nt][3]));
        }
        #pragma unroll
        for (int off = 1; off < 4; off <<= 1) {
            rmax[0] = fmaxf(rmax[0], __shfl_xor_sync(0xffffffffu, rmax[0], off));
            rmax[1] = fmaxf(rmax[1], __shfl_xor_sync(0xffffffffu, rmax[1], off));
        }
        float mnew[2], fac[2], ps[2] = {0.f, 0.f};
        #pragma unroll
        for (int hi = 0; hi < 2; hi++) {
            mnew[hi] = fmaxf(mprev[hi], rmax[hi]);
            fac[hi]  = exp2fast(mprev[hi] - mnew[hi]);
        }
        #pragma unroll
        for (int nt = 0; nt < 8; nt++) {
            #pragma unroll
            for (int ci = 0; ci < 4; ci++) {
                float p = exp2fast(s[nt][ci] - mnew[ci >> 1]);
                ps[ci >> 1] += p;
                s[nt][ci] = p;
            }
        }
        #pragma unroll
        for (int off = 1; off < 4; off <<= 1) {
            ps[0] += __shfl_xor_sync(0xffffffffu, ps[0], off);
            ps[1] += __shfl_xor_sync(0xffffffffu, ps[1], off);
        }
        #pragma unroll
        for (int hi = 0; hi < 2; hi++) {
            lsum[hi] = lsum[hi] * fac[hi] + ps[hi];
            mprev[hi] = mnew[hi];
        }
        #pragma unroll
        for (int nt = 0; nt < 8; nt++) {
            o[nt][0] *= fac[0]; o[nt][1] *= fac[0];
            o[nt][2] *= fac[1]; o[nt][3] *= fac[1];
        }

        // ---- O += P V ----
        #pragma unroll
        for (int kc = 0; kc < 4; kc++) {
            uint32_t a[4];
            a[0] = packbf(s[2 * kc][0],     s[2 * kc][1]);
            a[1] = packbf(s[2 * kc][2],     s[2 * kc][3]);
            a[2] = packbf(s[2 * kc + 1][0], s[2 * kc + 1][1]);
            a[3] = packbf(s[2 * kc + 1][2], s[2 * kc + 1][3]);
            #pragma unroll
            for (int p = 0; p < 4; p++) {
                uint32_t b0, b1, b2, b3;
                LDSM_X4T(b0, b1, b2, b3, vst + (uint32_t)(kc * 16 * ROWB) + p * 32);
                MMA_BF16(o[2 * p],     a, b0, b1);
                MMA_BF16(o[2 * p + 1], a, b2, b3);
            }
        }
        __syncthreads();
    }

    float inv0 = 1.0f / lsum[0], inv1 = 1.0f / lsum[1];
    int r0 = qt * 128 + rbase + g;
    #pragma unroll
    for (int nt = 0; nt < 8; nt++) {
        int col = h * 64 + nt * 8 + 2 * qd;
        *(uint32_t*)(out + (size_t)(b * L_ + r0    ) * D_ + col) = packbf(o[nt][0] * inv0, o[nt][1] * inv0);
        *(uint32_t*)(out + (size_t)(b * L_ + r0 + 8) * D_ + col) = packbf(o[nt][2] * inv1, o[nt][3] * inv1);
    }
}

// ============ launch ============
extern "C" void kernel_launch(void* const* d_in, const int* in_sizes, int n_in,
                              void* d_out, int out_size) {
    const float* x     = (const float*)d_in[0];
    const float* tsb   = (const float*)d_in[1];
    const float* mask  = (const float*)d_in[2];
    const float* ln1_g = (const float*)d_in[3];
    const float* ln1_b = (const float*)d_in[4];
    const float* w_qkv = (const float*)d_in[5];
    const float* w_out = (const float*)d_in[6];
    const float* decay = (const float*)d_in[7];
    const float* ln2_g = (const float*)d_in[8];
    const float* ln2_b = (const float*)d_in[9];
    const float* w_ff1 = (const float*)d_in[10];
    const float* w_ff2 = (const float*)d_in[11];
    float* out = (float*)d_out;

    __nv_bfloat16 *xn, *q, *k, *v, *att, *hh, *ff, *w0, *w1, *w2, *w3;
    float *x1;
    cudaGetSymbolAddress((void**)&xn, g_xn);
    cudaGetSymbolAddress((void**)&q, g_q);
    cudaGetSymbolAddress((void**)&k, g_k);
    cudaGetSymbolAddress((void**)&v, g_v);
    cudaGetSymbolAddress((void**)&att, g_att);
    cudaGetSymbolAddress((void**)&x1, g_x1);
    cudaGetSymbolAddress((void**)&hh, g_h);
    cudaGetSymbolAddress((void**)&ff, g_ff);
    cudaGetSymbolAddress((void**)&w0, g_w0);
    cudaGetSymbolAddress((void**)&w1, g_w1);
    cudaGetSymbolAddress((void**)&w2, g_w2);
    cudaGetSymbolAddress((void**)&w3, g_w3);

    cudaFuncSetAttribute(mma_gemm, cudaFuncAttributeMaxDynamicSharedMemorySize, GEMM_SMEM_B);
    cudaFuncSetAttribute(attn_kernel, cudaFuncAttributeMaxDynamicSharedMemorySize, ATTN_SMEM_B);

    const int n_total = 3 * D_ * D_ + D_ * D_ + FF_ * D_ + D_ * FF_;
    round_all_kernel<<<n_total / 1024, 256>>>(w_qkv, w0, w_out, w1, w_ff1, w2, w_ff2, w3);

    ln_kernel<<<BL_, 256>>>(x, ln1_g, ln1_b, xn);
    mma_gemm<<<dim3(1536 / 128, BL_ / 128), 256, GEMM_SMEM_B>>>(
        xn, w0, D_, 1536, MODE_QKV, nullptr, nullptr, nullptr, q, k, v);
    attn_kernel<<<dim3(L_ / 128, B_ * H_), 256, ATTN_SMEM_B>>>(
        q, k, v, tsb, mask, decay, att);
    mma_gemm<<<dim3(D_ / 128, BL_ / 128), 256, GEMM_SMEM_B>>>(
        att, w1, D_, D_, MODE_RESID, x, x1, nullptr, nullptr, nullptr, nullptr);
    ln_kernel<<<BL_, 256>>>(x1, ln2_g, ln2_b, hh);
    mma_gemm<<<dim3(FF_ / 128, BL_ / 128), 256, GEMM_SMEM_B>>>(
        hh, w2, D_, FF_, MODE_SILU, nullptr, nullptr, ff, nullptr, nullptr, nullptr);
    mma_gemm<<<dim3(D_ / 128, BL_ / 128), 256, GEMM_SMEM_B>>>(
        ff, w3, FF_, D_, MODE_RESID, x1, out, nullptr, nullptr, nullptr, nullptr);
}

// round 10
// speedup vs baseline: 6.9947x; 1.0577x over previous
#include <cuda_runtime.h>
#include <cuda_bf16.h>
#include <math.h>
#include <stdint.h>

#define B_  2
#define L_  4096
#define D_  512
#define H_  8
#define DH_ 64
#define BL_ 8192
#define FF_ 2048

// ---------------- scratch ----------------
__device__ __nv_bfloat16 g_xn [BL_ * D_];
__device__ __nv_bfloat16 g_q [B_ * H_ * L_ * DH_];
__device__ __nv_bfloat16 g_k [B_ * H_ * L_ * DH_];
__device__ __nv_bfloat16 g_v [B_ * H_ * L_ * DH_];
__device__ __nv_bfloat16 g_att[BL_ * D_];
__device__ float g_x1 [BL_ * D_];
__device__ __nv_bfloat16 g_h  [BL_ * D_];
__device__ __nv_bfloat16 g_ff [BL_ * FF_];
__device__ __nv_bfloat16 g_w0 [3 * D_ * D_];
__device__ __nv_bfloat16 g_w1 [D_ * D_];
__device__ __nv_bfloat16 g_w2 [FF_ * D_];
__device__ __nv_bfloat16 g_w3 [D_ * FF_];

__device__ __forceinline__ float exp2fast(float x) {
    float r;
    asm("ex2.approx.f32 %0, %1;" : "=f"(r) : "f"(x));
    return r;
}
__device__ __forceinline__ uint32_t packbf(float lo, float hi) {
    uint32_t r;
    asm("cvt.rn.bf16x2.f32 %0, %1, %2;" : "=r"(r) : "f"(hi), "f"(lo));
    return r;
}

#define MMA_BF16(d, a, b0, b1)                                               \
    asm volatile(                                                            \
        "mma.sync.aligned.m16n8k16.row.col.f32.bf16.bf16.f32 "               \
        "{%0,%1,%2,%3}, {%4,%5,%6,%7}, {%8,%9}, {%0,%1,%2,%3};"              \
        : "+f"(d[0]), "+f"(d[1]), "+f"(d[2]), "+f"(d[3])                     \
        : "r"(a[0]), "r"(a[1]), "r"(a[2]), "r"(a[3]), "r"(b0), "r"(b1))

#define LDSM_X4(r0, r1, r2, r3, addr)                                        \
    asm volatile("ldmatrix.sync.aligned.m8n8.x4.shared.b16 {%0,%1,%2,%3}, [%4];" \
        : "=r"(r0), "=r"(r1), "=r"(r2), "=r"(r3) : "r"(addr))

#define LDSM_X4T(r0, r1, r2, r3, addr)                                       \
    asm volatile("ldmatrix.sync.aligned.m8n8.x4.trans.shared.b16 {%0,%1,%2,%3}, [%4];" \
        : "=r"(r0), "=r"(r1), "=r"(r2), "=r"(r3) : "r"(addr))

// ============ weight conversion fp32 -> bf16 ============
__global__ __launch_bounds__(256) void round_all_kernel(
    const float* __restrict__ s0, __nv_bfloat16* __restrict__ d0,
    const float* __restrict__ s1, __nv_bfloat16* __restrict__ d1,
    const float* __restrict__ s2, __nv_bfloat16* __restrict__ d2,
    const float* __restrict__ s3, __nv_bfloat16* __restrict__ d3)
{
    const int n0 = 3 * D_ * D_, n1 = D_ * D_, n2 = FF_ * D_;
    int i = (blockIdx.x * 256 + threadIdx.x) * 4;
    const float* src; __nv_bfloat16* dst; int off;
    if (i < n0)                { src = s0; dst = d0; off = i; }
    else if (i < n0 + n1)      { src = s1; dst = d1; off = i - n0; }
    else if (i < n0 + n1 + n2) { src = s2; dst = d2; off = i - n0 - n1; }
    else                       { src = s3; dst = d3; off = i - n0 - n1 - n2; }
    float4 v = *(const float4*)(src + off);
    uint2 o;
    o.x = packbf(v.x, v.y);
    o.y = packbf(v.z, v.w);
    *(uint2*)(dst + off) = o;
}

// ============ LayerNorm (bf16 output) ============
__global__ __launch_bounds__(256) void ln_kernel(const float* __restrict__ x,
                                                 const float* __restrict__ g,
                                                 const float* __restrict__ b,
                                                 __nv_bfloat16* __restrict__ y) {
    int row = blockIdx.x;
    const float* xr = x + (size_t)row * D_;
    __nv_bfloat16* yr = y + (size_t)row * D_;
    int tid = threadIdx.x;
    float v0 = xr[tid], v1 = xr[tid + 256];
    float s = v0 + v1, ss = v0 * v0 + v1 * v1;
    #pragma unroll
    for (int o = 16; o > 0; o >>= 1) {
        s  += __shfl_xor_sync(0xffffffffu, s,  o);
        ss += __shfl_xor_sync(0xffffffffu, ss, o);
    }
    __shared__ float red[16];
    int w = tid >> 5, lane = tid & 31;
    if (lane == 0) { red[w] = s; red[w + 8] = ss; }
    __syncthreads();
    float S = 0.f, SS = 0.f;
    #pragma unroll
    for (int i = 0; i < 8; i++) { S += red[i]; SS += red[i + 8]; }
    float mu = S * (1.0f / D_);
    float inv = rsqrtf(SS * (1.0f / D_) - mu * mu + 1e-5f);
    yr[tid]       = __float2bfloat16((v0 - mu) * inv * g[tid]       + b[tid]);
    yr[tid + 256] = __float2bfloat16((v1 - mu) * inv * g[tid + 256] + b[tid + 256]);
}

// ============ bf16 mma GEMM: C = A[M,K] @ W[N,K]^T ============
#define ROWG 80
#define STG_B (128 * ROWG)
#define STAGE_B (2 * STG_B)
#define GEMM_SMEM_B (3 * STAGE_B)
#define MODE_QKV   0
#define MODE_RESID 1
#define MODE_SILU  2

__global__ __launch_bounds__(256, 2) void mma_gemm(
    const __nv_bfloat16* __restrict__ A, const __nv_bfloat16* __restrict__ W,
    int K, int N, int mode, const float* __restrict__ resid,
    float* __restrict__ out, __nv_bfloat16* __restrict__ outb,
    __nv_bfloat16* __restrict__ oq, __nv_bfloat16* __restrict__ okk,
    __nv_bfloat16* __restrict__ ov)
{
    extern __shared__ char smg[];
    uint32_t sbase = (uint32_t)__cvta_generic_to_shared(smg);
    int tid = threadIdx.x;
    int wid = tid >> 5, lane = tid & 31;
    int wm = wid & 1, wn = wid >> 1;
    int g = lane >> 2, qd = lane & 3;
    int bm = blockIdx.y, bn = blockIdx.x;
    const __nv_bfloat16* Ab = A + (size_t)bm * 128 * K;
    const __nv_bfloat16* Wb = W + (size_t)bn * 128 * K;
    const int NC = K >> 5;

    int arow = wm * 64 + (lane & 7) + ((lane >> 3) & 1) * 8;
    int acol = (lane >> 4) * 16;
    int wrow = wn * 32 + (lane & 7) + ((lane >> 4) & 1) * 8;
    int wcol = ((lane >> 3) & 1) * 16;

    float acc[4][4][4];
    #pragma unroll
    for (int i = 0; i < 4; i++)
        #pragma unroll
        for (int j = 0; j < 4; j++)
            #pragma unroll
            for (int e = 0; e < 4; e++) acc[i][j][e] = 0.f;

    auto load_stage = [&](int c, int st) {
        int k0 = c << 5;
        #pragma unroll
        for (int i = 0; i < 2; i++) {
            int idx = tid + i * 256;
            int r = idx >> 2, cb = idx & 3;
            uint32_t da = sbase + (uint32_t)(st * STAGE_B + r * ROWG + cb * 16);
            asm volatile("cp.async.cg.shared.global [%0], [%1], 16;"
                         :: "r"(da), "l"(Ab + (size_t)r * K + k0 + cb * 8) : "memory");
            asm volatile("cp.async.cg.shared.global [%0], [%1], 16;"
                         :: "r"(da + STG_B), "l"(Wb + (size_t)r * K + k0 + cb * 8) : "memory");
        }
        asm volatile("cp.async.commit_group;" ::: "memory");
    };

    load_stage(0, 0); load_stage(1, 1); load_stage(2, 2);
    int st = 0;

    for (int c = 0; c < NC; c++) {
        asm volatile("cp.async.wait_group 2;" ::: "memory");
        __syncthreads();

        uint32_t abase = sbase + (uint32_t)(st * STAGE_B);
        uint32_t wbase = abase + STG_B;
        #pragma unroll
        for (int kc = 0; kc < 2; kc++) {
            uint32_t a[4][4], bfr[2][4];
            #pragma unroll
            for (int mt = 0; mt < 4; mt++)
                LDSM_X4(a[mt][0], a[mt][1], a[mt][2], a[mt][3],
                        abase + (uint32_t)((arow + mt * 16) * ROWG + acol + kc * 32));
            #pragma unroll
            for (int t = 0; t < 2; t++)
                LDSM_X4(bfr[t][0], bfr[t][1], bfr[t][2], bfr[t][3],
                        wbase + (uint32_t)((wrow + t * 16) * ROWG + wcol + kc * 32));
            #pragma unroll
            for (int mt = 0; mt < 4; mt++)
                #pragma unroll
                for (int t = 0; t < 2; t++) {
                    MMA_BF16(acc[mt][2 * t],     a[mt], bfr[t][0], bfr[t][1]);
                    MMA_BF16(acc[mt][2 * t + 1], a[mt], bfr[t][2], bfr[t][3]);
                }
        }
        __syncthreads();
        if (c + 3 < NC) load_stage(c + 3, st);
        st = (st == 2) ? 0 : st + 1;
    }

    #pragma unroll
    for (int mt = 0; mt < 4; mt++) {
        #pragma unroll
        for (int nt = 0; nt < 4; nt++) {
            int cb = bn * 128 + wn * 32 + nt * 8 + 2 * qd;
            #pragma unroll
            for (int hi = 0; hi < 2; hi++) {
                int r = bm * 128 + wm * 64 + mt * 16 + g + hi * 8;
                float v0 = acc[mt][nt][hi * 2], v1 = acc[mt][nt][hi * 2 + 1];
                if (mode == MODE_QKV) {
                    int which = cb >> 9, h = (cb >> 6) & 7, d0 = cb & 63;
                    int bb = r >> 12, l = r & 4095;
                    __nv_bfloat16* dst = (which == 0) ? oq : (which == 1) ? okk : ov;
                    *(uint32_t*)(dst + (((size_t)bb * H_ + h) * L_ + l) * DH_ + d0) = packbf(v0, v1);
                } else if (mode == MODE_RESID) {
                    size_t idx = (size_t)r * N + cb;
                    float2 rv = *(const float2*)(resid + idx);
                    float2 o2 = {rv.x + v0, rv.y + v1};
                    *(float2*)(out + idx) = o2;
                } else {
                    size_t idx = (size_t)r * N + cb;
                    float a0 = v0 / (1.0f + __expf(-v0));
                    float a1 = v1 / (1.0f + __expf(-v1));
                    *(uint32_t*)(outb + idx) = packbf(a0, a1);
                }
            }
        }
    }
}

// ============ flash attention: 64-row Q tiles, 128 thr, 4 CTA/SM ============
#define KSB 72
#define ROWB (KSB * 2)
#define OQ_B   0
#define OK_B   (64 * ROWB)                    // 9216
#define OV_B   (OK_B + 2 * 64 * ROWB)         // +18432
#define OCB_B  (OV_B + 2 * 64 * ROWB)         // +18432
#define ATTN_SMEM_B (OCB_B + 2 * 64 * 4)      // 46592

__global__ __launch_bounds__(128, 4) void attn_kernel(
    const __nv_bfloat16* __restrict__ q, const __nv_bfloat16* __restrict__ k,
    const __nv_bfloat16* __restrict__ v, const float* __restrict__ ts,
    const float* __restrict__ mask, const float* __restrict__ decay_rate,
    __nv_bfloat16* __restrict__ out)
{
    extern __shared__ char smc[];
    uint32_t smb = (uint32_t)__cvta_generic_to_shared(smc);
    float* colb = (float*)(smc + OCB_B);

    int qt = gridDim.x - 1 - blockIdx.x;       // big blocks first
    int bh = blockIdx.y, b = bh >> 3, h = bh & 7;
    int tid = threadIdx.x, wid = tid >> 5, lane = tid & 31;
    int g = lane >> 2, qd = lane & 3;
    int rbase = wid * 16;
    const int nkt = qt + 1;

    uint32_t qaddr = smb + OQ_B + (uint32_t)(rbase + (lane & 7) + ((lane >> 3) & 1) * 8) * ROWB
                   + (uint32_t)(lane >> 4) * 16;
    uint32_t kaddr = smb + OK_B + (uint32_t)((lane & 7) + ((lane >> 4) & 1) * 8) * ROWB
                   + (uint32_t)((lane >> 3) & 1) * 16;
    uint32_t vaddr = smb + OV_B + (uint32_t)((lane & 7) + ((lane >> 3) & 1) * 8) * ROWB
                   + (uint32_t)(lane >> 4) * 16;

    // Q tile (once): 64 rows x 64 bf16
    const __nv_bfloat16* qb = q + ((size_t)bh * L_ + qt * 64) * DH_;
    #pragma unroll
    for (int i = 0; i < 4; i++) {
        int idx = tid + i * 128;
        int r = idx >> 3, c8 = (idx & 7) << 3;
        *(uint4*)(smc + OQ_B + r * ROWB + c8 * 2) = *(const uint4*)(qb + (size_t)r * DH_ + c8);
    }

    const float LOG2E = 1.44269504f;
    float scale2 = 0.125f * LOG2E;
    float dcy2 = log1pf(__expf(decay_rate[h])) * (LOG2E / 24.0f);
    float mprev[2] = {-1e30f, -1e30f};
    float lsum[2] = {0.f, 0.f};
    float o[8][4];
    #pragma unroll
    for (int i = 0; i < 8; i++)
        #pragma unroll
        for (int e = 0; e < 4; e++) o[i][e] = 0.f;

    auto load_kv = [&](int jt, int st) {
        const __nv_bfloat16* kb = k + ((size_t)bh * L_ + jt * 64) * DH_;
        const __nv_bfloat16* vb = v + ((size_t)bh * L_ + jt * 64) * DH_;
        uint32_t kdst = smb + OK_B + (uint32_t)st * 64 * ROWB;
        uint32_t vdst = smb + OV_B + (uint32_t)st * 64 * ROWB;
        #pragma unroll
        for (int i = 0; i < 4; i++) {
            int idx = tid + i * 128;
            int r = idx >> 3, c8 = (idx & 7) << 3;
            asm volatile("cp.async.cg.shared.global [%0], [%1], 16;"
                         :: "r"(kdst + (uint32_t)(r * ROWB + c8 * 2)),
                            "l"(kb + (size_t)r * DH_ + c8) : "memory");
            asm volatile("cp.async.cg.shared.global [%0], [%1], 16;"
                         :: "r"(vdst + (uint32_t)(r * ROWB + c8 * 2)),
                            "l"(vb + (size_t)r * DH_ + c8) : "memory");
        }
        asm volatile("cp.async.commit_group;" ::: "memory");
        if (tid < 64) {
            float t = ts[b * L_ + jt * 64 + tid];
            float m = mask[b * L_ + jt * 64 + tid];
            colb[st * 64 + tid] = (m != 0.f) ? dcy2 * t : -3e38f;
        }
    };

    load_kv(0, 0);

    for (int jt = 0; jt < nkt; jt++) {
        int st = jt & 1;
        if (jt + 1 < nkt) {
            load_kv(jt + 1, (jt + 1) & 1);
            asm volatile("cp.async.wait_group 1;" ::: "memory");
        } else {
            asm volatile("cp.async.wait_group 0;" ::: "memory");
        }
        __syncthreads();

        uint32_t kst = kaddr + (uint32_t)st * 64 * ROWB;
        uint32_t vst = vaddr + (uint32_t)st * 64 * ROWB;
        const float* cbs = colb + st * 64;
        bool diag = (jt == qt);

        // ---- S = Q K^T ----
        float s[8][4];
        #pragma unroll
        for (int i = 0; i < 8; i++)
            #pragma unroll
            for (int e = 0; e < 4; e++) s[i][e] = 0.f;
        #pragma unroll
        for (int ks = 0; ks < 4; ks++) {
            uint32_t qa0, qa1, qa2, qa3;
            LDSM_X4(qa0, qa1, qa2, qa3, qaddr + ks * 32);
            uint32_t a[4] = {qa0, qa1, qa2, qa3};
            #pragma unroll
            for (int p = 0; p < 4; p++) {
                uint32_t b0, b1, b2, b3;
                LDSM_X4(b0, b1, b2, b3, kst + (uint32_t)(p * 16 * ROWB) + ks * 32);
                MMA_BF16(s[2 * p],     a, b0, b1);
                MMA_BF16(s[2 * p + 1], a, b2, b3);
            }
        }

        // ---- bias (separable per-column) + causal on diag tile ----
        int qi0 = qt * 64 + rbase + g;
        #pragma unroll
        for (int nt = 0; nt < 8; nt++) {
            float2 cb2 = *(const float2*)(cbs + nt * 8 + 2 * qd);
            s[nt][0] = fmaf(s[nt][0], scale2, cb2.x);
            s[nt][1] = fmaf(s[nt][1], scale2, cb2.y);
            s[nt][2] = fmaf(s[nt][2], scale2, cb2.x);
            s[nt][3] = fmaf(s[nt][3], scale2, cb2.y);
            if (diag) {
                int colbase = jt * 64 + nt * 8 + 2 * qd;
                if (colbase     > qi0)     s[nt][0] = -3e38f;
                if (colbase + 1 > qi0)     s[nt][1] = -3e38f;
                if (colbase     > qi0 + 8) s[nt][2] = -3e38f;
                if (colbase + 1 > qi0 + 8) s[nt][3] = -3e38f;
            }
        }

        // ---- online softmax (exp2, dual partial sums) ----
        float rmax[2] = {-1e30f, -1e30f};
        #pragma unroll
        for (int nt = 0; nt < 8; nt++) {
            rmax[0] = fmaxf(rmax[0], fmaxf(s[nt][0], s[nt][1]));
            rmax[1] = fmaxf(rmax[1], fmaxf(s[nt][2], s[nt][3]));
        }
        #pragma unroll
        for (int off = 1; off < 4; off <<= 1) {
            rmax[0] = fmaxf(rmax[0], __shfl_xor_sync(0xffffffffu, rmax[0], off));
            rmax[1] = fmaxf(rmax[1], __shfl_xor_sync(0xffffffffu, rmax[1], off));
        }
        float mnew[2], fac[2];
        float psA[2] = {0.f, 0.f}, psB[2] = {0.f, 0.f};
        #pragma unroll
        for (int hi = 0; hi < 2; hi++) {
            mnew[hi] = fmaxf(mprev[hi], rmax[hi]);
            fac[hi]  = exp2fast(mprev[hi] - mnew[hi]);
        }
        #pragma unroll
        for (int nt = 0; nt < 8; nt++) {
            float p0 = exp2fast(s[nt][0] - mnew[0]);
            float p1 = exp2fast(s[nt][1] - mnew[0]);
            float p2 = exp2fast(s[nt][2] - mnew[1]);
            float p3 = exp2fast(s[nt][3] - mnew[1]);
            if (nt & 1) { psB[0] += p0 + p1; psB[1] += p2 + p3; }
            else        { psA[0] += p0 + p1; psA[1] += p2 + p3; }
            s[nt][0] = p0; s[nt][1] = p1; s[nt][2] = p2; s[nt][3] = p3;
        }
        float ps[2] = {psA[0] + psB[0], psA[1] + psB[1]};
        #pragma unroll
        for (int off = 1; off < 4; off <<= 1) {
            ps[0] += __shfl_xor_sync(0xffffffffu, ps[0], off);
            ps[1] += __shfl_xor_sync(0xffffffffu, ps[1], off);
        }
        #pragma unroll
        for (int hi = 0; hi < 2; hi++) {
            lsum[hi] = lsum[hi] * fac[hi] + ps[hi];
            mprev[hi] = mnew[hi];
        }
        #pragma unroll
        for (int nt = 0; nt < 8; nt++) {
            o[nt][0] *= fac[0]; o[nt][1] *= fac[0];
            o[nt][2] *= fac[1]; o[nt][3] *= fac[1];
        }

        // ---- O += P V ----
        #pragma unroll
        for (int kc = 0; kc < 4; kc++) {
            uint32_t a[4];
            a[0] = packbf(s[2 * kc][0],     s[2 * kc][1]);
            a[1] = packbf(s[2 * kc][2],     s[2 * kc][3]);
            a[2] = packbf(s[2 * kc + 1][0], s[2 * kc + 1][1]);
            a[3] = packbf(s[2 * kc + 1][2], s[2 * kc + 1][3]);
            #pragma unroll
            for (int p = 0; p < 4; p++) {
                uint32_t b0, b1, b2, b3;
                LDSM_X4T(b0, b1, b2, b3, vst + (uint32_t)(kc * 16 * ROWB) + p * 32);
                MMA_BF16(o[2 * p],     a, b0, b1);
                MMA_BF16(o[2 * p + 1], a, b2, b3);
            }
        }
        __syncthreads();
    }

    float inv0 = 1.0f / lsum[0], inv1 = 1.0f / lsum[1];
    int r0 = qt * 64 + rbase + g;
    #pragma unroll
    for (int nt = 0; nt < 8; nt++) {
        int col = h * 64 + nt * 8 + 2 * qd;
        *(uint32_t*)(out + (size_t)(b * L_ + r0    ) * D_ + col) = packbf(o[nt][0] * inv0, o[nt][1] * inv0);
        *(uint32_t*)(out + (size_t)(b * L_ + r0 + 8) * D_ + col) = packbf(o[nt][2] * inv1, o[nt][3] * inv1);
    }
}

// ============ launch ============
extern "C" void kernel_launch(void* const* d_in, const int* in_sizes, int n_in,
                              void* d_out, int out_size) {
    const float* x     = (const float*)d_in[0];
    const float* tsb   = (const float*)d_in[1];
    const float* mask  = (const float*)d_in[2];
    const float* ln1_g = (const float*)d_in[3];
    const float* ln1_b = (const float*)d_in[4];
    const float* w_qkv = (const float*)d_in[5];
    const float* w_out = (const float*)d_in[6];
    const float* decay = (const float*)d_in[7];
    const float* ln2_g = (const float*)d_in[8];
    const float* ln2_b = (const float*)d_in[9];
    const float* w_ff1 = (const float*)d_in[10];
    const float* w_ff2 = (const float*)d_in[11];
    float* out = (float*)d_out;

    __nv_bfloat16 *xn, *q, *k, *v, *att, *hh, *ff, *w0, *w1, *w2, *w3;
    float *x1;
    cudaGetSymbolAddress((void**)&xn, g_xn);
    cudaGetSymbolAddress((void**)&q, g_q);
    cudaGetSymbolAddress((void**)&k, g_k);
    cudaGetSymbolAddress((void**)&v, g_v);
    cudaGetSymbolAddress((void**)&att, g_att);
    cudaGetSymbolAddress((void**)&x1, g_x1);
    cudaGetSymbolAddress((void**)&hh, g_h);
    cudaGetSymbolAddress((void**)&ff, g_ff);
    cudaGetSymbolAddress((void**)&w0, g_w0);
    cudaGetSymbolAddress((void**)&w1, g_w1);
    cudaGetSymbolAddress((void**)&w2, g_w2);
    cudaGetSymbolAddress((void**)&w3, g_w3);

    cudaFuncSetAttribute(mma_gemm, cudaFuncAttributeMaxDynamicSharedMemorySize, GEMM_SMEM_B);
    cudaFuncSetAttribute(attn_kernel, cudaFuncAttributeMaxDynamicSharedMemorySize, ATTN_SMEM_B);

    const int n_total = 3 * D_ * D_ + D_ * D_ + FF_ * D_ + D_ * FF_;
    round_all_kernel<<<n_total / 1024, 256>>>(w_qkv, w0, w_out, w1, w_ff1, w2, w_ff2, w3);

    ln_kernel<<<BL_, 256>>>(x, ln1_g, ln1_b, xn);
    mma_gemm<<<dim3(1536 / 128, BL_ / 128), 256, GEMM_SMEM_B>>>(
        xn, w0, D_, 1536, MODE_QKV, nullptr, nullptr, nullptr, q, k, v);
    attn_kernel<<<dim3(L_ / 64, B_ * H_), 128, ATTN_SMEM_B>>>(
        q, k, v, tsb, mask, decay, att);
    mma_gemm<<<dim3(D_ / 128, BL_ / 128), 256, GEMM_SMEM_B>>>(
        att, w1, D_, D_, MODE_RESID, x, x1, nullptr, nullptr, nullptr, nullptr);
    ln_kernel<<<BL_, 256>>>(x1, ln2_g, ln2_b, hh);
    mma_gemm<<<dim3(FF_ / 128, BL_ / 128), 256, GEMM_SMEM_B>>>(
        hh, w2, D_, FF_, MODE_SILU, nullptr, nullptr, ff, nullptr, nullptr, nullptr);
    mma_gemm<<<dim3(D_ / 128, BL_ / 128), 256, GEMM_SMEM_B>>>(
        ff, w3, FF_, D_, MODE_RESID, x1, out, nullptr, nullptr, nullptr, nullptr);
}

// round 12
// speedup vs baseline: 7.4145x; 1.0600x over previous
#include <cuda_runtime.h>
#include <cuda_bf16.h>
#include <math.h>
#include <stdint.h>

#define B_  2
#define L_  4096
#define D_  512
#define H_  8
#define DH_ 64
#define BL_ 8192
#define FF_ 2048

// ---------------- scratch ----------------
__device__ __nv_bfloat16 g_xn [BL_ * D_];
__device__ __nv_bfloat16 g_q [B_ * H_ * L_ * DH_];
__device__ __nv_bfloat16 g_k [B_ * H_ * L_ * DH_];
__device__ __nv_bfloat16 g_v [B_ * H_ * L_ * DH_];
__device__ __nv_bfloat16 g_att[BL_ * D_];
__device__ float g_x1 [BL_ * D_];
__device__ __nv_bfloat16 g_h  [BL_ * D_];
__device__ __nv_bfloat16 g_ff [BL_ * FF_];
__device__ __nv_bfloat16 g_w0 [3 * D_ * D_];
__device__ __nv_bfloat16 g_w1 [D_ * D_];
__device__ __nv_bfloat16 g_w2 [FF_ * D_];
__device__ __nv_bfloat16 g_w3 [D_ * FF_];

__device__ __forceinline__ float exp2fast(float x) {
    float r;
    asm("ex2.approx.f32 %0, %1;" : "=f"(r) : "f"(x));
    return r;
}
__device__ __forceinline__ uint32_t packbf(float lo, float hi) {
    uint32_t r;
    asm("cvt.rn.bf16x2.f32 %0, %1, %2;" : "=r"(r) : "f"(hi), "f"(lo));
    return r;
}

#define MMA_BF16(d, a, b0, b1)                                               \
    asm volatile(                                                            \
        "mma.sync.aligned.m16n8k16.row.col.f32.bf16.bf16.f32 "               \
        "{%0,%1,%2,%3}, {%4,%5,%6,%7}, {%8,%9}, {%0,%1,%2,%3};"              \
        : "+f"(d[0]), "+f"(d[1]), "+f"(d[2]), "+f"(d[3])                     \
        : "r"(a[0]), "r"(a[1]), "r"(a[2]), "r"(a[3]), "r"(b0), "r"(b1))

#define LDSM_X4(r0, r1, r2, r3, addr)                                        \
    asm volatile("ldmatrix.sync.aligned.m8n8.x4.shared.b16 {%0,%1,%2,%3}, [%4];" \
        : "=r"(r0), "=r"(r1), "=r"(r2), "=r"(r3) : "r"(addr))

#define LDSM_X4T(r0, r1, r2, r3, addr)                                       \
    asm volatile("ldmatrix.sync.aligned.m8n8.x4.trans.shared.b16 {%0,%1,%2,%3}, [%4];" \
        : "=r"(r0), "=r"(r1), "=r"(r2), "=r"(r3) : "r"(addr))

// ============ weight conversion fp32 -> bf16 ============
__global__ __launch_bounds__(256) void round_all_kernel(
    const float* __restrict__ s0, __nv_bfloat16* __restrict__ d0,
    const float* __restrict__ s1, __nv_bfloat16* __restrict__ d1,
    const float* __restrict__ s2, __nv_bfloat16* __restrict__ d2,
    const float* __restrict__ s3, __nv_bfloat16* __restrict__ d3)
{
    const int n0 = 3 * D_ * D_, n1 = D_ * D_, n2 = FF_ * D_;
    int i = (blockIdx.x * 256 + threadIdx.x) * 4;
    const float* src; __nv_bfloat16* dst; int off;
    if (i < n0)                { src = s0; dst = d0; off = i; }
    else if (i < n0 + n1)      { src = s1; dst = d1; off = i - n0; }
    else if (i < n0 + n1 + n2) { src = s2; dst = d2; off = i - n0 - n1; }
    else                       { src = s3; dst = d3; off = i - n0 - n1 - n2; }
    float4 v = *(const float4*)(src + off);
    uint2 o;
    o.x = packbf(v.x, v.y);
    o.y = packbf(v.z, v.w);
    *(uint2*)(dst + off) = o;
}

// ============ LayerNorm (bf16 output) ============
__global__ __launch_bounds__(256) void ln_kernel(const float* __restrict__ x,
                                                 const float* __restrict__ g,
                                                 const float* __restrict__ b,
                                                 __nv_bfloat16* __restrict__ y) {
    int row = blockIdx.x;
    const float* xr = x + (size_t)row * D_;
    __nv_bfloat16* yr = y + (size_t)row * D_;
    int tid = threadIdx.x;
    float v0 = xr[tid], v1 = xr[tid + 256];
    float s = v0 + v1, ss = v0 * v0 + v1 * v1;
    #pragma unroll
    for (int o = 16; o > 0; o >>= 1) {
        s  += __shfl_xor_sync(0xffffffffu, s,  o);
        ss += __shfl_xor_sync(0xffffffffu, ss, o);
    }
    __shared__ float red[16];
    int w = tid >> 5, lane = tid & 31;
    if (lane == 0) { red[w] = s; red[w + 8] = ss; }
    __syncthreads();
    float S = 0.f, SS = 0.f;
    #pragma unroll
    for (int i = 0; i < 8; i++) { S += red[i]; SS += red[i + 8]; }
    float mu = S * (1.0f / D_);
    float inv = rsqrtf(SS * (1.0f / D_) - mu * mu + 1e-5f);
    yr[tid]       = __float2bfloat16((v0 - mu) * inv * g[tid]       + b[tid]);
    yr[tid + 256] = __float2bfloat16((v1 - mu) * inv * g[tid + 256] + b[tid + 256]);
}

// ============ bf16 mma GEMM: 4-stage, wait -> sync -> issue -> compute ============
#define ROWG 80
#define STG_B (128 * ROWG)
#define STAGE_B (2 * STG_B)
#define GEMM_SMEM_B (4 * STAGE_B)
#define MODE_QKV   0
#define MODE_RESID 1
#define MODE_SILU  2

__global__ __launch_bounds__(256, 2) void mma_gemm(
    const __nv_bfloat16* __restrict__ A, const __nv_bfloat16* __restrict__ W,
    int K, int N, int mode, const float* __restrict__ resid,
    float* __restrict__ out, __nv_bfloat16* __restrict__ outb,
    __nv_bfloat16* __restrict__ oq, __nv_bfloat16* __restrict__ okk,
    __nv_bfloat16* __restrict__ ov)
{
    extern __shared__ char smg[];
    uint32_t sbase = (uint32_t)__cvta_generic_to_shared(smg);
    int tid = threadIdx.x;
    int wid = tid >> 5, lane = tid & 31;
    int wm = wid & 1, wn = wid >> 1;
    int g = lane >> 2, qd = lane & 3;
    int bm = blockIdx.y, bn = blockIdx.x;
    const __nv_bfloat16* Ab = A + (size_t)bm * 128 * K;
    const __nv_bfloat16* Wb = W + (size_t)bn * 128 * K;
    const int NC = K >> 5;

    int arow = wm * 64 + (lane & 7) + ((lane >> 3) & 1) * 8;
    int acol = (lane >> 4) * 16;
    int wrow = wn * 32 + (lane & 7) + ((lane >> 4) & 1) * 8;
    int wcol = ((lane >> 3) & 1) * 16;

    float acc[4][4][4];
    #pragma unroll
    for (int i = 0; i < 4; i++)
        #pragma unroll
        for (int j = 0; j < 4; j++)
            #pragma unroll
            for (int e = 0; e < 4; e++) acc[i][j][e] = 0.f;

    auto load_stage = [&](int c, int st) {
        int k0 = c << 5;
        #pragma unroll
        for (int i = 0; i < 2; i++) {
            int idx = tid + i * 256;
            int r = idx >> 2, cb = idx & 3;
            uint32_t da = sbase + (uint32_t)(st * STAGE_B + r * ROWG + cb * 16);
            asm volatile("cp.async.cg.shared.global [%0], [%1], 16;"
                         :: "r"(da), "l"(Ab + (size_t)r * K + k0 + cb * 8) : "memory");
            asm volatile("cp.async.cg.shared.global [%0], [%1], 16;"
                         :: "r"(da + STG_B), "l"(Wb + (size_t)r * K + k0 + cb * 8) : "memory");
        }
        asm volatile("cp.async.commit_group;" ::: "memory");
    };

    load_stage(0, 0); load_stage(1, 1); load_stage(2, 2);

    for (int c = 0; c < NC; c++) {
        int rem = NC - 1 - c;
        if (rem >= 2)      asm volatile("cp.async.wait_group 2;" ::: "memory");
        else if (rem == 1) asm volatile("cp.async.wait_group 1;" ::: "memory");
        else               asm volatile("cp.async.wait_group 0;" ::: "memory");
        __syncthreads();                         // publish group c; all done reading (c-1)&3
        if (c + 3 < NC) load_stage(c + 3, (c + 3) & 3);

        uint32_t abase = sbase + (uint32_t)((c & 3) * STAGE_B);
        uint32_t wbase = abase + STG_B;
        #pragma unroll
        for (int kc = 0; kc < 2; kc++) {
            uint32_t a[4][4], bfr[2][4];
            #pragma unroll
            for (int mt = 0; mt < 4; mt++)
                LDSM_X4(a[mt][0], a[mt][1], a[mt][2], a[mt][3],
                        abase + (uint32_t)((arow + mt * 16) * ROWG + acol + kc * 32));
            #pragma unroll
            for (int t = 0; t < 2; t++)
                LDSM_X4(bfr[t][0], bfr[t][1], bfr[t][2], bfr[t][3],
                        wbase + (uint32_t)((wrow + t * 16) * ROWG + wcol + kc * 32));
            #pragma unroll
            for (int mt = 0; mt < 4; mt++)
                #pragma unroll
                for (int t = 0; t < 2; t++) {
                    MMA_BF16(acc[mt][2 * t],     a[mt], bfr[t][0], bfr[t][1]);
                    MMA_BF16(acc[mt][2 * t + 1], a[mt], bfr[t][2], bfr[t][3]);
                }
        }
    }

    #pragma unroll
    for (int mt = 0; mt < 4; mt++) {
        #pragma unroll
        for (int nt = 0; nt < 4; nt++) {
            int cb = bn * 128 + wn * 32 + nt * 8 + 2 * qd;
            #pragma unroll
            for (int hi = 0; hi < 2; hi++) {
                int r = bm * 128 + wm * 64 + mt * 16 + g + hi * 8;
                float v0 = acc[mt][nt][hi * 2], v1 = acc[mt][nt][hi * 2 + 1];
                if (mode == MODE_QKV) {
                    int which = cb >> 9, h = (cb >> 6) & 7, d0 = cb & 63;
                    int bb = r >> 12, l = r & 4095;
                    __nv_bfloat16* dst = (which == 0) ? oq : (which == 1) ? okk : ov;
                    *(uint32_t*)(dst + (((size_t)bb * H_ + h) * L_ + l) * DH_ + d0) = packbf(v0, v1);
                } else if (mode == MODE_RESID) {
                    size_t idx = (size_t)r * N + cb;
                    float2 rv = *(const float2*)(resid + idx);
                    float2 o2 = {rv.x + v0, rv.y + v1};
                    *(float2*)(out + idx) = o2;
                } else {
                    size_t idx = (size_t)r * N + cb;
                    float a0 = v0 / (1.0f + __expf(-v0));
                    float a1 = v1 / (1.0f + __expf(-v1));
                    *(uint32_t*)(outb + idx) = packbf(a0, a1);
                }
            }
        }
    }
}

// ============ flash attention: 64-row Q, 128 thr, 4 CTA/SM ============
#define KSB 72
#define ROWB (KSB * 2)
#define OQ_B   0
#define OK_B   (64 * ROWB)
#define OV_B   (OK_B + 2 * 64 * ROWB)
#define OCB_B  (OV_B + 2 * 64 * ROWB)
#define ATTN_SMEM_B (OCB_B + 2 * 64 * 4)

__global__ __launch_bounds__(128, 4) void attn_kernel(
    const __nv_bfloat16* __restrict__ q, const __nv_bfloat16* __restrict__ k,
    const __nv_bfloat16* __restrict__ v, const float* __restrict__ ts,
    const float* __restrict__ mask, const float* __restrict__ decay_rate,
    __nv_bfloat16* __restrict__ out)
{
    extern __shared__ char smc[];
    uint32_t smb = (uint32_t)__cvta_generic_to_shared(smc);
    float* colb = (float*)(smc + OCB_B);

    int qt = gridDim.x - 1 - blockIdx.x;
    int bh = blockIdx.y, b = bh >> 3, h = bh & 7;
    int tid = threadIdx.x, wid = tid >> 5, lane = tid & 31;
    int g = lane >> 2, qd = lane & 3;
    int rbase = wid * 16;
    const int nkt = qt + 1;

    uint32_t qaddr = smb + OQ_B + (uint32_t)(rbase + (lane & 7) + ((lane >> 3) & 1) * 8) * ROWB
                   + (uint32_t)(lane >> 4) * 16;
    uint32_t kaddr = smb + OK_B + (uint32_t)((lane & 7) + ((lane >> 4) & 1) * 8) * ROWB
                   + (uint32_t)((lane >> 3) & 1) * 16;
    uint32_t vaddr = smb + OV_B + (uint32_t)((lane & 7) + ((lane >> 3) & 1) * 8) * ROWB
                   + (uint32_t)(lane >> 4) * 16;

    const __nv_bfloat16* qb = q + ((size_t)bh * L_ + qt * 64) * DH_;
    #pragma unroll
    for (int i = 0; i < 4; i++) {
        int idx = tid + i * 128;
        int r = idx >> 3, c8 = (idx & 7) << 3;
        *(uint4*)(smc + OQ_B + r * ROWB + c8 * 2) = *(const uint4*)(qb + (size_t)r * DH_ + c8);
    }

    const float LOG2E = 1.44269504f;
    float scale2 = 0.125f * LOG2E;
    float dcy2 = log1pf(__expf(decay_rate[h])) * (LOG2E / 24.0f);
    float mprev[2] = {-1e30f, -1e30f};
    float lsum[2] = {0.f, 0.f};
    float o[8][4];
    #pragma unroll
    for (int i = 0; i < 8; i++)
        #pragma unroll
        for (int e = 0; e < 4; e++) o[i][e] = 0.f;

    auto load_kv = [&](int jt, int st) {
        const __nv_bfloat16* kb = k + ((size_t)bh * L_ + jt * 64) * DH_;
        const __nv_bfloat16* vb = v + ((size_t)bh * L_ + jt * 64) * DH_;
        uint32_t kdst = smb + OK_B + (uint32_t)st * 64 * ROWB;
        uint32_t vdst = smb + OV_B + (uint32_t)st * 64 * ROWB;
        #pragma unroll
        for (int i = 0; i < 4; i++) {
            int idx = tid + i * 128;
            int r = idx >> 3, c8 = (idx & 7) << 3;
            asm volatile("cp.async.cg.shared.global [%0], [%1], 16;"
                         :: "r"(kdst + (uint32_t)(r * ROWB + c8 * 2)),
                            "l"(kb + (size_t)r * DH_ + c8) : "memory");
            asm volatile("cp.async.cg.shared.global [%0], [%1], 16;"
                         :: "r"(vdst + (uint32_t)(r * ROWB + c8 * 2)),
                            "l"(vb + (size_t)r * DH_ + c8) : "memory");
        }
        asm volatile("cp.async.commit_group;" ::: "memory");
        if (tid < 64) {
            float t = ts[b * L_ + jt * 64 + tid];
            float m = mask[b * L_ + jt * 64 + tid];
            colb[st * 64 + tid] = (m != 0.f) ? dcy2 * t : -3e38f;
        }
    };

    load_kv(0, 0);

    for (int jt = 0; jt < nkt; jt++) {
        int st = jt & 1;
        asm volatile("cp.async.wait_group 0;" ::: "memory");  // own group jt done
        __syncthreads();                                      // publish + all done reading other slot
        if (jt + 1 < nkt) load_kv(jt + 1, (jt + 1) & 1);

        uint32_t kst = kaddr + (uint32_t)st * 64 * ROWB;
        uint32_t vst = vaddr + (uint32_t)st * 64 * ROWB;
        const float* cbs = colb + st * 64;
        bool diag = (jt == qt);

        // ---- S = Q K^T ----
        float s[8][4];
        #pragma unroll
        for (int i = 0; i < 8; i++)
            #pragma unroll
            for (int e = 0; e < 4; e++) s[i][e] = 0.f;
        #pragma unroll
        for (int ks = 0; ks < 4; ks++) {
            uint32_t qa0, qa1, qa2, qa3;
            LDSM_X4(qa0, qa1, qa2, qa3, qaddr + ks * 32);
            uint32_t a[4] = {qa0, qa1, qa2, qa3};
            #pragma unroll
            for (int p = 0; p < 4; p++) {
                uint32_t b0, b1, b2, b3;
                LDSM_X4(b0, b1, b2, b3, kst + (uint32_t)(p * 16 * ROWB) + ks * 32);
                MMA_BF16(s[2 * p],     a, b0, b1);
                MMA_BF16(s[2 * p + 1], a, b2, b3);
            }
        }

        // ---- bias + causal ----
        int qi0 = qt * 64 + rbase + g;
        #pragma unroll
        for (int nt = 0; nt < 8; nt++) {
            float2 cb2 = *(const float2*)(cbs + nt * 8 + 2 * qd);
            s[nt][0] = fmaf(s[nt][0], scale2, cb2.x);
            s[nt][1] = fmaf(s[nt][1], scale2, cb2.y);
            s[nt][2] = fmaf(s[nt][2], scale2, cb2.x);
            s[nt][3] = fmaf(s[nt][3], scale2, cb2.y);
            if (diag) {
                int colbase = jt * 64 + nt * 8 + 2 * qd;
                if (colbase     > qi0)     s[nt][0] = -3e38f;
                if (colbase + 1 > qi0)     s[nt][1] = -3e38f;
                if (colbase     > qi0 + 8) s[nt][2] = -3e38f;
                if (colbase + 1 > qi0 + 8) s[nt][3] = -3e38f;
            }
        }

        // ---- online softmax ----
        float rmax[2] = {-1e30f, -1e30f};
        #pragma unroll
        for (int nt = 0; nt < 8; nt++) {
            rmax[0] = fmaxf(rmax[0], fmaxf(s[nt][0], s[nt][1]));
            rmax[1] = fmaxf(rmax[1], fmaxf(s[nt][2], s[nt][3]));
        }
        #pragma unroll
        for (int off = 1; off < 4; off <<= 1) {
            rmax[0] = fmaxf(rmax[0], __shfl_xor_sync(0xffffffffu, rmax[0], off));
            rmax[1] = fmaxf(rmax[1], __shfl_xor_sync(0xffffffffu, rmax[1], off));
        }
        float mnew[2], fac[2];
        float psA[2] = {0.f, 0.f}, psB[2] = {0.f, 0.f};
        #pragma unroll
        for (int hi = 0; hi < 2; hi++) {
            mnew[hi] = fmaxf(mprev[hi], rmax[hi]);
            fac[hi]  = exp2fast(mprev[hi] - mnew[hi]);
        }
        #pragma unroll
        for (int nt = 0; nt < 8; nt++) {
            float p0 = exp2fast(s[nt][0] - mnew[0]);
            float p1 = exp2fast(s[nt][1] - mnew[0]);
            float p2 = exp2fast(s[nt][2] - mnew[1]);
            float p3 = exp2fast(s[nt][3] - mnew[1]);
            if (nt & 1) { psB[0] += p0 + p1; psB[1] += p2 + p3; }
            else        { psA[0] += p0 + p1; psA[1] += p2 + p3; }
            s[nt][0] = p0; s[nt][1] = p1; s[nt][2] = p2; s[nt][3] = p3;
        }
        float ps[2] = {psA[0] + psB[0], psA[1] + psB[1]};
        #pragma unroll
        for (int off = 1; off < 4; off <<= 1) {
            ps[0] += __shfl_xor_sync(0xffffffffu, ps[0], off);
            ps[1] += __shfl_xor_sync(0xffffffffu, ps[1], off);
        }
        #pragma unroll
        for (int hi = 0; hi < 2; hi++) {
            lsum[hi] = lsum[hi] * fac[hi] + ps[hi];
            mprev[hi] = mnew[hi];
        }
        #pragma unroll
        for (int nt = 0; nt < 8; nt++) {
            o[nt][0] *= fac[0]; o[nt][1] *= fac[0];
            o[nt][2] *= fac[1]; o[nt][3] *= fac[1];
        }

        // ---- O += P V ----
        #pragma unroll
        for (int kc = 0; kc < 4; kc++) {
            uint32_t a[4];
            a[0] = packbf(s[2 * kc][0],     s[2 * kc][1]);
            a[1] = packbf(s[2 * kc][2],     s[2 * kc][3]);
            a[2] = packbf(s[2 * kc + 1][0], s[2 * kc + 1][1]);
            a[3] = packbf(s[2 * kc + 1][2], s[2 * kc + 1][3]);
            #pragma unroll
            for (int p = 0; p < 4; p++) {
                uint32_t b0, b1, b2, b3;
                LDSM_X4T(b0, b1, b2, b3, vst + (uint32_t)(kc * 16 * ROWB) + p * 32);
                MMA_BF16(o[2 * p],     a, b0, b1);
                MMA_BF16(o[2 * p + 1], a, b2, b3);
            }
        }
    }

    float inv0 = 1.0f / lsum[0], inv1 = 1.0f / lsum[1];
    int r0 = qt * 64 + rbase + g;
    #pragma unroll
    for (int nt = 0; nt < 8; nt++) {
        int col = h * 64 + nt * 8 + 2 * qd;
        *(uint32_t*)(out + (size_t)(b * L_ + r0    ) * D_ + col) = packbf(o[nt][0] * inv0, o[nt][1] * inv0);
        *(uint32_t*)(out + (size_t)(b * L_ + r0 + 8) * D_ + col) = packbf(o[nt][2] * inv1, o[nt][3] * inv1);
    }
}

// ============ launch ============
extern "C" void kernel_launch(void* const* d_in, const int* in_sizes, int n_in,
                              void* d_out, int out_size) {
    const float* x     = (const float*)d_in[0];
    const float* tsb   = (const float*)d_in[1];
    const float* mask  = (const float*)d_in[2];
    const float* ln1_g = (const float*)d_in[3];
    const float* ln1_b = (const float*)d_in[4];
    const float* w_qkv = (const float*)d_in[5];
    const float* w_out = (const float*)d_in[6];
    const float* decay = (const float*)d_in[7];
    const float* ln2_g = (const float*)d_in[8];
    const float* ln2_b = (const float*)d_in[9];
    const float* w_ff1 = (const float*)d_in[10];
    const float* w_ff2 = (const float*)d_in[11];
    float* out = (float*)d_out;

    __nv_bfloat16 *xn, *q, *k, *v, *att, *hh, *ff, *w0, *w1, *w2, *w3;
    float *x1;
    cudaGetSymbolAddress((void**)&xn, g_xn);
    cudaGetSymbolAddress((void**)&q, g_q);
    cudaGetSymbolAddress((void**)&k, g_k);
    cudaGetSymbolAddress((void**)&v, g_v);
    cudaGetSymbolAddress((void**)&att, g_att);
    cudaGetSymbolAddress((void**)&x1, g_x1);
    cudaGetSymbolAddress((void**)&hh, g_h);
    cudaGetSymbolAddress((void**)&ff, g_ff);
    cudaGetSymbolAddress((void**)&w0, g_w0);
    cudaGetSymbolAddress((void**)&w1, g_w1);
    cudaGetSymbolAddress((void**)&w2, g_w2);
    cudaGetSymbolAddress((void**)&w3, g_w3);

    cudaFuncSetAttribute(mma_gemm, cudaFuncAttributeMaxDynamicSharedMemorySize, GEMM_SMEM_B);
    cudaFuncSetAttribute(attn_kernel, cudaFuncAttributeMaxDynamicSharedMemorySize, ATTN_SMEM_B);

    const int n_total = 3 * D_ * D_ + D_ * D_ + FF_ * D_ + D_ * FF_;
    round_all_kernel<<<n_total / 1024, 256>>>(w_qkv, w0, w_out, w1, w_ff1, w2, w_ff2, w3);

    ln_kernel<<<BL_, 256>>>(x, ln1_g, ln1_b, xn);
    mma_gemm<<<dim3(1536 / 128, BL_ / 128), 256, GEMM_SMEM_B>>>(
        xn, w0, D_, 1536, MODE_QKV, nullptr, nullptr, nullptr, q, k, v);
    attn_kernel<<<dim3(L_ / 64, B_ * H_), 128, ATTN_SMEM_B>>>(
        q, k, v, tsb, mask, decay, att);
    mma_gemm<<<dim3(D_ / 128, BL_ / 128), 256, GEMM_SMEM_B>>>(
        att, w1, D_, D_, MODE_RESID, x, x1, nullptr, nullptr, nullptr, nullptr);
    ln_kernel<<<BL_, 256>>>(x1, ln2_g, ln2_b, hh);
    mma_gemm<<<dim3(FF_ / 128, BL_ / 128), 256, GEMM_SMEM_B>>>(
        hh, w2, D_, FF_, MODE_SILU, nullptr, nullptr, ff, nullptr, nullptr, nullptr);
    mma_gemm<<<dim3(D_ / 128, BL_ / 128), 256, GEMM_SMEM_B>>>(
        ff, w3, FF_, D_, MODE_RESID, x1, out, nullptr, nullptr, nullptr, nullptr);
}

// round 13
// speedup vs baseline: 7.4458x; 1.0042x over previous
#include <cuda_runtime.h>
#include <cuda_bf16.h>
#include <math.h>
#include <stdint.h>

#define B_  2
#define L_  4096
#define D_  512
#define H_  8
#define DH_ 64
#define BL_ 8192
#define FF_ 2048

// ---------------- scratch ----------------
__device__ __nv_bfloat16 g_xn [BL_ * D_];
__device__ __nv_bfloat16 g_q [B_ * H_ * L_ * DH_];
__device__ __nv_bfloat16 g_k [B_ * H_ * L_ * DH_];
__device__ __nv_bfloat16 g_v [B_ * H_ * L_ * DH_];
__device__ __nv_bfloat16 g_att[BL_ * D_];
__device__ float g_x1 [BL_ * D_];
__device__ __nv_bfloat16 g_h  [BL_ * D_];
__device__ __nv_bfloat16 g_ff [BL_ * FF_];
__device__ __nv_bfloat16 g_w0 [3 * D_ * D_];
__device__ __nv_bfloat16 g_w1 [D_ * D_];
__device__ __nv_bfloat16 g_w2 [FF_ * D_];
__device__ __nv_bfloat16 g_w3 [D_ * FF_];

__device__ __forceinline__ float exp2fast(float x) {
    float r;
    asm("ex2.approx.f32 %0, %1;" : "=f"(r) : "f"(x));
    return r;
}
__device__ __forceinline__ uint32_t packbf(float lo, float hi) {
    uint32_t r;
    asm("cvt.rn.bf16x2.f32 %0, %1, %2;" : "=r"(r) : "f"(hi), "f"(lo));
    return r;
}

#define MMA_BF16(d, a, b0, b1)                                               \
    asm volatile(                                                            \
        "mma.sync.aligned.m16n8k16.row.col.f32.bf16.bf16.f32 "               \
        "{%0,%1,%2,%3}, {%4,%5,%6,%7}, {%8,%9}, {%0,%1,%2,%3};"              \
        : "+f"(d[0]), "+f"(d[1]), "+f"(d[2]), "+f"(d[3])                     \
        : "r"(a[0]), "r"(a[1]), "r"(a[2]), "r"(a[3]), "r"(b0), "r"(b1))

#define LDSM_X4(r0, r1, r2, r3, addr)                                        \
    asm volatile("ldmatrix.sync.aligned.m8n8.x4.shared.b16 {%0,%1,%2,%3}, [%4];" \
        : "=r"(r0), "=r"(r1), "=r"(r2), "=r"(r3) : "r"(addr))

#define LDSM_X4T(r0, r1, r2, r3, addr)                                       \
    asm volatile("ldmatrix.sync.aligned.m8n8.x4.trans.shared.b16 {%0,%1,%2,%3}, [%4];" \
        : "=r"(r0), "=r"(r1), "=r"(r2), "=r"(r3) : "r"(addr))

// ============ fused prep: weight conversion + LN1 ============
#define NW_BLOCKS ((3 * D_ * D_ + D_ * D_ + FF_ * D_ + D_ * FF_) / 1024)

__global__ __launch_bounds__(256) void prep_kernel(
    const float* __restrict__ s0, __nv_bfloat16* __restrict__ d0,
    const float* __restrict__ s1, __nv_bfloat16* __restrict__ d1,
    const float* __restrict__ s2, __nv_bfloat16* __restrict__ d2,
    const float* __restrict__ s3, __nv_bfloat16* __restrict__ d3,
    const float* __restrict__ x, const float* __restrict__ lg,
    const float* __restrict__ lb, __nv_bfloat16* __restrict__ y)
{
    if (blockIdx.x < NW_BLOCKS) {
        const int n0 = 3 * D_ * D_, n1 = D_ * D_, n2 = FF_ * D_;
        int i = (blockIdx.x * 256 + threadIdx.x) * 4;
        const float* src; __nv_bfloat16* dst; int off;
        if (i < n0)                { src = s0; dst = d0; off = i; }
        else if (i < n0 + n1)      { src = s1; dst = d1; off = i - n0; }
        else if (i < n0 + n1 + n2) { src = s2; dst = d2; off = i - n0 - n1; }
        else                       { src = s3; dst = d3; off = i - n0 - n1 - n2; }
        float4 v = *(const float4*)(src + off);
        uint2 o;
        o.x = packbf(v.x, v.y);
        o.y = packbf(v.z, v.w);
        *(uint2*)(dst + off) = o;
        return;
    }
    // LayerNorm rows
    int row = blockIdx.x - NW_BLOCKS;
    const float* xr = x + (size_t)row * D_;
    __nv_bfloat16* yr = y + (size_t)row * D_;
    int tid = threadIdx.x;
    float v0 = xr[tid], v1 = xr[tid + 256];
    float s = v0 + v1, ss = v0 * v0 + v1 * v1;
    #pragma unroll
    for (int o = 16; o > 0; o >>= 1) {
        s  += __shfl_xor_sync(0xffffffffu, s,  o);
        ss += __shfl_xor_sync(0xffffffffu, ss, o);
    }
    __shared__ float red[16];
    int w = tid >> 5, lane = tid & 31;
    if (lane == 0) { red[w] = s; red[w + 8] = ss; }
    __syncthreads();
    float S = 0.f, SS = 0.f;
    #pragma unroll
    for (int i = 0; i < 8; i++) { S += red[i]; SS += red[i + 8]; }
    float mu = S * (1.0f / D_);
    float inv = rsqrtf(SS * (1.0f / D_) - mu * mu + 1e-5f);
    yr[tid]       = __float2bfloat16((v0 - mu) * inv * lg[tid]       + lb[tid]);
    yr[tid + 256] = __float2bfloat16((v1 - mu) * inv * lg[tid + 256] + lb[tid + 256]);
}

// ============ LayerNorm (standalone, for LN2) ============
__global__ __launch_bounds__(256) void ln_kernel(const float* __restrict__ x,
                                                 const float* __restrict__ g,
                                                 const float* __restrict__ b,
                                                 __nv_bfloat16* __restrict__ y) {
    int row = blockIdx.x;
    const float* xr = x + (size_t)row * D_;
    __nv_bfloat16* yr = y + (size_t)row * D_;
    int tid = threadIdx.x;
    float v0 = xr[tid], v1 = xr[tid + 256];
    float s = v0 + v1, ss = v0 * v0 + v1 * v1;
    #pragma unroll
    for (int o = 16; o > 0; o >>= 1) {
        s  += __shfl_xor_sync(0xffffffffu, s,  o);
        ss += __shfl_xor_sync(0xffffffffu, ss, o);
    }
    __shared__ float red[16];
    int w = tid >> 5, lane = tid & 31;
    if (lane == 0) { red[w] = s; red[w + 8] = ss; }
    __syncthreads();
    float S = 0.f, SS = 0.f;
    #pragma unroll
    for (int i = 0; i < 8; i++) { S += red[i]; SS += red[i + 8]; }
    float mu = S * (1.0f / D_);
    float inv = rsqrtf(SS * (1.0f / D_) - mu * mu + 1e-5f);
    yr[tid]       = __float2bfloat16((v0 - mu) * inv * g[tid]       + b[tid]);
    yr[tid + 256] = __float2bfloat16((v1 - mu) * inv * g[tid + 256] + b[tid + 256]);
}

// ============ bf16 mma GEMM: 4-stage, double-buffered fragments ============
#define ROWG 80
#define STG_B (128 * ROWG)
#define STAGE_B (2 * STG_B)
#define GEMM_SMEM_B (4 * STAGE_B)
#define MODE_QKV   0
#define MODE_RESID 1
#define MODE_SILU  2

__global__ __launch_bounds__(256, 2) void mma_gemm(
    const __nv_bfloat16* __restrict__ A, const __nv_bfloat16* __restrict__ W,
    int K, int N, int mode, const float* __restrict__ resid,
    float* __restrict__ out, __nv_bfloat16* __restrict__ outb,
    __nv_bfloat16* __restrict__ oq, __nv_bfloat16* __restrict__ okk,
    __nv_bfloat16* __restrict__ ov)
{
    extern __shared__ char smg[];
    uint32_t sbase = (uint32_t)__cvta_generic_to_shared(smg);
    int tid = threadIdx.x;
    int wid = tid >> 5, lane = tid & 31;
    int wm = wid & 1, wn = wid >> 1;
    int g = lane >> 2, qd = lane & 3;
    int bm = blockIdx.y, bn = blockIdx.x;
    const __nv_bfloat16* Ab = A + (size_t)bm * 128 * K;
    const __nv_bfloat16* Wb = W + (size_t)bn * 128 * K;
    const int NC = K >> 5;

    int arow = wm * 64 + (lane & 7) + ((lane >> 3) & 1) * 8;
    int acol = (lane >> 4) * 16;
    int wrow = wn * 32 + (lane & 7) + ((lane >> 4) & 1) * 8;
    int wcol = ((lane >> 3) & 1) * 16;

    float acc[4][4][4];
    #pragma unroll
    for (int i = 0; i < 4; i++)
        #pragma unroll
        for (int j = 0; j < 4; j++)
            #pragma unroll
            for (int e = 0; e < 4; e++) acc[i][j][e] = 0.f;

    auto load_stage = [&](int c, int st) {
        int k0 = c << 5;
        #pragma unroll
        for (int i = 0; i < 2; i++) {
            int idx = tid + i * 256;
            int r = idx >> 2, cb = idx & 3;
            uint32_t da = sbase + (uint32_t)(st * STAGE_B + r * ROWG + cb * 16);
            asm volatile("cp.async.cg.shared.global [%0], [%1], 16;"
                         :: "r"(da), "l"(Ab + (size_t)r * K + k0 + cb * 8) : "memory");
            asm volatile("cp.async.cg.shared.global [%0], [%1], 16;"
                         :: "r"(da + STG_B), "l"(Wb + (size_t)r * K + k0 + cb * 8) : "memory");
        }
        asm volatile("cp.async.commit_group;" ::: "memory");
    };

    load_stage(0, 0); load_stage(1, 1); load_stage(2, 2);

    for (int c = 0; c < NC; c++) {
        int rem = NC - 1 - c;
        if (rem >= 2)      asm volatile("cp.async.wait_group 2;" ::: "memory");
        else if (rem == 1) asm volatile("cp.async.wait_group 1;" ::: "memory");
        else               asm volatile("cp.async.wait_group 0;" ::: "memory");
        __syncthreads();
        if (c + 3 < NC) load_stage(c + 3, (c + 3) & 3);

        uint32_t abase = sbase + (uint32_t)((c & 3) * STAGE_B);
        uint32_t wbase = abase + STG_B;

        // fragment double-buffer: issue ALL ldmatrix for both kc halves first
        uint32_t a0[4][4], a1[4][4], b0f[2][4], b1f[2][4];
        #pragma unroll
        for (int mt = 0; mt < 4; mt++)
            LDSM_X4(a0[mt][0], a0[mt][1], a0[mt][2], a0[mt][3],
                    abase + (uint32_t)((arow + mt * 16) * ROWG + acol));
        #pragma unroll
        for (int t = 0; t < 2; t++)
            LDSM_X4(b0f[t][0], b0f[t][1], b0f[t][2], b0f[t][3],
                    wbase + (uint32_t)((wrow + t * 16) * ROWG + wcol));
        #pragma unroll
        for (int mt = 0; mt < 4; mt++)
            LDSM_X4(a1[mt][0], a1[mt][1], a1[mt][2], a1[mt][3],
                    abase + (uint32_t)((arow + mt * 16) * ROWG + acol + 32));
        #pragma unroll
        for (int t = 0; t < 2; t++)
            LDSM_X4(b1f[t][0], b1f[t][1], b1f[t][2], b1f[t][3],
                    wbase + (uint32_t)((wrow + t * 16) * ROWG + wcol + 32));

        #pragma unroll
        for (int mt = 0; mt < 4; mt++)
            #pragma unroll
            for (int t = 0; t < 2; t++) {
                MMA_BF16(acc[mt][2 * t],     a0[mt], b0f[t][0], b0f[t][1]);
                MMA_BF16(acc[mt][2 * t + 1], a0[mt], b0f[t][2], b0f[t][3]);
            }
        #pragma unroll
        for (int mt = 0; mt < 4; mt++)
            #pragma unroll
            for (int t = 0; t < 2; t++) {
                MMA_BF16(acc[mt][2 * t],     a1[mt], b1f[t][0], b1f[t][1]);
                MMA_BF16(acc[mt][2 * t + 1], a1[mt], b1f[t][2], b1f[t][3]);
            }
    }

    #pragma unroll
    for (int mt = 0; mt < 4; mt++) {
        #pragma unroll
        for (int nt = 0; nt < 4; nt++) {
            int cb = bn * 128 + wn * 32 + nt * 8 + 2 * qd;
            #pragma unroll
            for (int hi = 0; hi < 2; hi++) {
                int r = bm * 128 + wm * 64 + mt * 16 + g + hi * 8;
                float v0 = acc[mt][nt][hi * 2], v1 = acc[mt][nt][hi * 2 + 1];
                if (mode == MODE_QKV) {
                    int which = cb >> 9, h = (cb >> 6) & 7, d0 = cb & 63;
                    int bb = r >> 12, l = r & 4095;
                    __nv_bfloat16* dst = (which == 0) ? oq : (which == 1) ? okk : ov;
                    *(uint32_t*)(dst + (((size_t)bb * H_ + h) * L_ + l) * DH_ + d0) = packbf(v0, v1);
                } else if (mode == MODE_RESID) {
                    size_t idx = (size_t)r * N + cb;
                    float2 rv = *(const float2*)(resid + idx);
                    float2 o2 = {rv.x + v0, rv.y + v1};
                    *(float2*)(out + idx) = o2;
                } else {
                    size_t idx = (size_t)r * N + cb;
                    float a0s = v0 / (1.0f + __expf(-v0));
                    float a1s = v1 / (1.0f + __expf(-v1));
                    *(uint32_t*)(outb + idx) = packbf(a0s, a1s);
                }
            }
        }
    }
}

// ============ flash attention: 64-row Q, 128 thr, 4 CTA/SM ============
#define KSB 72
#define ROWB (KSB * 2)
#define OQ_B   0
#define OK_B   (64 * ROWB)
#define OV_B   (OK_B + 2 * 64 * ROWB)
#define OCB_B  (OV_B + 2 * 64 * ROWB)
#define ATTN_SMEM_B (OCB_B + 2 * 64 * 4)

__global__ __launch_bounds__(128, 4) void attn_kernel(
    const __nv_bfloat16* __restrict__ q, const __nv_bfloat16* __restrict__ k,
    const __nv_bfloat16* __restrict__ v, const float* __restrict__ ts,
    const float* __restrict__ mask, const float* __restrict__ decay_rate,
    __nv_bfloat16* __restrict__ out)
{
    extern __shared__ char smc[];
    uint32_t smb = (uint32_t)__cvta_generic_to_shared(smc);
    float* colb = (float*)(smc + OCB_B);

    int qt = gridDim.x - 1 - blockIdx.x;
    int bh = blockIdx.y, b = bh >> 3, h = bh & 7;
    int tid = threadIdx.x, wid = tid >> 5, lane = tid & 31;
    int g = lane >> 2, qd = lane & 3;
    int rbase = wid * 16;
    const int nkt = qt + 1;

    uint32_t qaddr = smb + OQ_B + (uint32_t)(rbase + (lane & 7) + ((lane >> 3) & 1) * 8) * ROWB
                   + (uint32_t)(lane >> 4) * 16;
    uint32_t kaddr = smb + OK_B + (uint32_t)((lane & 7) + ((lane >> 4) & 1) * 8) * ROWB
                   + (uint32_t)((lane >> 3) & 1) * 16;
    uint32_t vaddr = smb + OV_B + (uint32_t)((lane & 7) + ((lane >> 3) & 1) * 8) * ROWB
                   + (uint32_t)(lane >> 4) * 16;

    const __nv_bfloat16* qb = q + ((size_t)bh * L_ + qt * 64) * DH_;
    #pragma unroll
    for (int i = 0; i < 4; i++) {
        int idx = tid + i * 128;
        int r = idx >> 3, c8 = (idx & 7) << 3;
        *(uint4*)(smc + OQ_B + r * ROWB + c8 * 2) = *(const uint4*)(qb + (size_t)r * DH_ + c8);
    }

    const float LOG2E = 1.44269504f;
    float scale2 = 0.125f * LOG2E;
    float dcy2 = log1pf(__expf(decay_rate[h])) * (LOG2E / 24.0f);
    float mprev[2] = {-1e30f, -1e30f};
    float lsum[2] = {0.f, 0.f};
    float o[8][4];
    #pragma unroll
    for (int i = 0; i < 8; i++)
        #pragma unroll
        for (int e = 0; e < 4; e++) o[i][e] = 0.f;

    auto load_kv = [&](int jt, int st) {
        const __nv_bfloat16* kb = k + ((size_t)bh * L_ + jt * 64) * DH_;
        const __nv_bfloat16* vb = v + ((size_t)bh * L_ + jt * 64) * DH_;
        uint32_t kdst = smb + OK_B + (uint32_t)st * 64 * ROWB;
        uint32_t vdst = smb + OV_B + (uint32_t)st * 64 * ROWB;
        #pragma unroll
        for (int i = 0; i < 4; i++) {
            int idx = tid + i * 128;
            int r = idx >> 3, c8 = (idx & 7) << 3;
            asm volatile("cp.async.cg.shared.global [%0], [%1], 16;"
                         :: "r"(kdst + (uint32_t)(r * ROWB + c8 * 2)),
                            "l"(kb + (size_t)r * DH_ + c8) : "memory");
            asm volatile("cp.async.cg.shared.global [%0], [%1], 16;"
                         :: "r"(vdst + (uint32_t)(r * ROWB + c8 * 2)),
                            "l"(vb + (size_t)r * DH_ + c8) : "memory");
        }
        asm volatile("cp.async.commit_group;" ::: "memory");
        if (tid < 64) {
            float t = ts[b * L_ + jt * 64 + tid];
            float m = mask[b * L_ + jt * 64 + tid];
            colb[st * 64 + tid] = (m != 0.f) ? dcy2 * t : -3e38f;
        }
    };

    load_kv(0, 0);

    for (int jt = 0; jt < nkt; jt++) {
        int st = jt & 1;
        asm volatile("cp.async.wait_group 0;" ::: "memory");
        __syncthreads();
        if (jt + 1 < nkt) load_kv(jt + 1, (jt + 1) & 1);

        uint32_t kst = kaddr + (uint32_t)st * 64 * ROWB;
        uint32_t vst = vaddr + (uint32_t)st * 64 * ROWB;
        const float* cbs = colb + st * 64;
        bool diag = (jt == qt);

        float s[8][4];
        #pragma unroll
        for (int i = 0; i < 8; i++)
            #pragma unroll
            for (int e = 0; e < 4; e++) s[i][e] = 0.f;
        #pragma unroll
        for (int ks = 0; ks < 4; ks++) {
            uint32_t qa0, qa1, qa2, qa3;
            LDSM_X4(qa0, qa1, qa2, qa3, qaddr + ks * 32);
            uint32_t a[4] = {qa0, qa1, qa2, qa3};
            #pragma unroll
            for (int p = 0; p < 4; p++) {
                uint32_t b0, b1, b2, b3;
                LDSM_X4(b0, b1, b2, b3, kst + (uint32_t)(p * 16 * ROWB) + ks * 32);
                MMA_BF16(s[2 * p],     a, b0, b1);
                MMA_BF16(s[2 * p + 1], a, b2, b3);
            }
        }

        int qi0 = qt * 64 + rbase + g;
        #pragma unroll
        for (int nt = 0; nt < 8; nt++) {
            float2 cb2 = *(const float2*)(cbs + nt * 8 + 2 * qd);
            s[nt][0] = fmaf(s[nt][0], scale2, cb2.x);
            s[nt][1] = fmaf(s[nt][1], scale2, cb2.y);
            s[nt][2] = fmaf(s[nt][2], scale2, cb2.x);
            s[nt][3] = fmaf(s[nt][3], scale2, cb2.y);
            if (diag) {
                int colbase = jt * 64 + nt * 8 + 2 * qd;
                if (colbase     > qi0)     s[nt][0] = -3e38f;
                if (colbase + 1 > qi0)     s[nt][1] = -3e38f;
                if (colbase     > qi0 + 8) s[nt][2] = -3e38f;
                if (colbase + 1 > qi0 + 8) s[nt][3] = -3e38f;
            }
        }

        float rmax[2] = {-1e30f, -1e30f};
        #pragma unroll
        for (int nt = 0; nt < 8; nt++) {
            rmax[0] = fmaxf(rmax[0], fmaxf(s[nt][0], s[nt][1]));
            rmax[1] = fmaxf(rmax[1], fmaxf(s[nt][2], s[nt][3]));
        }
        #pragma unroll
        for (int off = 1; off < 4; off <<= 1) {
            rmax[0] = fmaxf(rmax[0], __shfl_xor_sync(0xffffffffu, rmax[0], off));
            rmax[1] = fmaxf(rmax[1], __shfl_xor_sync(0xffffffffu, rmax[1], off));
        }
        float mnew[2], fac[2];
        float psA[2] = {0.f, 0.f}, psB[2] = {0.f, 0.f};
        #pragma unroll
        for (int hi = 0; hi < 2; hi++) {
            mnew[hi] = fmaxf(mprev[hi], rmax[hi]);
            fac[hi]  = exp2fast(mprev[hi] - mnew[hi]);
        }
        #pragma unroll
        for (int nt = 0; nt < 8; nt++) {
            float p0 = exp2fast(s[nt][0] - mnew[0]);
            float p1 = exp2fast(s[nt][1] - mnew[0]);
            float p2 = exp2fast(s[nt][2] - mnew[1]);
            float p3 = exp2fast(s[nt][3] - mnew[1]);
            if (nt & 1) { psB[0] += p0 + p1; psB[1] += p2 + p3; }
            else        { psA[0] += p0 + p1; psA[1] += p2 + p3; }
            s[nt][0] = p0; s[nt][1] = p1; s[nt][2] = p2; s[nt][3] = p3;
        }
        float ps[2] = {psA[0] + psB[0], psA[1] + psB[1]};
        #pragma unroll
        for (int off = 1; off < 4; off <<= 1) {
            ps[0] += __shfl_xor_sync(0xffffffffu, ps[0], off);
            ps[1] += __shfl_xor_sync(0xffffffffu, ps[1], off);
        }
        #pragma unroll
        for (int hi = 0; hi < 2; hi++) {
            lsum[hi] = lsum[hi] * fac[hi] + ps[hi];
            mprev[hi] = mnew[hi];
        }
        #pragma unroll
        for (int nt = 0; nt < 8; nt++) {
            o[nt][0] *= fac[0]; o[nt][1] *= fac[0];
            o[nt][2] *= fac[1]; o[nt][3] *= fac[1];
        }

        #pragma unroll
        for (int kc = 0; kc < 4; kc++) {
            uint32_t a[4];
            a[0] = packbf(s[2 * kc][0],     s[2 * kc][1]);
            a[1] = packbf(s[2 * kc][2],     s[2 * kc][3]);
            a[2] = packbf(s[2 * kc + 1][0], s[2 * kc + 1][1]);
            a[3] = packbf(s[2 * kc + 1][2], s[2 * kc + 1][3]);
            #pragma unroll
            for (int p = 0; p < 4; p++) {
                uint32_t b0, b1, b2, b3;
                LDSM_X4T(b0, b1, b2, b3, vst + (uint32_t)(kc * 16 * ROWB) + p * 32);
                MMA_BF16(o[2 * p],     a, b0, b1);
                MMA_BF16(o[2 * p + 1], a, b2, b3);
            }
        }
    }

    float inv0 = 1.0f / lsum[0], inv1 = 1.0f / lsum[1];
    int r0 = qt * 64 + rbase + g;
    #pragma unroll
    for (int nt = 0; nt < 8; nt++) {
        int col = h * 64 + nt * 8 + 2 * qd;
        *(uint32_t*)(out + (size_t)(b * L_ + r0    ) * D_ + col) = packbf(o[nt][0] * inv0, o[nt][1] * inv0);
        *(uint32_t*)(out + (size_t)(b * L_ + r0 + 8) * D_ + col) = packbf(o[nt][2] * inv1, o[nt][3] * inv1);
    }
}

// ============ launch ============
extern "C" void kernel_launch(void* const* d_in, const int* in_sizes, int n_in,
                              void* d_out, int out_size) {
    const float* x     = (const float*)d_in[0];
    const float* tsb   = (const float*)d_in[1];
    const float* mask  = (const float*)d_in[2];
    const float* ln1_g = (const float*)d_in[3];
    const float* ln1_b = (const float*)d_in[4];
    const float* w_qkv = (const float*)d_in[5];
    const float* w_out = (const float*)d_in[6];
    const float* decay = (const float*)d_in[7];
    const float* ln2_g = (const float*)d_in[8];
    const float* ln2_b = (const float*)d_in[9];
    const float* w_ff1 = (const float*)d_in[10];
    const float* w_ff2 = (const float*)d_in[11];
    float* out = (float*)d_out;

    __nv_bfloat16 *xn, *q, *k, *v, *att, *hh, *ff, *w0, *w1, *w2, *w3;
    float *x1;
    cudaGetSymbolAddress((void**)&xn, g_xn);
    cudaGetSymbolAddress((void**)&q, g_q);
    cudaGetSymbolAddress((void**)&k, g_k);
    cudaGetSymbolAddress((void**)&v, g_v);
    cudaGetSymbolAddress((void**)&att, g_att);
    cudaGetSymbolAddress((void**)&x1, g_x1);
    cudaGetSymbolAddress((void**)&hh, g_h);
    cudaGetSymbolAddress((void**)&ff, g_ff);
    cudaGetSymbolAddress((void**)&w0, g_w0);
    cudaGetSymbolAddress((void**)&w1, g_w1);
    cudaGetSymbolAddress((void**)&w2, g_w2);
    cudaGetSymbolAddress((void**)&w3, g_w3);

    cudaFuncSetAttribute(mma_gemm, cudaFuncAttributeMaxDynamicSharedMemorySize, GEMM_SMEM_B);
    cudaFuncSetAttribute(attn_kernel, cudaFuncAttributeMaxDynamicSharedMemorySize, ATTN_SMEM_B);

    prep_kernel<<<NW_BLOCKS + BL_, 256>>>(w_qkv, w0, w_out, w1, w_ff1, w2, w_ff2, w3,
                                          x, ln1_g, ln1_b, xn);
    mma_gemm<<<dim3(1536 / 128, BL_ / 128), 256, GEMM_SMEM_B>>>(
        xn, w0, D_, 1536, MODE_QKV, nullptr, nullptr, nullptr, q, k, v);
    attn_kernel<<<dim3(L_ / 64, B_ * H_), 128, ATTN_SMEM_B>>>(
        q, k, v, tsb, mask, decay, att);
    mma_gemm<<<dim3(D_ / 128, BL_ / 128), 256, GEMM_SMEM_B>>>(
        att, w1, D_, D_, MODE_RESID, x, x1, nullptr, nullptr, nullptr, nullptr);
    ln_kernel<<<BL_, 256>>>(x1, ln2_g, ln2_b, hh);
    mma_gemm<<<dim3(FF_ / 128, BL_ / 128), 256, GEMM_SMEM_B>>>(
        hh, w2, D_, FF_, MODE_SILU, nullptr, nullptr, ff, nullptr, nullptr, nullptr);
    mma_gemm<<<dim3(D_ / 128, BL_ / 128), 256, GEMM_SMEM_B>>>(
        ff, w3, FF_, D_, MODE_RESID, x1, out, nullptr, nullptr, nullptr, nullptr);
}